// round 2
// baseline (speedup 1.0000x reference)
#include <cuda_runtime.h>

#define BATCHN 4
#define SEQ 2048
#define DM 1024
#define NH 16
#define HD 64
#define DFF 4096
#define MFEAT 532
#define MP 576            // padded feature dim (multiple of 64)
#define NROWS (BATCHN*SEQ) // 8192
#define NBH (BATCHN*NH)    // 64
#define KVLD 72            // kvs^T rows: 64 dims + 1 sum + 7 pad

#define DN 0.35355339059327373f          /* 64^-0.25 */
#define RATIO 0.0433555f                 /* 1/sqrt(532) */
#define FEPS 1e-6f

// ----------------- scratch (device globals; no allocation) -----------------
__device__ float g_xn [(size_t)NROWS*DM];
__device__ float g_q  [(size_t)NROWS*DM];
__device__ float g_k  [(size_t)NROWS*DM];
__device__ float g_v  [(size_t)NROWS*DM];
__device__ float g_qp [(size_t)NBH*SEQ*MP];
__device__ float g_kp [(size_t)NBH*SEQ*MP];
__device__ float g_kvsT[(size_t)NBH*KVLD*MP];
__device__ float g_numer[(size_t)NBH*SEQ*KVLD];
__device__ float g_attn[(size_t)NROWS*DM];
__device__ float g_x1 [(size_t)NROWS*DM];
__device__ float g_hn [(size_t)NROWS*DM];
__device__ float g_ff [(size_t)NROWS*DFF];

// ----------------- LayerNorm: one block per 1024-float row -----------------
__global__ __launch_bounds__(256)
void ln_kernel(const float* __restrict__ x, const float* __restrict__ g,
               const float* __restrict__ beta, float* __restrict__ y)
{
    size_t row = blockIdx.x;
    int tid = threadIdx.x;
    float4 v = ((const float4*)(x + row * DM))[tid];
    float s = v.x + v.y + v.z + v.w;
    __shared__ float sm[8];
    #pragma unroll
    for (int o = 16; o > 0; o >>= 1) s += __shfl_xor_sync(~0u, s, o);
    if ((tid & 31) == 0) sm[tid >> 5] = s;
    __syncthreads();
    float mu = 0.f;
    #pragma unroll
    for (int i = 0; i < 8; i++) mu += sm[i];
    mu *= (1.f / (float)DM);
    float dx = v.x - mu, dy = v.y - mu, dz = v.z - mu, dw = v.w - mu;
    float q = dx*dx + dy*dy + dz*dz + dw*dw;
    __syncthreads();
    #pragma unroll
    for (int o = 16; o > 0; o >>= 1) q += __shfl_xor_sync(~0u, q, o);
    if ((tid & 31) == 0) sm[tid >> 5] = q;
    __syncthreads();
    float var = 0.f;
    #pragma unroll
    for (int i = 0; i < 8; i++) var += sm[i];
    var *= (1.f / (float)DM);
    float inv = rsqrtf(var + 1e-5f);
    float4 gg = ((const float4*)g)[tid];
    float4 bb = ((const float4*)beta)[tid];
    float4 o;
    o.x = dx * inv * gg.x + bb.x;
    o.y = dy * inv * gg.y + bb.y;
    o.z = dz * inv * gg.z + bb.z;
    o.w = dw * inv * gg.w + bb.w;
    ((float4*)(y + row * DM))[tid] = o;
}

// ----------------- generic NT SGEMM: C = A(MxK) * B(NxK)^T -----------------
// lda=ldb=K, ldc=N. M must be a multiple of 128, K a multiple of 16.
// N is predicated. Optional bias / residual / relu. Batched over z.
template<bool RELU, bool RES, bool BIAS>
__global__ __launch_bounds__(256)
void gemm_nt(const float* __restrict__ A, const float* __restrict__ B,
             const float* __restrict__ bias, const float* __restrict__ res,
             float* __restrict__ C,
             int M, int N, int K,
             long long sA, long long sB, long long sC)
{
    const int z = blockIdx.z;
    A += (size_t)z * sA; B += (size_t)z * sB; C += (size_t)z * sC;
    const int m0 = blockIdx.y * 128;
    const int n0 = blockIdx.x * 128;
    __shared__ __align__(16) float As[16][132];
    __shared__ __align__(16) float Bs[16][132];
    const int tid = threadIdx.x;
    const int lrow = tid >> 2;          // 0..63
    const int lkq  = (tid & 3) << 2;    // 0,4,8,12
    const int tx = tid & 15;
    const int ty = tid >> 4;
    float acc[8][8];
    #pragma unroll
    for (int i = 0; i < 8; i++)
        #pragma unroll
        for (int j = 0; j < 8; j++) acc[i][j] = 0.f;

    for (int kk = 0; kk < K; kk += 16) {
        #pragma unroll
        for (int r = 0; r < 2; r++) {
            int row = lrow + (r << 6);
            float4 a = *(const float4*)(A + (size_t)(m0 + row) * K + kk + lkq);
            As[lkq+0][row] = a.x; As[lkq+1][row] = a.y;
            As[lkq+2][row] = a.z; As[lkq+3][row] = a.w;
            float4 b = make_float4(0.f, 0.f, 0.f, 0.f);
            if (n0 + row < N)
                b = *(const float4*)(B + (size_t)(n0 + row) * K + kk + lkq);
            Bs[lkq+0][row] = b.x; Bs[lkq+1][row] = b.y;
            Bs[lkq+2][row] = b.z; Bs[lkq+3][row] = b.w;
        }
        __syncthreads();
        #pragma unroll
        for (int k = 0; k < 16; k++) {
            float4 a0 = *(const float4*)&As[k][ty * 8];
            float4 a1 = *(const float4*)&As[k][ty * 8 + 4];
            float4 b0 = *(const float4*)&Bs[k][tx * 8];
            float4 b1 = *(const float4*)&Bs[k][tx * 8 + 4];
            float av[8] = {a0.x,a0.y,a0.z,a0.w,a1.x,a1.y,a1.z,a1.w};
            float bv[8] = {b0.x,b0.y,b0.z,b0.w,b1.x,b1.y,b1.z,b1.w};
            #pragma unroll
            for (int i = 0; i < 8; i++)
                #pragma unroll
                for (int j = 0; j < 8; j++)
                    acc[i][j] = fmaf(av[i], bv[j], acc[i][j]);
        }
        __syncthreads();
    }
    #pragma unroll
    for (int i = 0; i < 8; i++) {
        int m = m0 + ty * 8 + i;
        #pragma unroll
        for (int j = 0; j < 8; j++) {
            int n = n0 + tx * 8 + j;
            if (n < N) {
                float vv = acc[i][j];
                if (BIAS) vv += bias[n];
                if (RES)  vv += res[(size_t)m * N + n];
                if (RELU) vv = fmaxf(vv, 0.f);
                C[(size_t)m * N + n] = vv;
            }
        }
    }
}

// ----------------- FAVOR+ feature map (single pass, both Q and K) ----------
// One block per (b,l). dd[h][m] = DN * dot(x[h*64:..], proj[m]).
// ISQ: stab = per-(row,head) max over m.
// !ISQ: stab = max over (h,m) for this (b,l) row (matches reference axis=(-2,-1)
//       on a [b,l,h,m] tensor), then masked by the padding mask.
template<bool ISQ>
__global__ __launch_bounds__(256)
void feat_kernel(const float* __restrict__ qk, const float* __restrict__ proj,
                 float* __restrict__ out, const unsigned char* __restrict__ padmask)
{
    const int bl = blockIdx.x;
    const int b = bl >> 11;       // / SEQ
    const int l = bl & (SEQ - 1);
    __shared__ __align__(16) float xr[DM];
    __shared__ float dd[NH][MP + 4];
    __shared__ float red[NH][17];
    __shared__ float stab[NH], dia[NH];
    __shared__ float stab_all;
    const int tid = threadIdx.x;
    ((float4*)xr)[tid] = ((const float4*)(qk + (size_t)bl * DM))[tid];
    __syncthreads();
    if (tid < NH) {
        float s = 0.f;
        #pragma unroll
        for (int d = 0; d < HD; d++) { float v = xr[tid * HD + d]; s = fmaf(v, v, s); }
        dia[tid] = 0.5f * DN * DN * s;
    }
    for (int m = tid; m < MFEAT; m += 256) {
        float acc[NH];
        #pragma unroll
        for (int h = 0; h < NH; h++) acc[h] = 0.f;
        const float4* pr = (const float4*)(proj + (size_t)m * HD);
        #pragma unroll
        for (int d4 = 0; d4 < HD / 4; d4++) {
            float4 p = pr[d4];
            #pragma unroll
            for (int h = 0; h < NH; h++) {
                float4 xv = *(const float4*)&xr[h * HD + d4 * 4];
                acc[h] += p.x * xv.x + p.y * xv.y + p.z * xv.z + p.w * xv.w;
            }
        }
        #pragma unroll
        for (int h = 0; h < NH; h++) dd[h][m] = DN * acc[h];
    }
    __syncthreads();
    {   // per-head max over m (16 threads per head)
        int h = tid >> 4, j = tid & 15;
        float mx = -1e30f;
        for (int m = j; m < MFEAT; m += 16) mx = fmaxf(mx, dd[h][m]);
        red[h][j] = mx;
    }
    __syncthreads();
    if (tid < NH) {
        float mx = red[tid][0];
        #pragma unroll
        for (int j = 1; j < 16; j++) mx = fmaxf(mx, red[tid][j]);
        stab[tid] = mx;
    }
    __syncthreads();
    if (!ISQ && tid == 0) {
        float mx = stab[0];
        #pragma unroll
        for (int h = 1; h < NH; h++) mx = fmaxf(mx, stab[h]);
        stab_all = mx;
    }
    if (!ISQ) __syncthreads();

    const float keep = (!ISQ && padmask[b * SEQ + l] != 0) ? 0.f : 1.f;
    for (int m = tid; m < MP; m += 256) {
        #pragma unroll
        for (int h = 0; h < NH; h++) {
            float o = 0.f;
            if (m < MFEAT) {
                float st = ISQ ? stab[h] : stab_all;
                o = RATIO * (__expf(dd[h][m] - st - dia[h]) + FEPS);
                if (!ISQ) o *= keep;
            }
            out[((size_t)(b * NH + h) * SEQ + l) * MP + m] = o;
        }
    }
}

// ----------------- kvs^T[d][m] = sum_l v[l][d] * kp[l][m], per (b,h) -----------------
__global__ __launch_bounds__(256)
void kvs_kernel(const float* __restrict__ v, const float* __restrict__ kp,
                float* __restrict__ kvsT)
{
    const int bh = blockIdx.z;
    const int b = bh >> 4, h = bh & 15;
    const int mt = blockIdx.x * 64;
    const float* Av = v + (size_t)b * SEQ * DM + h * HD;
    const float* Bk = kp + (size_t)bh * SEQ * MP + mt;
    __shared__ __align__(16) float Vs[16][64];
    __shared__ __align__(16) float Ks[16][68];
    const int tid = threadIdx.x;
    const int lr = tid >> 4;
    const int lq = (tid & 15) << 2;
    const int tx = tid & 15, ty = tid >> 4;
    float acc[4][4];
    #pragma unroll
    for (int i = 0; i < 4; i++)
        #pragma unroll
        for (int j = 0; j < 4; j++) acc[i][j] = 0.f;

    for (int l0 = 0; l0 < SEQ; l0 += 16) {
        *(float4*)&Vs[lr][lq] = *(const float4*)(Av + (size_t)(l0 + lr) * DM + lq);
        *(float4*)&Ks[lr][lq] = *(const float4*)(Bk + (size_t)(l0 + lr) * MP + lq);
        __syncthreads();
        #pragma unroll
        for (int k = 0; k < 16; k++) {
            float4 a = *(const float4*)&Vs[k][ty * 4];
            float4 bb = *(const float4*)&Ks[k][tx * 4];
            float av[4] = {a.x, a.y, a.z, a.w};
            float bv[4] = {bb.x, bb.y, bb.z, bb.w};
            #pragma unroll
            for (int i = 0; i < 4; i++)
                #pragma unroll
                for (int j = 0; j < 4; j++)
                    acc[i][j] = fmaf(av[i], bv[j], acc[i][j]);
        }
        __syncthreads();
    }
    float* outp = kvsT + (size_t)bh * KVLD * MP;
    #pragma unroll
    for (int i = 0; i < 4; i++) {
        int d = ty * 4 + i;
        float4 o = make_float4(acc[i][0], acc[i][1], acc[i][2], acc[i][3]);
        *(float4*)(outp + (size_t)d * MP + mt + tx * 4) = o;
    }
}

// ks_sum (row 64 of kvs^T) + zero pad rows 65..71
__global__ void kssum_kernel(const float* __restrict__ kp, float* __restrict__ kvsT)
{
    int bh = blockIdx.y;
    int m = blockIdx.x * 192 + threadIdx.x;
    if (m >= MP) return;
    const float* p = kp + (size_t)bh * SEQ * MP + m;
    float a0 = 0.f, a1 = 0.f, a2 = 0.f, a3 = 0.f;
    for (int l = 0; l < SEQ; l += 4) {
        a0 += p[(size_t)l * MP];
        a1 += p[(size_t)(l + 1) * MP];
        a2 += p[(size_t)(l + 2) * MP];
        a3 += p[(size_t)(l + 3) * MP];
    }
    float* o = kvsT + (size_t)bh * KVLD * MP;
    o[(size_t)64 * MP + m] = (a0 + a1) + (a2 + a3);
    #pragma unroll
    for (int r = 65; r < KVLD; r++) o[(size_t)r * MP + m] = 0.f;
}

// attn[b,l,h*64+d] = numer[bh,l,d] / (numer[bh,l,64] + 1e-6)
__global__ void divide_kernel(const float* __restrict__ numer, float* __restrict__ attn)
{
    size_t i = (size_t)blockIdx.x * 256 + threadIdx.x;
    if (i >= (size_t)NBH * SEQ * HD) return;
    int d = (int)(i & 63);
    int l = (int)((i >> 6) & (SEQ - 1));
    int bh = (int)(i >> 17);
    int b = bh >> 4, h = bh & 15;
    const float* row = numer + ((size_t)bh * SEQ + l) * KVLD;
    float den = row[64] + 1e-6f;
    attn[((size_t)(b * SEQ + l)) * DM + h * HD + d] = row[d] / den;
}

// ----------------- launch -----------------
static void* getsym(const void* shadow)
{
    void* p = nullptr;
    cudaGetSymbolAddress(&p, shadow);
    return p;
}

extern "C" void kernel_launch(void* const* d_in, const int* in_sizes, int n_in,
                              void* d_out, int out_size)
{
    const float* src    = (const float*)d_in[0];
    const unsigned char* mask = (const unsigned char*)d_in[1];
    const float* proj   = (const float*)d_in[2];
    const float* q_w    = (const float*)d_in[3];
    const float* q_b    = (const float*)d_in[4];
    const float* k_w    = (const float*)d_in[5];
    const float* k_b    = (const float*)d_in[6];
    const float* v_w    = (const float*)d_in[7];
    const float* v_b    = (const float*)d_in[8];
    const float* out_w  = (const float*)d_in[9];
    const float* out_b  = (const float*)d_in[10];
    const float* ln1_g  = (const float*)d_in[11];
    const float* ln1_b  = (const float*)d_in[12];
    const float* ln2_g  = (const float*)d_in[13];
    const float* ln2_b  = (const float*)d_in[14];
    const float* ff1_w  = (const float*)d_in[15];
    const float* ff1_b  = (const float*)d_in[16];
    const float* ff2_w  = (const float*)d_in[17];
    const float* ff2_b  = (const float*)d_in[18];
    float* out = (float*)d_out;

    float* p_xn   = (float*)getsym(g_xn);
    float* p_q    = (float*)getsym(g_q);
    float* p_k    = (float*)getsym(g_k);
    float* p_v    = (float*)getsym(g_v);
    float* p_qp   = (float*)getsym(g_qp);
    float* p_kp   = (float*)getsym(g_kp);
    float* p_kvsT = (float*)getsym(g_kvsT);
    float* p_numer= (float*)getsym(g_numer);
    float* p_attn = (float*)getsym(g_attn);
    float* p_x1   = (float*)getsym(g_x1);
    float* p_hn   = (float*)getsym(g_hn);
    float* p_ff   = (float*)getsym(g_ff);

    // 1) LN1
    ln_kernel<<<NROWS, 256>>>(src, ln1_g, ln1_b, p_xn);

    // 2) QKV projections
    dim3 gQ(DM / 128, NROWS / 128, 1);
    gemm_nt<false,false,true><<<gQ, 256>>>(p_xn, q_w, q_b, nullptr, p_q, NROWS, DM, DM, 0, 0, 0);
    gemm_nt<false,false,true><<<gQ, 256>>>(p_xn, k_w, k_b, nullptr, p_k, NROWS, DM, DM, 0, 0, 0);
    gemm_nt<false,false,true><<<gQ, 256>>>(p_xn, v_w, v_b, nullptr, p_v, NROWS, DM, DM, 0, 0, 0);

    // 3) feature maps (single pass each)
    feat_kernel<true ><<<NROWS, 256>>>(p_q, proj, p_qp, nullptr);
    feat_kernel<false><<<NROWS, 256>>>(p_k, proj, p_kp, mask);

    // 4) kvs^T + ks_sum
    kvs_kernel<<<dim3(MP / 64, 1, NBH), 256>>>(p_v, p_kp, p_kvsT);
    kssum_kernel<<<dim3(3, NBH), 192>>>(p_kp, p_kvsT);

    // 5) numer (+denom as col 64): batched NT gemm, qp @ kvsT^T
    gemm_nt<false,false,false><<<dim3(1, SEQ / 128, NBH), 256>>>(
        p_qp, p_kvsT, nullptr, nullptr, p_numer,
        SEQ, KVLD, MP,
        (long long)SEQ * MP, (long long)KVLD * MP, (long long)SEQ * KVLD);

    // 6) divide + interleave heads back to [B,L,D]
    divide_kernel<<<(NBH * SEQ * HD) / 256, 256>>>(p_numer, p_attn);

    // 7) out projection + residual(src)
    gemm_nt<false,true,true><<<gQ, 256>>>(p_attn, out_w, out_b, src, p_x1, NROWS, DM, DM, 0, 0, 0);

    // 8) LN2
    ln_kernel<<<NROWS, 256>>>(p_x1, ln2_g, ln2_b, p_hn);

    // 9) FF1 (+ReLU)
    gemm_nt<true,false,true><<<dim3(DFF / 128, NROWS / 128, 1), 256>>>(
        p_hn, ff1_w, ff1_b, nullptr, p_ff, NROWS, DFF, DM, 0, 0, 0);

    // 10) FF2 + residual(x1) -> final output
    gemm_nt<false,true,true><<<gQ, 256>>>(p_ff, ff2_w, ff2_b, p_x1, out, NROWS, DM, DFF, 0, 0, 0);
}

// round 4
// speedup vs baseline: 3.7156x; 3.7156x over previous
#include <cuda_runtime.h>
#include <cstdint>

#define BATCHN 4
#define SEQ 2048
#define DM 1024
#define NH 16
#define HD 64
#define DFF 4096
#define MFEAT 532
#define MP 576             // padded feature dim
#define NROWS (BATCHN*SEQ) // 8192
#define NBH (BATCHN*NH)    // 64
#define KVR 128            // kvs^T rows: 64 dims + 1 sum + 63 pad

#define DN 0.35355339059327373f          /* 64^-0.25 */
#define RATIO 0.0433555f                 /* 1/sqrt(532) */
#define FEPS 1e-6f

// ----------------- scratch (device globals; no allocation) -----------------
__device__ float g_xn [(size_t)NROWS*DM];
__device__ float g_q  [(size_t)NROWS*DM];
__device__ float g_k  [(size_t)NROWS*DM];
__device__ float g_v  [(size_t)NROWS*DM];
__device__ float g_qp [(size_t)NBH*SEQ*MP];
__device__ float g_kp [(size_t)NBH*SEQ*MP];
__device__ float g_kvsT[(size_t)NBH*KVR*MP];
__device__ float g_numer[(size_t)NBH*SEQ*KVR];
__device__ float g_attn[(size_t)NROWS*DM];
__device__ float g_x1 [(size_t)NROWS*DM];
__device__ float g_hn [(size_t)NROWS*DM];
__device__ float g_ff [(size_t)NROWS*DFF];
// rounded weight copies (tf32-rna)
__device__ float g_wq[(size_t)DM*DM];
__device__ float g_wk[(size_t)DM*DM];
__device__ float g_wv[(size_t)DM*DM];
__device__ float g_wo[(size_t)DM*DM];
__device__ float g_w1[(size_t)DFF*DM];
__device__ float g_w2[(size_t)DM*DFF];
__device__ float g_pj[(size_t)MFEAT*HD];

// ===================== helpers =====================
static __device__ __forceinline__ float rna(float x) {
    uint32_t u;
    asm("cvt.rna.tf32.f32 %0, %1;" : "=r"(u) : "f"(x));
    return __uint_as_float(u);
}
static __device__ __forceinline__ uint32_t smem_u32(const void* p) {
    uint32_t a;
    asm("{ .reg .u64 t; cvta.to.shared.u64 t, %1; cvt.u32.u64 %0, t; }"
        : "=r"(a) : "l"(p));
    return a;
}
static __device__ __forceinline__ void cp16(uint32_t dst, const float* src, int sz) {
    asm volatile("cp.async.cg.shared.global [%0], [%1], 16, %2;"
                 :: "r"(dst), "l"(src), "r"(sz));
}
#define CP_COMMIT() asm volatile("cp.async.commit_group;" ::: "memory")
#define CP_WAIT1()  asm volatile("cp.async.wait_group 1;" ::: "memory")

static __device__ __forceinline__ void mma8(float* c, const uint32_t* a, const uint32_t* b) {
    asm volatile(
        "mma.sync.aligned.m16n8k8.row.col.f32.tf32.tf32.f32 "
        "{%0,%1,%2,%3}, {%4,%5,%6,%7}, {%8,%9}, {%0,%1,%2,%3};"
        : "+f"(c[0]), "+f"(c[1]), "+f"(c[2]), "+f"(c[3])
        : "r"(a[0]), "r"(a[1]), "r"(a[2]), "r"(a[3]), "r"(b[0]), "r"(b[1]));
}

// ===================== tf32 mma.sync NT GEMM =====================
// C[M,N] = A[M,K] * B[N,K]^T (+bias +res, relu, optional tf32-rna on store).
// A,B must already be tf32-rna-rounded. M mult of 128; K mult of 32; N even.
// smem stores operands in mma-fragment order:
//   As[ks(4)][mt(8)][reg(4)][lane(32)], Bs[ks(4)][nt(16)][reg(2)][lane(32)]
#define ASTG 4096                 // floats per A stage
#define STG  8192                 // floats per stage (A+B)
#define GSM  (2*STG*4)            // 64 KB

template<bool RELU, bool RES, bool BIAS, bool RND>
__global__ __launch_bounds__(256)
void gemm_mma(const float* __restrict__ A, const float* __restrict__ B,
              const float* __restrict__ bias, const float* __restrict__ res,
              float* __restrict__ C,
              int M, int N, int K, int lda, int ldb, int ldc,
              long long sAo, long long sAi, long long sBo, long long sBi,
              long long sCo, long long sCi, int zdiv)
{
    extern __shared__ float smem[];
    const int tid = threadIdx.x;
    const int lane = tid & 31;
    const int w = tid >> 5;
    const int wm = w & 1, wn = w >> 1;
    const uint32_t sbase = smem_u32(smem);

    const int z = blockIdx.z;
    const int zo = z / zdiv, zi = z - zo * zdiv;
    const float* Ag = A + (size_t)zo * sAo + (size_t)zi * sAi;
    const float* Bg = B + (size_t)zo * sBo + (size_t)zi * sBi;
    float* Cg = C + (size_t)zo * sCo + (size_t)zi * sCi;
    const int m0 = blockIdx.y * 128, n0 = blockIdx.x * 128;

    // loader assignments: 4 float4 each for A and B per stage per thread
    const float* asrc[4]; uint32_t adst[4];
    const float* bsrc[4]; uint32_t bdst[4]; int bsz[4];
    #pragma unroll
    for (int j = 0; j < 4; j++) {
        int f = j * 256 + tid;
        int row = f >> 3, kq = f & 7;
        int ks = kq >> 1;
        {   // A: element (row, k) -> reg=((row%16)>>3)+2*(kq&1), lane base (row&7)*4
            int reg = ((row & 15) >> 3) + ((kq & 1) << 1);
            int fi = ((ks * 8 + (row >> 4)) * 4 + reg) * 32 + (row & 7) * 4;
            adst[j] = sbase + fi * 4;
            asrc[j] = Ag + (size_t)(m0 + row) * lda + kq * 4;
        }
        {   // B: reg = kq&1, ntile = row>>3
            int reg = kq & 1;
            int fi = ASTG + ((ks * 16 + (row >> 3)) * 2 + reg) * 32 + (row & 7) * 4;
            bdst[j] = sbase + fi * 4;
            int rr = (n0 + row) < N ? (n0 + row) : 0;
            bsrc[j] = Bg + (size_t)rr * ldb + kq * 4;
            bsz[j] = (n0 + row) < N ? 16 : 0;
        }
    }

    float acc[4][4][4];
    #pragma unroll
    for (int a = 0; a < 4; a++)
        #pragma unroll
        for (int b = 0; b < 4; b++)
            #pragma unroll
            for (int c = 0; c < 4; c++) acc[a][b][c] = 0.f;

    const int nk = K >> 5;
    #pragma unroll
    for (int j = 0; j < 4; j++) { cp16(adst[j], asrc[j], 16); cp16(bdst[j], bsrc[j], bsz[j]); }
    CP_COMMIT();

    for (int i = 0; i < nk; i++) {
        if (i + 1 < nk) {
            uint32_t so = (uint32_t)((i + 1) & 1) * (STG * 4);
            int koff = (i + 1) * 32;
            #pragma unroll
            for (int j = 0; j < 4; j++) {
                cp16(adst[j] + so, asrc[j] + koff, 16);
                cp16(bdst[j] + so, bsrc[j] + koff, bsz[j]);
            }
        }
        CP_COMMIT();
        CP_WAIT1();
        __syncthreads();
        const uint32_t* sa = (const uint32_t*)smem + (i & 1) * STG;
        const uint32_t* sbp = sa + ASTG;
        #pragma unroll
        for (int ks = 0; ks < 4; ks++) {
            uint32_t af[4][4], bf[4][2];
            #pragma unroll
            for (int mt = 0; mt < 4; mt++) {
                const uint32_t* p = sa + (size_t)((ks * 8 + wm * 4 + mt) * 4) * 32 + lane;
                af[mt][0] = p[0]; af[mt][1] = p[32]; af[mt][2] = p[64]; af[mt][3] = p[96];
            }
            #pragma unroll
            for (int nt = 0; nt < 4; nt++) {
                const uint32_t* p = sbp + (size_t)((ks * 16 + wn * 4 + nt) * 2) * 32 + lane;
                bf[nt][0] = p[0]; bf[nt][1] = p[32];
            }
            #pragma unroll
            for (int mt = 0; mt < 4; mt++)
                #pragma unroll
                for (int nt = 0; nt < 4; nt++)
                    mma8(acc[mt][nt], af[mt], bf[nt]);
        }
        __syncthreads();
    }

    // epilogue: thread holds (r, c..c+1) and (r+8, c..c+1) per 16x8 tile
    #pragma unroll
    for (int mt = 0; mt < 4; mt++) {
        const int r0 = m0 + wm * 64 + mt * 16 + (lane >> 2);
        #pragma unroll
        for (int nt = 0; nt < 4; nt++) {
            const int c0 = n0 + wn * 32 + nt * 8 + (lane & 3) * 2;
            if (c0 < N) {
                float bx = 0.f, by = 0.f;
                if (BIAS) { float2 b2 = *(const float2*)(bias + c0); bx = b2.x; by = b2.y; }
                float x0 = acc[mt][nt][0] + bx, x1 = acc[mt][nt][1] + by;
                float y0 = acc[mt][nt][2] + bx, y1 = acc[mt][nt][3] + by;
                if (RES) {
                    float2 ra = *(const float2*)(res + (size_t)r0 * ldc + c0);
                    float2 rb = *(const float2*)(res + (size_t)(r0 + 8) * ldc + c0);
                    x0 += ra.x; x1 += ra.y; y0 += rb.x; y1 += rb.y;
                }
                if (RELU) {
                    x0 = fmaxf(x0, 0.f); x1 = fmaxf(x1, 0.f);
                    y0 = fmaxf(y0, 0.f); y1 = fmaxf(y1, 0.f);
                }
                if (RND) { x0 = rna(x0); x1 = rna(x1); y0 = rna(y0); y1 = rna(y1); }
                *(float2*)(Cg + (size_t)r0 * ldc + c0) = make_float2(x0, x1);
                *(float2*)(Cg + (size_t)(r0 + 8) * ldc + c0) = make_float2(y0, y1);
            }
        }
    }
}

// ----------------- weight rounding -----------------
__global__ void rnd_kernel(const float* __restrict__ src, float* __restrict__ dst, int n4)
{
    int i = blockIdx.x * 256 + threadIdx.x;
    if (i >= n4) return;
    float4 v = ((const float4*)src)[i];
    v.x = rna(v.x); v.y = rna(v.y); v.z = rna(v.z); v.w = rna(v.w);
    ((float4*)dst)[i] = v;
}

// ----------------- LayerNorm (output tf32-rounded: always a GEMM A operand) --
__global__ __launch_bounds__(256)
void ln_kernel(const float* __restrict__ x, const float* __restrict__ g,
               const float* __restrict__ beta, float* __restrict__ y)
{
    size_t row = blockIdx.x;
    int tid = threadIdx.x;
    float4 v = ((const float4*)(x + row * DM))[tid];
    float s = v.x + v.y + v.z + v.w;
    __shared__ float sm[8];
    #pragma unroll
    for (int o = 16; o > 0; o >>= 1) s += __shfl_xor_sync(~0u, s, o);
    if ((tid & 31) == 0) sm[tid >> 5] = s;
    __syncthreads();
    float mu = 0.f;
    #pragma unroll
    for (int i = 0; i < 8; i++) mu += sm[i];
    mu *= (1.f / (float)DM);
    float dx = v.x - mu, dy = v.y - mu, dz = v.z - mu, dw = v.w - mu;
    float q = dx*dx + dy*dy + dz*dz + dw*dw;
    __syncthreads();
    #pragma unroll
    for (int o = 16; o > 0; o >>= 1) q += __shfl_xor_sync(~0u, q, o);
    if ((tid & 31) == 0) sm[tid >> 5] = q;
    __syncthreads();
    float var = 0.f;
    #pragma unroll
    for (int i = 0; i < 8; i++) var += sm[i];
    var *= (1.f / (float)DM);
    float inv = rsqrtf(var + 1e-5f);
    float4 gg = ((const float4*)g)[tid];
    float4 bb = ((const float4*)beta)[tid];
    float4 o;
    o.x = rna(dx * inv * gg.x + bb.x);
    o.y = rna(dy * inv * gg.y + bb.y);
    o.z = rna(dz * inv * gg.z + bb.z);
    o.w = rna(dw * inv * gg.w + bb.w);
    ((float4*)(y + row * DM))[tid] = o;
}

// ----------------- q exp epilogue (in-place on qp, rounded out) --------------
__global__ __launch_bounds__(256)
void qexp_kernel(float* __restrict__ qp, const float* __restrict__ q)
{
    const int r = blockIdx.x * 8 + (threadIdx.x >> 5);
    const int lane = threadIdx.x & 31;
    const int bh = r >> 11, l = r & (SEQ - 1);
    const int b = bh >> 4, h = bh & 15;
    float* row = qp + (size_t)r * MP;
    float vals[17];
    float mx = -1e30f;
    #pragma unroll
    for (int j = 0; j < 17; j++) {
        int m = j * 32 + lane;
        if (m < MFEAT) { float v = DN * row[m]; vals[j] = v; mx = fmaxf(mx, v); }
    }
    #pragma unroll
    for (int o = 16; o > 0; o >>= 1) mx = fmaxf(mx, __shfl_xor_sync(~0u, mx, o));
    const float* qr = q + ((size_t)(b * SEQ + l)) * DM + h * HD;
    float a = qr[lane], bb2 = qr[lane + 32];
    float s = a * a + bb2 * bb2;
    #pragma unroll
    for (int o = 16; o > 0; o >>= 1) s += __shfl_xor_sync(~0u, s, o);
    float dia = 0.5f * DN * DN * s;
    #pragma unroll
    for (int j = 0; j < 18; j++) {
        int m = j * 32 + lane;
        if (m < MP)
            row[m] = (m < MFEAT) ? rna(RATIO * (__expf(vals[j] - mx - dia) + FEPS)) : 0.f;
    }
}

// ----------------- k exp epilogue (in-place on kp, rounded out) --------------
__global__ __launch_bounds__(256)
void kexp_kernel(float* __restrict__ kp, const float* __restrict__ k,
                 const unsigned char* __restrict__ padmask)
{
    const int b = blockIdx.x >> 11, l = blockIdx.x & (SEQ - 1);
    const int t = threadIdx.x;
    const int h = t >> 4, j = t & 15;
    __shared__ float red[256], red2[256], diag[NH];
    __shared__ float stab_s;
    float* row = kp + ((size_t)(b * NH + h) * SEQ + l) * MP;
    float mx = -1e30f;
    for (int m = j; m < MFEAT; m += 16) mx = fmaxf(mx, DN * row[m]);
    red[t] = mx;
    const float* kr = k + ((size_t)(b * SEQ + l)) * DM + h * HD;
    float s = 0.f;
    #pragma unroll
    for (int d = 0; d < 4; d++) { float v = kr[j + 16 * d]; s = fmaf(v, v, s); }
    red2[t] = s;
    __syncthreads();
    for (int st = 128; st > 0; st >>= 1) {
        if (t < st) red[t] = fmaxf(red[t], red[t + st]);
        __syncthreads();
    }
    if (t < NH) {
        float ds = 0.f;
        #pragma unroll
        for (int jj = 0; jj < 16; jj++) ds += red2[t * 16 + jj];
        diag[t] = 0.5f * DN * DN * ds;
    }
    if (t == 0) stab_s = red[0];
    __syncthreads();
    const float stab = stab_s;
    const float keep = padmask[b * SEQ + l] ? 0.f : 1.f;
    const float dia = diag[h];
    for (int m = j; m < MP; m += 16)
        row[m] = (m < MFEAT) ? rna(keep * RATIO * (__expf(DN * row[m] - stab - dia) + FEPS)) : 0.f;
}

// ----------------- kvs^T[d][m] = sum_l v[l][d] * kp[l][m] --------------------
__global__ __launch_bounds__(256)
void kvs_kernel(const float* __restrict__ v, const float* __restrict__ kp,
                float* __restrict__ kvsT)
{
    const int bh = blockIdx.z;
    const int b = bh >> 4, h = bh & 15;
    const int mt = blockIdx.x * 64;
    const float* Av = v + (size_t)b * SEQ * DM + h * HD;
    const float* Bk = kp + (size_t)bh * SEQ * MP + mt;
    __shared__ __align__(16) float Vs[16][64];
    __shared__ __align__(16) float Ks[16][68];
    const int tid = threadIdx.x;
    const int lr = tid >> 4;
    const int lq = (tid & 15) << 2;
    const int tx = tid & 15, ty = tid >> 4;
    float acc[4][4];
    #pragma unroll
    for (int i = 0; i < 4; i++)
        #pragma unroll
        for (int j = 0; j < 4; j++) acc[i][j] = 0.f;

    for (int l0 = 0; l0 < SEQ; l0 += 16) {
        *(float4*)&Vs[lr][lq] = *(const float4*)(Av + (size_t)(l0 + lr) * DM + lq);
        *(float4*)&Ks[lr][lq] = *(const float4*)(Bk + (size_t)(l0 + lr) * MP + lq);
        __syncthreads();
        #pragma unroll
        for (int kx = 0; kx < 16; kx++) {
            float4 a = *(const float4*)&Vs[kx][ty * 4];
            float4 bb = *(const float4*)&Ks[kx][tx * 4];
            float av[4] = {a.x, a.y, a.z, a.w};
            float bv[4] = {bb.x, bb.y, bb.z, bb.w};
            #pragma unroll
            for (int i = 0; i < 4; i++)
                #pragma unroll
                for (int j = 0; j < 4; j++)
                    acc[i][j] = fmaf(av[i], bv[j], acc[i][j]);
        }
        __syncthreads();
    }
    float* outp = kvsT + (size_t)bh * KVR * MP;
    #pragma unroll
    for (int i = 0; i < 4; i++) {
        int d = ty * 4 + i;
        float4 o = make_float4(rna(acc[i][0]), rna(acc[i][1]), rna(acc[i][2]), rna(acc[i][3]));
        *(float4*)(outp + (size_t)d * MP + mt + tx * 4) = o;
    }
}

// ks_sum (row 64 of kvs^T) + zero pad rows 65..127
__global__ void kssum_kernel(const float* __restrict__ kp, float* __restrict__ kvsT)
{
    int bh = blockIdx.y;
    int m = blockIdx.x * 192 + threadIdx.x;
    if (m >= MP) return;
    const float* p = kp + (size_t)bh * SEQ * MP + m;
    float a0 = 0.f, a1 = 0.f, a2 = 0.f, a3 = 0.f;
    for (int l = 0; l < SEQ; l += 4) {
        a0 += p[(size_t)l * MP];
        a1 += p[(size_t)(l + 1) * MP];
        a2 += p[(size_t)(l + 2) * MP];
        a3 += p[(size_t)(l + 3) * MP];
    }
    float* o = kvsT + (size_t)bh * KVR * MP;
    o[(size_t)64 * MP + m] = rna((a0 + a1) + (a2 + a3));
    for (int r = 65; r < KVR; r++) o[(size_t)r * MP + m] = 0.f;
}

// attn[b,l,h*64+d] = numer[bh,l,d] / (numer[bh,l,64] + 1e-6), rounded (A of out-proj)
__global__ void divide_kernel(const float* __restrict__ numer, float* __restrict__ attn)
{
    size_t i = (size_t)blockIdx.x * 256 + threadIdx.x;
    if (i >= (size_t)NBH * SEQ * HD) return;
    int d = (int)(i & 63);
    int l = (int)((i >> 6) & (SEQ - 1));
    int bh = (int)(i >> 17);
    int b = bh >> 4, h = bh & 15;
    const float* row = numer + ((size_t)bh * SEQ + l) * KVR;
    float den = row[64] + 1e-6f;
    attn[((size_t)(b * SEQ + l)) * DM + h * HD + d] = rna(row[d] / den);
}

// ----------------- launch -----------------
static void* getsym(const void* shadow)
{
    void* p = nullptr;
    cudaGetSymbolAddress(&p, shadow);
    return p;
}

extern "C" void kernel_launch(void* const* d_in, const int* in_sizes, int n_in,
                              void* d_out, int out_size)
{
    const float* src    = (const float*)d_in[0];
    const unsigned char* mask = (const unsigned char*)d_in[1];
    const float* proj   = (const float*)d_in[2];
    const float* q_w    = (const float*)d_in[3];
    const float* q_b    = (const float*)d_in[4];
    const float* k_w    = (const float*)d_in[5];
    const float* k_b    = (const float*)d_in[6];
    const float* v_w    = (const float*)d_in[7];
    const float* v_b    = (const float*)d_in[8];
    const float* out_w  = (const float*)d_in[9];
    const float* out_b  = (const float*)d_in[10];
    const float* ln1_g  = (const float*)d_in[11];
    const float* ln1_b  = (const float*)d_in[12];
    const float* ln2_g  = (const float*)d_in[13];
    const float* ln2_b  = (const float*)d_in[14];
    const float* ff1_w  = (const float*)d_in[15];
    const float* ff1_b  = (const float*)d_in[16];
    const float* ff2_w  = (const float*)d_in[17];
    const float* ff2_b  = (const float*)d_in[18];
    float* out = (float*)d_out;

    float* p_xn   = (float*)getsym(g_xn);
    float* p_q    = (float*)getsym(g_q);
    float* p_k    = (float*)getsym(g_k);
    float* p_v    = (float*)getsym(g_v);
    float* p_qp   = (float*)getsym(g_qp);
    float* p_kp   = (float*)getsym(g_kp);
    float* p_kvsT = (float*)getsym(g_kvsT);
    float* p_numer= (float*)getsym(g_numer);
    float* p_attn = (float*)getsym(g_attn);
    float* p_x1   = (float*)getsym(g_x1);
    float* p_hn   = (float*)getsym(g_hn);
    float* p_ff   = (float*)getsym(g_ff);
    float* p_wq   = (float*)getsym(g_wq);
    float* p_wk   = (float*)getsym(g_wk);
    float* p_wv   = (float*)getsym(g_wv);
    float* p_wo   = (float*)getsym(g_wo);
    float* p_w1   = (float*)getsym(g_w1);
    float* p_w2   = (float*)getsym(g_w2);
    float* p_pj   = (float*)getsym(g_pj);

    cudaFuncSetAttribute(gemm_mma<false,false,true,true>,
                         cudaFuncAttributeMaxDynamicSharedMemorySize, GSM);
    cudaFuncSetAttribute(gemm_mma<false,false,false,false>,
                         cudaFuncAttributeMaxDynamicSharedMemorySize, GSM);
    cudaFuncSetAttribute(gemm_mma<false,true,true,false>,
                         cudaFuncAttributeMaxDynamicSharedMemorySize, GSM);
    cudaFuncSetAttribute(gemm_mma<true,false,true,true>,
                         cudaFuncAttributeMaxDynamicSharedMemorySize, GSM);

    // 0) round weights to tf32 (rna) once per launch
    {
        int n4 = DM * DM / 4;
        rnd_kernel<<<(n4 + 255) / 256, 256>>>(q_w, p_wq, n4);
        rnd_kernel<<<(n4 + 255) / 256, 256>>>(k_w, p_wk, n4);
        rnd_kernel<<<(n4 + 255) / 256, 256>>>(v_w, p_wv, n4);
        rnd_kernel<<<(n4 + 255) / 256, 256>>>(out_w, p_wo, n4);
        int nf = DFF * DM / 4;
        rnd_kernel<<<(nf + 255) / 256, 256>>>(ff1_w, p_w1, nf);
        rnd_kernel<<<(nf + 255) / 256, 256>>>(ff2_w, p_w2, nf);
        int np = MFEAT * HD / 4;
        rnd_kernel<<<(np + 255) / 256, 256>>>(proj, p_pj, np);
    }

    // 1) LN1 (rounded out)
    ln_kernel<<<NROWS, 256>>>(src, ln1_g, ln1_b, p_xn);

    // 2) QKV projections (rounded out: feed feature GEMM / kvs)
    dim3 gQ(DM / 128, NROWS / 128, 1);
    gemm_mma<false,false,true,true><<<gQ, 256, GSM>>>(
        p_xn, p_wq, q_b, nullptr, p_q, NROWS, DM, DM, DM, DM, DM,
        0, 0, 0, 0, 0, 0, 1);
    gemm_mma<false,false,true,true><<<gQ, 256, GSM>>>(
        p_xn, p_wk, k_b, nullptr, p_k, NROWS, DM, DM, DM, DM, DM,
        0, 0, 0, 0, 0, 0, 1);
    gemm_mma<false,false,true,true><<<gQ, 256, GSM>>>(
        p_xn, p_wv, v_b, nullptr, p_v, NROWS, DM, DM, DM, DM, DM,
        0, 0, 0, 0, 0, 0, 1);

    // 3) feature-map GEMMs: dd = q_head @ proj^T, batched over z=bh
    dim3 gF((MFEAT + 127) / 128, SEQ / 128, NBH);
    gemm_mma<false,false,false,false><<<gF, 256, GSM>>>(
        p_q, p_pj, nullptr, nullptr, p_qp, SEQ, MFEAT, HD, DM, HD, MP,
        (long long)SEQ * DM, HD, 0, 0, (long long)NH * SEQ * MP, (long long)SEQ * MP, NH);
    gemm_mma<false,false,false,false><<<gF, 256, GSM>>>(
        p_k, p_pj, nullptr, nullptr, p_kp, SEQ, MFEAT, HD, DM, HD, MP,
        (long long)SEQ * DM, HD, 0, 0, (long long)NH * SEQ * MP, (long long)SEQ * MP, NH);

    // 4) exp epilogues (in place, rounded out)
    qexp_kernel<<<NBH * SEQ / 8, 256>>>(p_qp, p_q);
    kexp_kernel<<<BATCHN * SEQ, 256>>>(p_kp, p_k, mask);

    // 5) kvs^T + ks_sum (+ zero pad rows), rounded out
    kvs_kernel<<<dim3(MP / 64, 1, NBH), 256>>>(p_v, p_kp, p_kvsT);
    kssum_kernel<<<dim3(3, NBH), 192>>>(p_kp, p_kvsT);

    // 6) numer (+denom as col 64): batched GEMM, qp @ kvsT^T, N=128 dense
    gemm_mma<false,false,false,false><<<dim3(1, SEQ / 128, NBH), 256, GSM>>>(
        p_qp, p_kvsT, nullptr, nullptr, p_numer, SEQ, KVR, MP, MP, MP, KVR,
        (long long)SEQ * MP, 0, (long long)KVR * MP, 0, (long long)SEQ * KVR, 0, 1);

    // 7) divide + head interleave (rounded out)
    divide_kernel<<<(NBH * SEQ * HD) / 256, 256>>>(p_numer, p_attn);

    // 8) out projection + residual(src)
    gemm_mma<false,true,true,false><<<gQ, 256, GSM>>>(
        p_attn, p_wo, out_b, src, p_x1, NROWS, DM, DM, DM, DM, DM,
        0, 0, 0, 0, 0, 0, 1);

    // 9) LN2 (rounded out)
    ln_kernel<<<NROWS, 256>>>(p_x1, ln2_g, ln2_b, p_hn);

    // 10) FF1 (+ReLU, rounded out)
    gemm_mma<true,false,true,true><<<dim3(DFF / 128, NROWS / 128, 1), 256, GSM>>>(
        p_hn, p_w1, ff1_b, nullptr, p_ff, NROWS, DFF, DM, DM, DM, DFF,
        0, 0, 0, 0, 0, 0, 1);

    // 11) FF2 + residual(x1) -> final output
    gemm_mma<false,true,true,false><<<gQ, 256, GSM>>>(
        p_ff, p_w2, ff2_b, p_x1, out, NROWS, DM, DFF, DFF, DFF, DM,
        0, 0, 0, 0, 0, 0, 1);
}

// round 5
// speedup vs baseline: 7.0554x; 1.8988x over previous
#include <cuda_runtime.h>
#include <cuda_fp16.h>
#include <cstdint>

#define BATCHN 4
#define SEQ 2048
#define DM 1024
#define NH 16
#define HD 64
#define DFF 4096
#define MFEAT 532
#define MP 576             // padded feature dim
#define NROWS (BATCHN*SEQ) // 8192
#define NBH (BATCHN*NH)    // 64
#define KVR 128            // kvs^T rows: 64 dims + 1 sum + 63 pad

#define DN 0.35355339059327373f          /* 64^-0.25 */
#define RATIO 0.0433555f                 /* 1/sqrt(532) */
#define FEPS 1e-6f

// ----------------- scratch (device globals; no allocation) -----------------
__device__ __half g_xnh [(size_t)NROWS*DM];
__device__ __half g_qh  [(size_t)NROWS*DM];
__device__ __half g_kh  [(size_t)NROWS*DM];
__device__ __half g_vh  [(size_t)NROWS*DM];
__device__ float  g_dd  [(size_t)NBH*SEQ*MP];
__device__ __half g_qph [(size_t)NBH*SEQ*MP];
__device__ __half g_kph [(size_t)NBH*SEQ*MP];
__device__ float  g_kvs2[(size_t)NBH*MP*HD];
__device__ __half g_kvsTh[(size_t)NBH*KVR*MP];
__device__ float  g_numer[(size_t)NBH*SEQ*KVR];
__device__ __half g_attnh[(size_t)NROWS*DM];
__device__ float  g_x1 [(size_t)NROWS*DM];
__device__ __half g_hnh [(size_t)NROWS*DM];
__device__ __half g_ffh [(size_t)NROWS*DFF];
// fp16 weight copies
__device__ __half g_wq[(size_t)DM*DM];
__device__ __half g_wk[(size_t)DM*DM];
__device__ __half g_wv[(size_t)DM*DM];
__device__ __half g_wo[(size_t)DM*DM];
__device__ __half g_w1[(size_t)DFF*DM];
__device__ __half g_w2[(size_t)DM*DFF];
__device__ __half g_pj[(size_t)MFEAT*HD];

// ===================== helpers =====================
static __device__ __forceinline__ uint32_t smem_u32(const void* p) {
    uint32_t a;
    asm("{ .reg .u64 t; cvta.to.shared.u64 t, %1; cvt.u32.u64 %0, t; }"
        : "=r"(a) : "l"(p));
    return a;
}
static __device__ __forceinline__ void cp16(uint32_t dst, const void* src, int sz) {
    asm volatile("cp.async.cg.shared.global [%0], [%1], 16, %2;"
                 :: "r"(dst), "l"(src), "r"(sz));
}
#define CP_COMMIT() asm volatile("cp.async.commit_group;" ::: "memory")
#define CP_WAIT1()  asm volatile("cp.async.wait_group 1;" ::: "memory")

static __device__ __forceinline__ void mma16(float* c, const uint32_t* a, const uint32_t* b) {
    asm volatile(
        "mma.sync.aligned.m16n8k16.row.col.f32.f16.f16.f32 "
        "{%0,%1,%2,%3}, {%4,%5,%6,%7}, {%8,%9}, {%0,%1,%2,%3};"
        : "+f"(c[0]), "+f"(c[1]), "+f"(c[2]), "+f"(c[3])
        : "r"(a[0]), "r"(a[1]), "r"(a[2]), "r"(a[3]), "r"(b[0]), "r"(b[1]));
}
static __device__ __forceinline__ void ldsm4t(uint32_t* r, uint32_t addr) {
    asm volatile("ldmatrix.sync.aligned.m8n8.x4.trans.shared.b16 {%0,%1,%2,%3}, [%4];"
        : "=r"(r[0]), "=r"(r[1]), "=r"(r[2]), "=r"(r[3]) : "r"(addr));
}
static __device__ __forceinline__ void store2(__half* p, float x, float y) {
    *(__half2*)p = __floats2half2_rn(x, y);
}
static __device__ __forceinline__ void store2(float* p, float x, float y) {
    *(float2*)p = make_float2(x, y);
}

// ===================== fp16 mma.sync NT GEMM =====================
// C[M,N] = A[M,K]*B[N,K]^T (+bias +res, relu). A,B fp16 K-major; fp32 accum.
// M mult of 128; K mult of 32; N even (predicated). Fragment-ordered smem:
//   A: [kblk(2)][mtile(8)][reg(4)][lane(32)] b32 ; B: [kblk(2)][ntile(16)][reg(2)][lane(32)]
#define HSTG 4096              // b32 per stage (A 2048 + B 2048) = 16KB
#define HSM  (2*HSTG*4)        // 32KB

template<bool RELU, bool RES, bool BIAS, typename CT>
__global__ __launch_bounds__(256)
void hgemm(const __half* __restrict__ A, const __half* __restrict__ B,
           const float* __restrict__ bias, const float* __restrict__ res,
           CT* __restrict__ C,
           int M, int N, int K, int lda, int ldb, int ldc,
           long long sAo, long long sAi, long long sBo, long long sBi,
           long long sCo, long long sCi, int zdiv)
{
    extern __shared__ uint32_t smem[];
    const int tid = threadIdx.x, lane = tid & 31, w = tid >> 5;
    const int wm = w & 1, wn = w >> 1;
    const uint32_t sbase = smem_u32(smem);

    const int z = blockIdx.z;
    const int zo = z / zdiv, zi = z - zo * zdiv;
    const __half* Ag = A + (size_t)zo * sAo + (size_t)zi * sAi;
    const __half* Bg = B + (size_t)zo * sBo + (size_t)zi * sBi;
    CT* Cg = C + (size_t)zo * sCo + (size_t)zi * sCi;
    const int m0 = blockIdx.y * 128, n0 = blockIdx.x * 128;

    const __half* asrc[2]; uint32_t adst[2];
    const __half* bsrc[2]; uint32_t bdst[2]; int bsz[2];
    #pragma unroll
    for (int j = 0; j < 2; j++) {
        int c = j * 256 + tid;
        int row = c >> 2, o = c & 3;
        {
            int reg = ((row >> 3) & 1) + ((o & 1) << 1);
            int idx = (((o >> 1) * 8 + (row >> 4)) * 4 + reg) * 32 + (row & 7) * 4;
            adst[j] = sbase + idx * 4;
            asrc[j] = Ag + (size_t)(m0 + row) * lda + o * 8;
        }
        {
            int reg = o & 1;
            int idx = 2048 + (((o >> 1) * 16 + (row >> 3)) * 2 + reg) * 32 + (row & 7) * 4;
            bdst[j] = sbase + idx * 4;
            int rr = (n0 + row) < N ? (n0 + row) : 0;
            bsrc[j] = Bg + (size_t)rr * ldb + o * 8;
            bsz[j] = (n0 + row) < N ? 16 : 0;
        }
    }

    float acc[4][4][4];
    #pragma unroll
    for (int a = 0; a < 4; a++)
        #pragma unroll
        for (int b = 0; b < 4; b++)
            #pragma unroll
            for (int c = 0; c < 4; c++) acc[a][b][c] = 0.f;

    const int nk = K >> 5;
    #pragma unroll
    for (int j = 0; j < 2; j++) { cp16(adst[j], asrc[j], 16); cp16(bdst[j], bsrc[j], bsz[j]); }
    CP_COMMIT();

    for (int i = 0; i < nk; i++) {
        if (i + 1 < nk) {
            uint32_t so = (uint32_t)((i + 1) & 1) * (HSTG * 4);
            int koff = (i + 1) * 32;
            #pragma unroll
            for (int j = 0; j < 2; j++) {
                cp16(adst[j] + so, asrc[j] + koff, 16);
                cp16(bdst[j] + so, bsrc[j] + koff, bsz[j]);
            }
        }
        CP_COMMIT();
        CP_WAIT1();
        __syncthreads();
        const uint32_t* sa = smem + (i & 1) * HSTG;
        const uint32_t* sb = sa + 2048;
        #pragma unroll
        for (int kb = 0; kb < 2; kb++) {
            uint32_t af[4][4], bf[4][2];
            #pragma unroll
            for (int mt = 0; mt < 4; mt++) {
                const uint32_t* p = sa + (size_t)((kb * 8 + wm * 4 + mt) * 4) * 32 + lane;
                af[mt][0] = p[0]; af[mt][1] = p[32]; af[mt][2] = p[64]; af[mt][3] = p[96];
            }
            #pragma unroll
            for (int nt = 0; nt < 4; nt++) {
                const uint32_t* p = sb + (size_t)((kb * 16 + wn * 4 + nt) * 2) * 32 + lane;
                bf[nt][0] = p[0]; bf[nt][1] = p[32];
            }
            #pragma unroll
            for (int mt = 0; mt < 4; mt++)
                #pragma unroll
                for (int nt = 0; nt < 4; nt++)
                    mma16(acc[mt][nt], af[mt], bf[nt]);
        }
        __syncthreads();
    }

    #pragma unroll
    for (int mt = 0; mt < 4; mt++) {
        const int r0 = m0 + wm * 64 + mt * 16 + (lane >> 2);
        #pragma unroll
        for (int nt = 0; nt < 4; nt++) {
            const int c0 = n0 + wn * 32 + nt * 8 + (lane & 3) * 2;
            if (c0 < N) {
                float bx = 0.f, by = 0.f;
                if (BIAS) { float2 b2 = *(const float2*)(bias + c0); bx = b2.x; by = b2.y; }
                float x0 = acc[mt][nt][0] + bx, x1 = acc[mt][nt][1] + by;
                float y0 = acc[mt][nt][2] + bx, y1 = acc[mt][nt][3] + by;
                if (RES) {
                    float2 ra = *(const float2*)(res + (size_t)r0 * ldc + c0);
                    float2 rb = *(const float2*)(res + (size_t)(r0 + 8) * ldc + c0);
                    x0 += ra.x; x1 += ra.y; y0 += rb.x; y1 += rb.y;
                }
                if (RELU) {
                    x0 = fmaxf(x0, 0.f); x1 = fmaxf(x1, 0.f);
                    y0 = fmaxf(y0, 0.f); y1 = fmaxf(y1, 0.f);
                }
                store2(Cg + (size_t)r0 * ldc + c0, x0, x1);
                store2(Cg + (size_t)(r0 + 8) * ldc + c0, y0, y1);
            }
        }
    }
}

// ===================== fp16 TN GEMM for kvs (ldmatrix.trans) =====================
// kvs2[bh][m][d] = sum_l kph[bh][l][m] * vh[b][l][h*64+d]
// Tiles: 128(m) x 64(d) x 32(l). Raw l-major smem tiles + ldmatrix.x4.trans.
#define TNSTG 3072             // b32 per stage: A 2048 (8KB) + B 1024 (4KB)
#define TNSM (2*TNSTG*4)       // 24KB

__global__ __launch_bounds__(256)
void kvs_gemm(const __half* __restrict__ kp, const __half* __restrict__ v,
              float* __restrict__ kvs2)
{
    extern __shared__ uint32_t smem[];
    const int tid = threadIdx.x, lane = tid & 31, w = tid >> 5;
    const int wm = w >> 2, wn = w & 3;
    const uint32_t sbase = smem_u32(smem);
    const int bh = blockIdx.z, b = bh >> 4, h = bh & 15;
    const int m0 = blockIdx.x * 128;
    const __half* Ag = kp + (size_t)bh * SEQ * MP;
    const __half* Bg = v + (size_t)b * SEQ * DM + h * HD;

    // loaders: A 2 chunks/thread (32 rows x 16 u), B 1 chunk (32 rows x 8 u)
    const __half* asrc[2]; uint32_t adst[2]; int asz[2];
    #pragma unroll
    for (int j = 0; j < 2; j++) {
        int c = j * 256 + tid;
        int row = c >> 4, u = c & 15;
        adst[j] = sbase + row * 256 + ((u ^ (row & 7)) << 4);
        bool val = (m0 + u * 8) < MP;
        asrc[j] = Ag + (size_t)row * MP + (val ? (m0 + u * 8) : 0);
        asz[j] = val ? 16 : 0;
    }
    const int brow = tid >> 3, bu = tid & 7;
    const uint32_t bdst = sbase + 8192 + brow * 128 + ((bu ^ (brow & 7)) << 4);
    const __half* bsrc = Bg + (size_t)brow * DM + bu * 8;

    float acc[4][2][4];
    #pragma unroll
    for (int a = 0; a < 4; a++)
        #pragma unroll
        for (int bb = 0; bb < 2; bb++)
            #pragma unroll
            for (int c = 0; c < 4; c++) acc[a][bb][c] = 0.f;

    const int nk = SEQ / 32;   // 64
    #pragma unroll
    for (int j = 0; j < 2; j++) cp16(adst[j], asrc[j], asz[j]);
    cp16(bdst, bsrc, 16);
    CP_COMMIT();

    const int q = lane >> 3, r = lane & 7;
    for (int i = 0; i < nk; i++) {
        if (i + 1 < nk) {
            uint32_t so = (uint32_t)((i + 1) & 1) * (TNSTG * 4);
            size_t ko = (size_t)(i + 1) * 32;
            #pragma unroll
            for (int j = 0; j < 2; j++) cp16(adst[j] + so, asrc[j] + ko * MP, asz[j]);
            cp16(bdst + so, bsrc + ko * DM, 16);
        }
        CP_COMMIT();
        CP_WAIT1();
        __syncthreads();
        const uint32_t st = sbase + (uint32_t)(i & 1) * (TNSTG * 4);
        #pragma unroll
        for (int kb = 0; kb < 2; kb++) {
            uint32_t bf[4];
            {
                int krow = kb * 16 + (q & 1) * 8 + r;
                int du = wn * 2 + (q >> 1);
                ldsm4t(bf, st + 8192 + krow * 128 + ((du ^ (krow & 7)) << 4));
            }
            #pragma unroll
            for (int mt = 0; mt < 4; mt++) {
                uint32_t af[4];
                int krow = kb * 16 + (q >> 1) * 8 + r;
                int mu = wm * 8 + mt * 2 + (q & 1);
                ldsm4t(af, st + krow * 256 + ((mu ^ (krow & 7)) << 4));
                mma16(acc[mt][0], af, bf);
                mma16(acc[mt][1], af, bf + 2);
            }
        }
        __syncthreads();
    }

    float* outp = kvs2 + (size_t)bh * MP * HD;
    #pragma unroll
    for (int mt = 0; mt < 4; mt++) {
        const int r0 = m0 + wm * 64 + mt * 16 + (lane >> 2);
        #pragma unroll
        for (int nt = 0; nt < 2; nt++) {
            const int c0 = wn * 16 + nt * 8 + (lane & 3) * 2;
            if (r0 < MP)
                *(float2*)(outp + (size_t)r0 * HD + c0) = make_float2(acc[mt][nt][0], acc[mt][nt][1]);
            if (r0 + 8 < MP)
                *(float2*)(outp + (size_t)(r0 + 8) * HD + c0) = make_float2(acc[mt][nt][2], acc[mt][nt][3]);
        }
    }
}

// ----------------- fp32 -> fp16 convert -----------------
__global__ void cvt_kernel(const float* __restrict__ s, __half* __restrict__ d, int n4)
{
    int i = blockIdx.x * 256 + threadIdx.x;
    if (i >= n4) return;
    float4 v = ((const float4*)s)[i];
    __half2* o = (__half2*)d + (size_t)i * 2;
    o[0] = __floats2half2_rn(v.x, v.y);
    o[1] = __floats2half2_rn(v.z, v.w);
}

// ----------------- LayerNorm (fp32 in, fp16 out) -----------------
__global__ __launch_bounds__(256)
void ln_kernel(const float* __restrict__ x, const float* __restrict__ g,
               const float* __restrict__ beta, __half* __restrict__ y)
{
    size_t row = blockIdx.x;
    int tid = threadIdx.x;
    float4 v = ((const float4*)(x + row * DM))[tid];
    float s = v.x + v.y + v.z + v.w;
    __shared__ float sm[8];
    #pragma unroll
    for (int o = 16; o > 0; o >>= 1) s += __shfl_xor_sync(~0u, s, o);
    if ((tid & 31) == 0) sm[tid >> 5] = s;
    __syncthreads();
    float mu = 0.f;
    #pragma unroll
    for (int i = 0; i < 8; i++) mu += sm[i];
    mu *= (1.f / (float)DM);
    float dx = v.x - mu, dy = v.y - mu, dz = v.z - mu, dw = v.w - mu;
    float q = dx*dx + dy*dy + dz*dz + dw*dw;
    __syncthreads();
    #pragma unroll
    for (int o = 16; o > 0; o >>= 1) q += __shfl_xor_sync(~0u, q, o);
    if ((tid & 31) == 0) sm[tid >> 5] = q;
    __syncthreads();
    float var = 0.f;
    #pragma unroll
    for (int i = 0; i < 8; i++) var += sm[i];
    var *= (1.f / (float)DM);
    float inv = rsqrtf(var + 1e-5f);
    float4 gg = ((const float4*)g)[tid];
    float4 bb = ((const float4*)beta)[tid];
    __half2* o = (__half2*)(y + row * DM) + tid * 2;
    o[0] = __floats2half2_rn(dx * inv * gg.x + bb.x, dy * inv * gg.y + bb.y);
    o[1] = __floats2half2_rn(dz * inv * gg.z + bb.z, dw * inv * gg.w + bb.w);
}

// ----------------- q exp epilogue: dd fp32 -> qph fp16 -----------------
__global__ __launch_bounds__(256)
void qexp_kernel(const float* __restrict__ dd, const __half* __restrict__ q,
                 __half* __restrict__ qph)
{
    const int r = blockIdx.x * 8 + (threadIdx.x >> 5);
    const int lane = threadIdx.x & 31;
    const int bh = r >> 11, l = r & (SEQ - 1);
    const int b = bh >> 4, h = bh & 15;
    const float* row = dd + (size_t)r * MP;
    __half* orow = qph + (size_t)r * MP;
    float vals[17];
    float mx = -1e30f;
    #pragma unroll
    for (int j = 0; j < 17; j++) {
        int m = j * 32 + lane;
        if (m < MFEAT) { float v = DN * row[m]; vals[j] = v; mx = fmaxf(mx, v); }
    }
    #pragma unroll
    for (int o = 16; o > 0; o >>= 1) mx = fmaxf(mx, __shfl_xor_sync(~0u, mx, o));
    const __half* qr = q + ((size_t)(b * SEQ + l)) * DM + h * HD;
    float a = __half2float(qr[lane]), bb2 = __half2float(qr[lane + 32]);
    float s = a * a + bb2 * bb2;
    #pragma unroll
    for (int o = 16; o > 0; o >>= 1) s += __shfl_xor_sync(~0u, s, o);
    float dia = 0.5f * DN * DN * s;
    #pragma unroll
    for (int j = 0; j < 18; j++) {
        int m = j * 32 + lane;
        if (m < MP)
            orow[m] = __float2half(
                (m < MFEAT) ? RATIO * (__expf(vals[j] - mx - dia) + FEPS) : 0.f);
    }
}

// ----------------- k exp epilogue: dd fp32 -> kph fp16 -----------------
__global__ __launch_bounds__(256)
void kexp_kernel(const float* __restrict__ dd, const __half* __restrict__ k,
                 const unsigned char* __restrict__ padmask, __half* __restrict__ kph)
{
    const int b = blockIdx.x >> 11, l = blockIdx.x & (SEQ - 1);
    const int t = threadIdx.x;
    const int h = t >> 4, j = t & 15;
    __shared__ float red[256], red2[256], diag[NH];
    __shared__ float stab_s;
    const float* row = dd + ((size_t)(b * NH + h) * SEQ + l) * MP;
    __half* orow = kph + ((size_t)(b * NH + h) * SEQ + l) * MP;
    float mx = -1e30f;
    for (int m = j; m < MFEAT; m += 16) mx = fmaxf(mx, DN * row[m]);
    red[t] = mx;
    const __half* kr = k + ((size_t)(b * SEQ + l)) * DM + h * HD;
    float s = 0.f;
    #pragma unroll
    for (int d = 0; d < 4; d++) { float v = __half2float(kr[j + 16 * d]); s = fmaf(v, v, s); }
    red2[t] = s;
    __syncthreads();
    for (int st = 128; st > 0; st >>= 1) {
        if (t < st) red[t] = fmaxf(red[t], red[t + st]);
        __syncthreads();
    }
    if (t < NH) {
        float ds = 0.f;
        #pragma unroll
        for (int jj = 0; jj < 16; jj++) ds += red2[t * 16 + jj];
        diag[t] = 0.5f * DN * DN * ds;
    }
    if (t == 0) stab_s = red[0];
    __syncthreads();
    const float stab = stab_s;
    const float keep = padmask[b * SEQ + l] ? 0.f : 1.f;
    const float dia = diag[h];
    for (int m = j; m < MP; m += 16)
        orow[m] = __float2half(
            (m < MFEAT) ? keep * RATIO * (__expf(DN * row[m] - stab - dia) + FEPS) : 0.f);
}

// ----------------- assemble kvsT rows 0..63 from kvs2 (transpose) ------------
__global__ void assemble_kernel(const float* __restrict__ kvs2, __half* __restrict__ kvsT)
{
    int bh = blockIdx.y;
    int idx = blockIdx.x * 256 + threadIdx.x;   // over 64*576
    if (idx >= HD * MP) return;
    int d = idx / MP, m = idx - d * MP;
    kvsT[(size_t)bh * KVR * MP + (size_t)d * MP + m] =
        __float2half(kvs2[(size_t)bh * MP * HD + (size_t)m * HD + d]);
}

// ks_sum (row 64 of kvsT) + zero rows 65..127
__global__ void kssum_kernel(const __half* __restrict__ kp, __half* __restrict__ kvsT)
{
    int bh = blockIdx.y;
    int m = blockIdx.x * 192 + threadIdx.x;
    if (m >= MP) return;
    const __half* p = kp + (size_t)bh * SEQ * MP + m;
    float a0 = 0.f, a1 = 0.f, a2 = 0.f, a3 = 0.f;
    for (int l = 0; l < SEQ; l += 4) {
        a0 += __half2float(p[(size_t)l * MP]);
        a1 += __half2float(p[(size_t)(l + 1) * MP]);
        a2 += __half2float(p[(size_t)(l + 2) * MP]);
        a3 += __half2float(p[(size_t)(l + 3) * MP]);
    }
    __half* o = kvsT + (size_t)bh * KVR * MP;
    o[(size_t)64 * MP + m] = __float2half((a0 + a1) + (a2 + a3));
    for (int r = 65; r < KVR; r++) o[(size_t)r * MP + m] = __float2half(0.f);
}

// attn[b,l,h*64+d] = numer[bh,l,d] / (numer[bh,l,64] + 1e-6) -> fp16
__global__ void divide_kernel(const float* __restrict__ numer, __half* __restrict__ attn)
{
    size_t i = (size_t)blockIdx.x * 256 + threadIdx.x;
    if (i >= (size_t)NBH * SEQ * HD) return;
    int d = (int)(i & 63);
    int l = (int)((i >> 6) & (SEQ - 1));
    int bh = (int)(i >> 17);
    int b = bh >> 4, h = bh & 15;
    const float* row = numer + ((size_t)bh * SEQ + l) * KVR;
    float den = row[64] + 1e-6f;
    attn[((size_t)(b * SEQ + l)) * DM + h * HD + d] = __float2half(row[d] / den);
}

// ----------------- launch -----------------
static void* getsym(const void* shadow)
{
    void* p = nullptr;
    cudaGetSymbolAddress(&p, shadow);
    return p;
}

extern "C" void kernel_launch(void* const* d_in, const int* in_sizes, int n_in,
                              void* d_out, int out_size)
{
    const float* src    = (const float*)d_in[0];
    const unsigned char* mask = (const unsigned char*)d_in[1];
    const float* proj   = (const float*)d_in[2];
    const float* q_w    = (const float*)d_in[3];
    const float* q_b    = (const float*)d_in[4];
    const float* k_w    = (const float*)d_in[5];
    const float* k_b    = (const float*)d_in[6];
    const float* v_w    = (const float*)d_in[7];
    const float* v_b    = (const float*)d_in[8];
    const float* out_w  = (const float*)d_in[9];
    const float* out_b  = (const float*)d_in[10];
    const float* ln1_g  = (const float*)d_in[11];
    const float* ln1_b  = (const float*)d_in[12];
    const float* ln2_g  = (const float*)d_in[13];
    const float* ln2_b  = (const float*)d_in[14];
    const float* ff1_w  = (const float*)d_in[15];
    const float* ff1_b  = (const float*)d_in[16];
    const float* ff2_w  = (const float*)d_in[17];
    const float* ff2_b  = (const float*)d_in[18];
    float* out = (float*)d_out;

    __half* p_xn   = (__half*)getsym(g_xnh);
    __half* p_q    = (__half*)getsym(g_qh);
    __half* p_k    = (__half*)getsym(g_kh);
    __half* p_v    = (__half*)getsym(g_vh);
    float*  p_dd   = (float*)getsym(g_dd);
    __half* p_qp   = (__half*)getsym(g_qph);
    __half* p_kp   = (__half*)getsym(g_kph);
    float*  p_kvs2 = (float*)getsym(g_kvs2);
    __half* p_kvsT = (__half*)getsym(g_kvsTh);
    float*  p_numer= (float*)getsym(g_numer);
    __half* p_attn = (__half*)getsym(g_attnh);
    float*  p_x1   = (float*)getsym(g_x1);
    __half* p_hn   = (__half*)getsym(g_hnh);
    __half* p_ff   = (__half*)getsym(g_ffh);
    __half* p_wq   = (__half*)getsym(g_wq);
    __half* p_wk   = (__half*)getsym(g_wk);
    __half* p_wv   = (__half*)getsym(g_wv);
    __half* p_wo   = (__half*)getsym(g_wo);
    __half* p_w1   = (__half*)getsym(g_w1);
    __half* p_w2   = (__half*)getsym(g_w2);
    __half* p_pj   = (__half*)getsym(g_pj);

    cudaFuncSetAttribute(hgemm<false,false,true,__half>,
                         cudaFuncAttributeMaxDynamicSharedMemorySize, HSM);
    cudaFuncSetAttribute(hgemm<false,false,false,float>,
                         cudaFuncAttributeMaxDynamicSharedMemorySize, HSM);
    cudaFuncSetAttribute(hgemm<false,true,true,float>,
                         cudaFuncAttributeMaxDynamicSharedMemorySize, HSM);
    cudaFuncSetAttribute(hgemm<true,false,true,__half>,
                         cudaFuncAttributeMaxDynamicSharedMemorySize, HSM);
    cudaFuncSetAttribute(kvs_gemm,
                         cudaFuncAttributeMaxDynamicSharedMemorySize, TNSM);

    // 0) weights -> fp16
    {
        int n4 = DM * DM / 4;
        cvt_kernel<<<(n4 + 255) / 256, 256>>>(q_w, p_wq, n4);
        cvt_kernel<<<(n4 + 255) / 256, 256>>>(k_w, p_wk, n4);
        cvt_kernel<<<(n4 + 255) / 256, 256>>>(v_w, p_wv, n4);
        cvt_kernel<<<(n4 + 255) / 256, 256>>>(out_w, p_wo, n4);
        int nf = DFF * DM / 4;
        cvt_kernel<<<(nf + 255) / 256, 256>>>(ff1_w, p_w1, nf);
        cvt_kernel<<<(nf + 255) / 256, 256>>>(ff2_w, p_w2, nf);
        int np = MFEAT * HD / 4;
        cvt_kernel<<<(np + 255) / 256, 256>>>(proj, p_pj, np);
    }

    // 1) LN1 -> fp16
    ln_kernel<<<NROWS, 256>>>(src, ln1_g, ln1_b, p_xn);

    // 2) QKV projections -> fp16
    dim3 gQ(DM / 128, NROWS / 128, 1);
    hgemm<false,false,true,__half><<<gQ, 256, HSM>>>(
        p_xn, p_wq, q_b, nullptr, p_q, NROWS, DM, DM, DM, DM, DM,
        0, 0, 0, 0, 0, 0, 1);
    hgemm<false,false,true,__half><<<gQ, 256, HSM>>>(
        p_xn, p_wk, k_b, nullptr, p_k, NROWS, DM, DM, DM, DM, DM,
        0, 0, 0, 0, 0, 0, 1);
    hgemm<false,false,true,__half><<<gQ, 256, HSM>>>(
        p_xn, p_wv, v_b, nullptr, p_v, NROWS, DM, DM, DM, DM, DM,
        0, 0, 0, 0, 0, 0, 1);

    // 3) feature GEMMs -> dd fp32, then exp epilogues -> fp16 (reuse dd buffer)
    dim3 gF((MFEAT + 127) / 128, SEQ / 128, NBH);
    hgemm<false,false,false,float><<<gF, 256, HSM>>>(
        p_q, p_pj, nullptr, nullptr, p_dd, SEQ, MFEAT, HD, DM, HD, MP,
        (long long)SEQ * DM, HD, 0, 0, (long long)NH * SEQ * MP, (long long)SEQ * MP, NH);
    qexp_kernel<<<NBH * SEQ / 8, 256>>>(p_dd, p_q, p_qp);
    hgemm<false,false,false,float><<<gF, 256, HSM>>>(
        p_k, p_pj, nullptr, nullptr, p_dd, SEQ, MFEAT, HD, DM, HD, MP,
        (long long)SEQ * DM, HD, 0, 0, (long long)NH * SEQ * MP, (long long)SEQ * MP, NH);
    kexp_kernel<<<BATCHN * SEQ, 256>>>(p_dd, p_k, mask, p_kp);

    // 4) kvs via fp16 TN mma GEMM, then assemble + ks_sum
    kvs_gemm<<<dim3((MP + 127) / 128, 1, NBH), 256, TNSM>>>(p_kp, p_v, p_kvs2);
    assemble_kernel<<<dim3((HD * MP + 255) / 256, NBH), 256>>>(p_kvs2, p_kvsT);
    kssum_kernel<<<dim3(3, NBH), 192>>>(p_kp, p_kvsT);

    // 5) numer (+denom as col 64): batched GEMM, qp @ kvsT^T, N=128 dense
    hgemm<false,false,false,float><<<dim3(1, SEQ / 128, NBH), 256, HSM>>>(
        p_qp, p_kvsT, nullptr, nullptr, p_numer, SEQ, KVR, MP, MP, MP, KVR,
        (long long)SEQ * MP, 0, (long long)KVR * MP, 0, (long long)SEQ * KVR, 0, 1);

    // 6) divide + head interleave -> fp16
    divide_kernel<<<(NBH * SEQ * HD) / 256, 256>>>(p_numer, p_attn);

    // 7) out projection + residual(src) -> x1 fp32
    hgemm<false,true,true,float><<<gQ, 256, HSM>>>(
        p_attn, p_wo, out_b, src, p_x1, NROWS, DM, DM, DM, DM, DM,
        0, 0, 0, 0, 0, 0, 1);

    // 8) LN2 -> fp16
    ln_kernel<<<NROWS, 256>>>(p_x1, ln2_g, ln2_b, p_hn);

    // 9) FF1 (+ReLU) -> fp16
    hgemm<true,false,true,__half><<<dim3(DFF / 128, NROWS / 128, 1), 256, HSM>>>(
        p_hn, p_w1, ff1_b, nullptr, p_ff, NROWS, DFF, DM, DM, DM, DFF,
        0, 0, 0, 0, 0, 0, 1);

    // 10) FF2 + residual(x1) -> final fp32 output
    hgemm<false,true,true,float><<<gQ, 256, HSM>>>(
        p_ff, p_w2, ff2_b, p_x1, out, NROWS, DM, DFF, DFF, DFF, DM,
        0, 0, 0, 0, 0, 0, 1);
}

// round 6
// speedup vs baseline: 7.3310x; 1.0391x over previous
#include <cuda_runtime.h>
#include <cuda_fp16.h>
#include <cstdint>

#define BATCHN 4
#define SEQ 2048
#define DM 1024
#define NH 16
#define HD 64
#define DFF 4096
#define MFEAT 532
#define MP 576             // padded feature dim
#define NROWS (BATCHN*SEQ) // 8192
#define NBH (BATCHN*NH)    // 64
#define KVR 128            // kvs^T rows: 64 dims + 1 sum + 63 pad
#define NXT 5              // feature GEMM x-tiles (ceil(532/128))

#define DN 0.35355339059327373f          /* 64^-0.25 */
#define RATIO 0.0433555f                 /* 1/sqrt(532) */
#define FEPS 1e-6f

// ----------------- scratch (device globals; no allocation) -----------------
__device__ __half g_xnh [(size_t)NROWS*DM];
__device__ __half g_qh  [(size_t)NROWS*DM];
__device__ __half g_kh  [(size_t)NROWS*DM];
__device__ __half g_vh  [(size_t)NROWS*DM];
__device__ float  g_dd  [(size_t)NBH*SEQ*MP];
__device__ __half g_qph [(size_t)NBH*SEQ*MP];
__device__ __half g_kph [(size_t)NBH*SEQ*MP];
__device__ float  g_pmaxq[(size_t)NBH*NXT*SEQ];
__device__ float  g_pmaxk[(size_t)NBH*NXT*SEQ];
__device__ float  g_stab[(size_t)BATCHN*SEQ];
__device__ float  g_kvs2[(size_t)NBH*MP*HD];
__device__ __half g_kvsTh[(size_t)NBH*KVR*MP];
__device__ float  g_numer[(size_t)NBH*SEQ*KVR];
__device__ __half g_attnh[(size_t)NROWS*DM];
__device__ float  g_x1 [(size_t)NROWS*DM];
__device__ __half g_hnh [(size_t)NROWS*DM];
__device__ __half g_ffh [(size_t)NROWS*DFF];
// fp16 weight copies
__device__ __half g_wq[(size_t)DM*DM];
__device__ __half g_wk[(size_t)DM*DM];
__device__ __half g_wv[(size_t)DM*DM];
__device__ __half g_wo[(size_t)DM*DM];
__device__ __half g_w1[(size_t)DFF*DM];
__device__ __half g_w2[(size_t)DM*DFF];
__device__ __half g_pj[(size_t)MFEAT*HD];

// ===================== helpers =====================
static __device__ __forceinline__ uint32_t smem_u32(const void* p) {
    uint32_t a;
    asm("{ .reg .u64 t; cvta.to.shared.u64 t, %1; cvt.u32.u64 %0, t; }"
        : "=r"(a) : "l"(p));
    return a;
}
static __device__ __forceinline__ void cp16(uint32_t dst, const void* src, int sz) {
    asm volatile("cp.async.cg.shared.global [%0], [%1], 16, %2;"
                 :: "r"(dst), "l"(src), "r"(sz));
}
#define CP_COMMIT() asm volatile("cp.async.commit_group;" ::: "memory")
#define CP_WAIT1()  asm volatile("cp.async.wait_group 1;" ::: "memory")
#define CP_WAIT2()  asm volatile("cp.async.wait_group 2;" ::: "memory")

static __device__ __forceinline__ void mma16(float* c, const uint32_t* a, const uint32_t* b) {
    asm volatile(
        "mma.sync.aligned.m16n8k16.row.col.f32.f16.f16.f32 "
        "{%0,%1,%2,%3}, {%4,%5,%6,%7}, {%8,%9}, {%0,%1,%2,%3};"
        : "+f"(c[0]), "+f"(c[1]), "+f"(c[2]), "+f"(c[3])
        : "r"(a[0]), "r"(a[1]), "r"(a[2]), "r"(a[3]), "r"(b[0]), "r"(b[1]));
}
static __device__ __forceinline__ void ldsm4t(uint32_t* r, uint32_t addr) {
    asm volatile("ldmatrix.sync.aligned.m8n8.x4.trans.shared.b16 {%0,%1,%2,%3}, [%4];"
        : "=r"(r[0]), "=r"(r[1]), "=r"(r[2]), "=r"(r[3]) : "r"(addr));
}
static __device__ __forceinline__ void store2(__half* p, float x, float y) {
    *(__half2*)p = __floats2half2_rn(x, y);
}
static __device__ __forceinline__ void store2(float* p, float x, float y) {
    *(float2*)p = make_float2(x, y);
}
// order-preserving float<->uint for max
static __device__ __forceinline__ unsigned encf(float f) {
    unsigned u = __float_as_uint(f);
    return (u & 0x80000000u) ? ~u : (u | 0x80000000u);
}
static __device__ __forceinline__ float decf(unsigned u) {
    u = (u & 0x80000000u) ? (u ^ 0x80000000u) : ~u;
    return __uint_as_float(u);
}

// ===================== v1: fp16 mma NT GEMM, 128x128 tile =====================
// C[M,N] = A[M,K]*B[N,K]^T. N predicated. Optional STAB: per-row max of the
// valid columns of this CTA written to pmax[(z*NX + bx)*M + row].
#define HSTG 4096
#define HSM  (2*HSTG*4)

template<bool STAB, typename CT>
__global__ __launch_bounds__(256)
void hgemm(const __half* __restrict__ A, const __half* __restrict__ B,
           CT* __restrict__ C, float* __restrict__ pmax, int NX,
           int M, int N, int K, int lda, int ldb, int ldc,
           long long sAo, long long sAi, long long sBo, long long sBi,
           long long sCo, long long sCi, int zdiv)
{
    extern __shared__ uint32_t smem[];
    const int tid = threadIdx.x, lane = tid & 31, w = tid >> 5;
    const int wm = w & 1, wn = w >> 1;
    const uint32_t sbase = smem_u32(smem);

    const int z = blockIdx.z;
    const int zo = z / zdiv, zi = z - zo * zdiv;
    const __half* Ag = A + (size_t)zo * sAo + (size_t)zi * sAi;
    const __half* Bg = B + (size_t)zo * sBo + (size_t)zi * sBi;
    CT* Cg = C + (size_t)zo * sCo + (size_t)zi * sCi;
    const int m0 = blockIdx.y * 128, n0 = blockIdx.x * 128;

    const __half* asrc[2]; uint32_t adst[2];
    const __half* bsrc[2]; uint32_t bdst[2]; int bsz[2];
    #pragma unroll
    for (int j = 0; j < 2; j++) {
        int c = j * 256 + tid;
        int row = c >> 2, o = c & 3;
        {
            int reg = ((row >> 3) & 1) + ((o & 1) << 1);
            int idx = (((o >> 1) * 8 + (row >> 4)) * 4 + reg) * 32 + (row & 7) * 4;
            adst[j] = sbase + idx * 4;
            asrc[j] = Ag + (size_t)(m0 + row) * lda + o * 8;
        }
        {
            int reg = o & 1;
            int idx = 2048 + (((o >> 1) * 16 + (row >> 3)) * 2 + reg) * 32 + (row & 7) * 4;
            bdst[j] = sbase + idx * 4;
            int rr = (n0 + row) < N ? (n0 + row) : 0;
            bsrc[j] = Bg + (size_t)rr * ldb + o * 8;
            bsz[j] = (n0 + row) < N ? 16 : 0;
        }
    }

    float acc[4][4][4];
    #pragma unroll
    for (int a = 0; a < 4; a++)
        #pragma unroll
        for (int b = 0; b < 4; b++)
            #pragma unroll
            for (int c = 0; c < 4; c++) acc[a][b][c] = 0.f;

    const int nk = K >> 5;
    #pragma unroll
    for (int j = 0; j < 2; j++) { cp16(adst[j], asrc[j], 16); cp16(bdst[j], bsrc[j], bsz[j]); }
    CP_COMMIT();

    for (int i = 0; i < nk; i++) {
        if (i + 1 < nk) {
            uint32_t so = (uint32_t)((i + 1) & 1) * (HSTG * 4);
            int koff = (i + 1) * 32;
            #pragma unroll
            for (int j = 0; j < 2; j++) {
                cp16(adst[j] + so, asrc[j] + koff, 16);
                cp16(bdst[j] + so, bsrc[j] + koff, bsz[j]);
            }
        }
        CP_COMMIT();
        CP_WAIT1();
        __syncthreads();
        const uint32_t* sa = smem + (i & 1) * HSTG;
        const uint32_t* sb = sa + 2048;
        #pragma unroll
        for (int kb = 0; kb < 2; kb++) {
            uint32_t af[4][4], bf[4][2];
            #pragma unroll
            for (int mt = 0; mt < 4; mt++) {
                const uint32_t* p = sa + (size_t)((kb * 8 + wm * 4 + mt) * 4) * 32 + lane;
                af[mt][0] = p[0]; af[mt][1] = p[32]; af[mt][2] = p[64]; af[mt][3] = p[96];
            }
            #pragma unroll
            for (int nt = 0; nt < 4; nt++) {
                const uint32_t* p = sb + (size_t)((kb * 16 + wn * 4 + nt) * 2) * 32 + lane;
                bf[nt][0] = p[0]; bf[nt][1] = p[32];
            }
            #pragma unroll
            for (int mt = 0; mt < 4; mt++)
                #pragma unroll
                for (int nt = 0; nt < 4; nt++)
                    mma16(acc[mt][nt], af[mt], bf[nt]);
        }
        __syncthreads();
    }

    #pragma unroll
    for (int mt = 0; mt < 4; mt++) {
        const int r0 = m0 + wm * 64 + mt * 16 + (lane >> 2);
        #pragma unroll
        for (int nt = 0; nt < 4; nt++) {
            const int c0 = n0 + wn * 32 + nt * 8 + (lane & 3) * 2;
            if (c0 < N) {
                store2(Cg + (size_t)r0 * ldc + c0, acc[mt][nt][0], acc[mt][nt][1]);
                store2(Cg + (size_t)(r0 + 8) * ldc + c0, acc[mt][nt][2], acc[mt][nt][3]);
            }
        }
    }

    if (STAB) {
        __shared__ unsigned smax[128];
        if (tid < 128) smax[tid] = 0u;
        __syncthreads();
        #pragma unroll
        for (int mt = 0; mt < 4; mt++) {
            float v0 = -1e30f, v1 = -1e30f;
            #pragma unroll
            for (int nt = 0; nt < 4; nt++) {
                int c0 = n0 + wn * 32 + nt * 8 + (lane & 3) * 2;
                if (c0 < N) {
                    v0 = fmaxf(v0, fmaxf(acc[mt][nt][0], acc[mt][nt][1]));
                    v1 = fmaxf(v1, fmaxf(acc[mt][nt][2], acc[mt][nt][3]));
                }
            }
            v0 = fmaxf(v0, __shfl_xor_sync(~0u, v0, 1));
            v0 = fmaxf(v0, __shfl_xor_sync(~0u, v0, 2));
            v1 = fmaxf(v1, __shfl_xor_sync(~0u, v1, 1));
            v1 = fmaxf(v1, __shfl_xor_sync(~0u, v1, 2));
            if ((lane & 3) == 0) {
                int rl = wm * 64 + mt * 16 + (lane >> 2);
                atomicMax(&smax[rl], encf(v0));
                atomicMax(&smax[rl + 8], encf(v1));
            }
        }
        __syncthreads();
        if (tid < 128)
            pmax[((size_t)z * NX + blockIdx.x) * M + m0 + tid] = decf(smax[tid]);
    }
}

// ===================== v2: fp16 mma NT GEMM, 128x256 tile, 3-stage =====================
// N multiple of 256, M multiple of 128, K multiple of 32. bias/res/relu fused.
#define H2STG 6144               // b32 per stage (A 2048 + B 4096) = 24KB
#define H2SM  (3*H2STG*4)        // 72KB

template<bool RELU, bool RES, bool BIAS, typename CT>
__global__ __launch_bounds__(256)
void hgemm2(const __half* __restrict__ A, const __half* __restrict__ B,
            const float* __restrict__ bias, const float* __restrict__ res,
            CT* __restrict__ C, int M, int N, int K, int lda, int ldb, int ldc)
{
    extern __shared__ uint32_t smem[];
    const int tid = threadIdx.x, lane = tid & 31, w = tid >> 5;
    const int wm = w & 1, wn = w >> 1;
    const uint32_t sbase = smem_u32(smem);
    const int m0 = blockIdx.y * 128, n0 = blockIdx.x * 256;

    const __half* asrc[2]; uint32_t adst[2];
    #pragma unroll
    for (int j = 0; j < 2; j++) {
        int c = j * 256 + tid;
        int row = c >> 2, o = c & 3;
        int reg = ((row >> 3) & 1) + ((o & 1) << 1);
        int idx = (((o >> 1) * 8 + (row >> 4)) * 4 + reg) * 32 + (row & 7) * 4;
        adst[j] = sbase + idx * 4;
        asrc[j] = A + (size_t)(m0 + row) * lda + o * 8;
    }
    const __half* bsrc[4]; uint32_t bdst[4];
    #pragma unroll
    for (int j = 0; j < 4; j++) {
        int c = j * 256 + tid;
        int row = c >> 2, o = c & 3;
        int reg = o & 1;
        int idx = 2048 + (((o >> 1) * 32 + (row >> 3)) * 2 + reg) * 32 + (row & 7) * 4;
        bdst[j] = sbase + idx * 4;
        bsrc[j] = B + (size_t)(n0 + row) * ldb + o * 8;
    }

    float acc[4][8][4];
    #pragma unroll
    for (int a = 0; a < 4; a++)
        #pragma unroll
        for (int b = 0; b < 8; b++)
            #pragma unroll
            for (int c = 0; c < 4; c++) acc[a][b][c] = 0.f;

    const int nk = K >> 5;
    #pragma unroll
    for (int s = 0; s < 2; s++) {
        uint32_t so = (uint32_t)s * (H2STG * 4);
        int koff = s * 32;
        #pragma unroll
        for (int j = 0; j < 2; j++) cp16(adst[j] + so, asrc[j] + koff, 16);
        #pragma unroll
        for (int j = 0; j < 4; j++) cp16(bdst[j] + so, bsrc[j] + koff, 16);
        CP_COMMIT();
    }

    int slot = 0;
    for (int i = 0; i < nk; i++) {
        if (i + 2 < nk) {
            int s2 = (i + 2) % 3;
            uint32_t so = (uint32_t)s2 * (H2STG * 4);
            int koff = (i + 2) * 32;
            #pragma unroll
            for (int j = 0; j < 2; j++) cp16(adst[j] + so, asrc[j] + koff, 16);
            #pragma unroll
            for (int j = 0; j < 4; j++) cp16(bdst[j] + so, bsrc[j] + koff, 16);
        }
        CP_COMMIT();
        CP_WAIT2();
        __syncthreads();
        const uint32_t* sa = smem + (size_t)slot * H2STG;
        const uint32_t* sb = sa + 2048;
        #pragma unroll
        for (int kb = 0; kb < 2; kb++) {
            uint32_t af[4][4], bf[8][2];
            #pragma unroll
            for (int mt = 0; mt < 4; mt++) {
                const uint32_t* p = sa + (size_t)((kb * 8 + wm * 4 + mt) * 4) * 32 + lane;
                af[mt][0] = p[0]; af[mt][1] = p[32]; af[mt][2] = p[64]; af[mt][3] = p[96];
            }
            #pragma unroll
            for (int nt = 0; nt < 8; nt++) {
                const uint32_t* p = sb + (size_t)((kb * 32 + wn * 8 + nt) * 2) * 32 + lane;
                bf[nt][0] = p[0]; bf[nt][1] = p[32];
            }
            #pragma unroll
            for (int mt = 0; mt < 4; mt++)
                #pragma unroll
                for (int nt = 0; nt < 8; nt++)
                    mma16(acc[mt][nt], af[mt], bf[nt]);
        }
        __syncthreads();
        slot = (slot + 1 == 3) ? 0 : slot + 1;
    }

    #pragma unroll
    for (int mt = 0; mt < 4; mt++) {
        const int r0 = m0 + wm * 64 + mt * 16 + (lane >> 2);
        #pragma unroll
        for (int nt = 0; nt < 8; nt++) {
            const int c0 = n0 + wn * 64 + nt * 8 + (lane & 3) * 2;
            float bx = 0.f, by = 0.f;
            if (BIAS) { float2 b2 = *(const float2*)(bias + c0); bx = b2.x; by = b2.y; }
            float x0 = acc[mt][nt][0] + bx, x1 = acc[mt][nt][1] + by;
            float y0 = acc[mt][nt][2] + bx, y1 = acc[mt][nt][3] + by;
            if (RES) {
                float2 ra = *(const float2*)(res + (size_t)r0 * ldc + c0);
                float2 rb = *(const float2*)(res + (size_t)(r0 + 8) * ldc + c0);
                x0 += ra.x; x1 += ra.y; y0 += rb.x; y1 += rb.y;
            }
            if (RELU) {
                x0 = fmaxf(x0, 0.f); x1 = fmaxf(x1, 0.f);
                y0 = fmaxf(y0, 0.f); y1 = fmaxf(y1, 0.f);
            }
            store2(C + (size_t)r0 * ldc + c0, x0, x1);
            store2(C + (size_t)(r0 + 8) * ldc + c0, y0, y1);
        }
    }
}

// ===================== fp16 TN GEMM for kvs (ldmatrix.trans) =====================
#define TNSTG 3072
#define TNSM (2*TNSTG*4)

__global__ __launch_bounds__(256)
void kvs_gemm(const __half* __restrict__ kp, const __half* __restrict__ v,
              float* __restrict__ kvs2)
{
    extern __shared__ uint32_t smem[];
    const int tid = threadIdx.x, lane = tid & 31, w = tid >> 5;
    const int wm = w >> 2, wn = w & 3;
    const uint32_t sbase = smem_u32(smem);
    const int bh = blockIdx.z, b = bh >> 4, h = bh & 15;
    const int m0 = blockIdx.x * 128;
    const __half* Ag = kp + (size_t)bh * SEQ * MP;
    const __half* Bg = v + (size_t)b * SEQ * DM + h * HD;

    const __half* asrc[2]; uint32_t adst[2]; int asz[2];
    #pragma unroll
    for (int j = 0; j < 2; j++) {
        int c = j * 256 + tid;
        int row = c >> 4, u = c & 15;
        adst[j] = sbase + row * 256 + ((u ^ (row & 7)) << 4);
        bool val = (m0 + u * 8) < MP;
        asrc[j] = Ag + (size_t)row * MP + (val ? (m0 + u * 8) : 0);
        asz[j] = val ? 16 : 0;
    }
    const int brow = tid >> 3, bu = tid & 7;
    const uint32_t bdst = sbase + 8192 + brow * 128 + ((bu ^ (brow & 7)) << 4);
    const __half* bsrc = Bg + (size_t)brow * DM + bu * 8;

    float acc[4][2][4];
    #pragma unroll
    for (int a = 0; a < 4; a++)
        #pragma unroll
        for (int bb = 0; bb < 2; bb++)
            #pragma unroll
            for (int c = 0; c < 4; c++) acc[a][bb][c] = 0.f;

    const int nk = SEQ / 32;
    #pragma unroll
    for (int j = 0; j < 2; j++) cp16(adst[j], asrc[j], asz[j]);
    cp16(bdst, bsrc, 16);
    CP_COMMIT();

    const int q = lane >> 3, r = lane & 7;
    for (int i = 0; i < nk; i++) {
        if (i + 1 < nk) {
            uint32_t so = (uint32_t)((i + 1) & 1) * (TNSTG * 4);
            size_t ko = (size_t)(i + 1) * 32;
            #pragma unroll
            for (int j = 0; j < 2; j++) cp16(adst[j] + so, asrc[j] + ko * MP, asz[j]);
            cp16(bdst + so, bsrc + ko * DM, 16);
        }
        CP_COMMIT();
        CP_WAIT1();
        __syncthreads();
        const uint32_t st = sbase + (uint32_t)(i & 1) * (TNSTG * 4);
        #pragma unroll
        for (int kb = 0; kb < 2; kb++) {
            uint32_t bf[4];
            {
                int krow = kb * 16 + (q & 1) * 8 + r;
                int du = wn * 2 + (q >> 1);
                ldsm4t(bf, st + 8192 + krow * 128 + ((du ^ (krow & 7)) << 4));
            }
            #pragma unroll
            for (int mt = 0; mt < 4; mt++) {
                uint32_t af[4];
                int krow = kb * 16 + (q >> 1) * 8 + r;
                int mu = wm * 8 + mt * 2 + (q & 1);
                ldsm4t(af, st + krow * 256 + ((mu ^ (krow & 7)) << 4));
                mma16(acc[mt][0], af, bf);
                mma16(acc[mt][1], af, bf + 2);
            }
        }
        __syncthreads();
    }

    float* outp = kvs2 + (size_t)bh * MP * HD;
    #pragma unroll
    for (int mt = 0; mt < 4; mt++) {
        const int r0 = m0 + wm * 64 + mt * 16 + (lane >> 2);
        #pragma unroll
        for (int nt = 0; nt < 2; nt++) {
            const int c0 = wn * 16 + nt * 8 + (lane & 3) * 2;
            if (r0 < MP)
                *(float2*)(outp + (size_t)r0 * HD + c0) = make_float2(acc[mt][nt][0], acc[mt][nt][1]);
            if (r0 + 8 < MP)
                *(float2*)(outp + (size_t)(r0 + 8) * HD + c0) = make_float2(acc[mt][nt][2], acc[mt][nt][3]);
        }
    }
}

// ----------------- fp32 -> fp16 convert -----------------
__global__ void cvt_kernel(const float* __restrict__ s, __half* __restrict__ d, int n4)
{
    int i = blockIdx.x * 256 + threadIdx.x;
    if (i >= n4) return;
    float4 v = ((const float4*)s)[i];
    __half2* o = (__half2*)d + (size_t)i * 2;
    o[0] = __floats2half2_rn(v.x, v.y);
    o[1] = __floats2half2_rn(v.z, v.w);
}

// ----------------- LayerNorm (fp32 in, fp16 out) -----------------
__global__ __launch_bounds__(256)
void ln_kernel(const float* __restrict__ x, const float* __restrict__ g,
               const float* __restrict__ beta, __half* __restrict__ y)
{
    size_t row = blockIdx.x;
    int tid = threadIdx.x;
    float4 v = ((const float4*)(x + row * DM))[tid];
    float s = v.x + v.y + v.z + v.w;
    __shared__ float sm[8];
    #pragma unroll
    for (int o = 16; o > 0; o >>= 1) s += __shfl_xor_sync(~0u, s, o);
    if ((tid & 31) == 0) sm[tid >> 5] = s;
    __syncthreads();
    float mu = 0.f;
    #pragma unroll
    for (int i = 0; i < 8; i++) mu += sm[i];
    mu *= (1.f / (float)DM);
    float dx = v.x - mu, dy = v.y - mu, dz = v.z - mu, dw = v.w - mu;
    float q = dx*dx + dy*dy + dz*dz + dw*dw;
    __syncthreads();
    #pragma unroll
    for (int o = 16; o > 0; o >>= 1) q += __shfl_xor_sync(~0u, q, o);
    if ((tid & 31) == 0) sm[tid >> 5] = q;
    __syncthreads();
    float var = 0.f;
    #pragma unroll
    for (int i = 0; i < 8; i++) var += sm[i];
    var *= (1.f / (float)DM);
    float inv = rsqrtf(var + 1e-5f);
    float4 gg = ((const float4*)g)[tid];
    float4 bb = ((const float4*)beta)[tid];
    __half2* o = (__half2*)(y + row * DM) + tid * 2;
    o[0] = __floats2half2_rn(dx * inv * gg.x + bb.x, dy * inv * gg.y + bb.y);
    o[1] = __floats2half2_rn(dz * inv * gg.z + bb.z, dw * inv * gg.w + bb.w);
}

// ----------------- kstab: stab[b,l] = max over (h, xt) of pmaxk -----------------
__global__ void kstab_kernel(const float* __restrict__ pmaxk, float* __restrict__ stab)
{
    int i = blockIdx.x * 256 + threadIdx.x;   // i = b*SEQ + l
    if (i >= BATCHN * SEQ) return;
    int b = i >> 11, l = i & (SEQ - 1);
    float mx = -1e30f;
    #pragma unroll
    for (int h = 0; h < NH; h++)
        #pragma unroll
        for (int x = 0; x < NXT; x++)
            mx = fmaxf(mx, pmaxk[((size_t)(b * NH + h) * NXT + x) * SEQ + l]);
    stab[i] = mx;
}

// ----------------- q exp: dd fp32 -> qph fp16 (stab from pmaxq) -----------------
__global__ __launch_bounds__(256)
void qexp_kernel(const float* __restrict__ dd, const __half* __restrict__ q,
                 const float* __restrict__ pmaxq, __half* __restrict__ qph)
{
    const int rr = blockIdx.x * 8 + (threadIdx.x >> 5);
    const int lane = threadIdx.x & 31;
    const int bh = rr >> 11, l = rr & (SEQ - 1);
    const int b = bh >> 4, h = bh & 15;
    float mx = -1e30f;
    #pragma unroll
    for (int x = 0; x < NXT; x++)
        mx = fmaxf(mx, pmaxq[((size_t)bh * NXT + x) * SEQ + l]);
    mx *= DN;
    const __half* qr = q + ((size_t)(b * SEQ + l)) * DM + h * HD;
    float a = __half2float(qr[lane]), bb2 = __half2float(qr[lane + 32]);
    float s = a * a + bb2 * bb2;
    #pragma unroll
    for (int o = 16; o > 0; o >>= 1) s += __shfl_xor_sync(~0u, s, o);
    const float dia = 0.5f * DN * DN * s;
    const float* row = dd + (size_t)rr * MP;
    __half* orow = qph + (size_t)rr * MP;
    #pragma unroll
    for (int j = 0; j < 18; j++) {
        int m = j * 32 + lane;
        if (m < MP)
            orow[m] = __float2half(
                (m < MFEAT) ? RATIO * (__expf(DN * row[m] - mx - dia) + FEPS) : 0.f);
    }
}

// ----------------- k exp: dd fp32 -> kph fp16 (stab from g_stab) -----------------
__global__ __launch_bounds__(256)
void kexp_kernel(const float* __restrict__ dd, const __half* __restrict__ k,
                 const float* __restrict__ stab, const unsigned char* __restrict__ padmask,
                 __half* __restrict__ kph)
{
    const int rr = blockIdx.x * 8 + (threadIdx.x >> 5);
    const int lane = threadIdx.x & 31;
    const int bh = rr >> 11, l = rr & (SEQ - 1);
    const int b = bh >> 4, h = bh & 15;
    const float mx = DN * stab[b * SEQ + l];
    const __half* kr = k + ((size_t)(b * SEQ + l)) * DM + h * HD;
    float a = __half2float(kr[lane]), bb2 = __half2float(kr[lane + 32]);
    float s = a * a + bb2 * bb2;
    #pragma unroll
    for (int o = 16; o > 0; o >>= 1) s += __shfl_xor_sync(~0u, s, o);
    const float dia = 0.5f * DN * DN * s;
    const float keep = padmask[b * SEQ + l] ? 0.f : 1.f;
    const float* row = dd + (size_t)rr * MP;
    __half* orow = kph + (size_t)rr * MP;
    #pragma unroll
    for (int j = 0; j < 18; j++) {
        int m = j * 32 + lane;
        if (m < MP)
            orow[m] = __float2half(
                (m < MFEAT) ? keep * RATIO * (__expf(DN * row[m] - mx - dia) + FEPS) : 0.f);
    }
}

// ----------------- assemble kvsT rows 0..63 from kvs2 (transpose) ------------
__global__ void assemble_kernel(const float* __restrict__ kvs2, __half* __restrict__ kvsT)
{
    int bh = blockIdx.y;
    int idx = blockIdx.x * 256 + threadIdx.x;
    if (idx >= HD * MP) return;
    int d = idx / MP, m = idx - d * MP;
    kvsT[(size_t)bh * KVR * MP + (size_t)d * MP + m] =
        __float2half(kvs2[(size_t)bh * MP * HD + (size_t)m * HD + d]);
}

// ks_sum (row 64 of kvsT) + zero rows 65..127
__global__ void kssum_kernel(const __half* __restrict__ kp, __half* __restrict__ kvsT)
{
    int bh = blockIdx.y;
    int m = blockIdx.x * 192 + threadIdx.x;
    if (m >= MP) return;
    const __half* p = kp + (size_t)bh * SEQ * MP + m;
    float a0 = 0.f, a1 = 0.f, a2 = 0.f, a3 = 0.f;
    for (int l = 0; l < SEQ; l += 4) {
        a0 += __half2float(p[(size_t)l * MP]);
        a1 += __half2float(p[(size_t)(l + 1) * MP]);
        a2 += __half2float(p[(size_t)(l + 2) * MP]);
        a3 += __half2float(p[(size_t)(l + 3) * MP]);
    }
    __half* o = kvsT + (size_t)bh * KVR * MP;
    o[(size_t)64 * MP + m] = __float2half((a0 + a1) + (a2 + a3));
    for (int r = 65; r < KVR; r++) o[(size_t)r * MP + m] = __float2half(0.f);
}

// attn = numer / (denom + 1e-6) -> fp16
__global__ void divide_kernel(const float* __restrict__ numer, __half* __restrict__ attn)
{
    size_t i = (size_t)blockIdx.x * 256 + threadIdx.x;
    if (i >= (size_t)NBH * SEQ * HD) return;
    int d = (int)(i & 63);
    int l = (int)((i >> 6) & (SEQ - 1));
    int bh = (int)(i >> 17);
    int b = bh >> 4, h = bh & 15;
    const float* row = numer + ((size_t)bh * SEQ + l) * KVR;
    float den = row[64] + 1e-6f;
    attn[((size_t)(b * SEQ + l)) * DM + h * HD + d] = __float2half(row[d] / den);
}

// ----------------- launch -----------------
static void* getsym(const void* shadow)
{
    void* p = nullptr;
    cudaGetSymbolAddress(&p, shadow);
    return p;
}

extern "C" void kernel_launch(void* const* d_in, const int* in_sizes, int n_in,
                              void* d_out, int out_size)
{
    const float* src    = (const float*)d_in[0];
    const unsigned char* mask = (const unsigned char*)d_in[1];
    const float* proj   = (const float*)d_in[2];
    const float* q_w    = (const float*)d_in[3];
    const float* q_b    = (const float*)d_in[4];
    const float* k_w    = (const float*)d_in[5];
    const float* k_b    = (const float*)d_in[6];
    const float* v_w    = (const float*)d_in[7];
    const float* v_b    = (const float*)d_in[8];
    const float* out_w  = (const float*)d_in[9];
    const float* out_b  = (const float*)d_in[10];
    const float* ln1_g  = (const float*)d_in[11];
    const float* ln1_b  = (const float*)d_in[12];
    const float* ln2_g  = (const float*)d_in[13];
    const float* ln2_b  = (const float*)d_in[14];
    const float* ff1_w  = (const float*)d_in[15];
    const float* ff1_b  = (const float*)d_in[16];
    const float* ff2_w  = (const float*)d_in[17];
    const float* ff2_b  = (const float*)d_in[18];
    float* out = (float*)d_out;

    __half* p_xn   = (__half*)getsym(g_xnh);
    __half* p_q    = (__half*)getsym(g_qh);
    __half* p_k    = (__half*)getsym(g_kh);
    __half* p_v    = (__half*)getsym(g_vh);
    float*  p_dd   = (float*)getsym(g_dd);
    __half* p_qp   = (__half*)getsym(g_qph);
    __half* p_kp   = (__half*)getsym(g_kph);
    float*  p_pmq  = (float*)getsym(g_pmaxq);
    float*  p_pmk  = (float*)getsym(g_pmaxk);
    float*  p_stab = (float*)getsym(g_stab);
    float*  p_kvs2 = (float*)getsym(g_kvs2);
    __half* p_kvsT = (__half*)getsym(g_kvsTh);
    float*  p_numer= (float*)getsym(g_numer);
    __half* p_attn = (__half*)getsym(g_attnh);
    float*  p_x1   = (float*)getsym(g_x1);
    __half* p_hn   = (__half*)getsym(g_hnh);
    __half* p_ff   = (__half*)getsym(g_ffh);
    __half* p_wq   = (__half*)getsym(g_wq);
    __half* p_wk   = (__half*)getsym(g_wk);
    __half* p_wv   = (__half*)getsym(g_wv);
    __half* p_wo   = (__half*)getsym(g_wo);
    __half* p_w1   = (__half*)getsym(g_w1);
    __half* p_w2   = (__half*)getsym(g_w2);
    __half* p_pj   = (__half*)getsym(g_pj);

    cudaFuncSetAttribute(hgemm<true,float>,
                         cudaFuncAttributeMaxDynamicSharedMemorySize, HSM);
    cudaFuncSetAttribute(hgemm<false,float>,
                         cudaFuncAttributeMaxDynamicSharedMemorySize, HSM);
    cudaFuncSetAttribute(hgemm2<false,false,true,__half>,
                         cudaFuncAttributeMaxDynamicSharedMemorySize, H2SM);
    cudaFuncSetAttribute(hgemm2<false,true,true,float>,
                         cudaFuncAttributeMaxDynamicSharedMemorySize, H2SM);
    cudaFuncSetAttribute(hgemm2<true,false,true,__half>,
                         cudaFuncAttributeMaxDynamicSharedMemorySize, H2SM);
    cudaFuncSetAttribute(kvs_gemm,
                         cudaFuncAttributeMaxDynamicSharedMemorySize, TNSM);

    // 0) weights -> fp16
    {
        int n4 = DM * DM / 4;
        cvt_kernel<<<(n4 + 255) / 256, 256>>>(q_w, p_wq, n4);
        cvt_kernel<<<(n4 + 255) / 256, 256>>>(k_w, p_wk, n4);
        cvt_kernel<<<(n4 + 255) / 256, 256>>>(v_w, p_wv, n4);
        cvt_kernel<<<(n4 + 255) / 256, 256>>>(out_w, p_wo, n4);
        int nf = DFF * DM / 4;
        cvt_kernel<<<(nf + 255) / 256, 256>>>(ff1_w, p_w1, nf);
        cvt_kernel<<<(nf + 255) / 256, 256>>>(ff2_w, p_w2, nf);
        int np = MFEAT * HD / 4;
        cvt_kernel<<<(np + 255) / 256, 256>>>(proj, p_pj, np);
    }

    // 1) LN1 -> fp16
    ln_kernel<<<NROWS, 256>>>(src, ln1_g, ln1_b, p_xn);

    // 2) QKV projections (v2 GEMM) -> fp16
    dim3 g2(DM / 256, NROWS / 128, 1);
    hgemm2<false,false,true,__half><<<g2, 256, H2SM>>>(
        p_xn, p_wq, q_b, nullptr, p_q, NROWS, DM, DM, DM, DM, DM);
    hgemm2<false,false,true,__half><<<g2, 256, H2SM>>>(
        p_xn, p_wk, k_b, nullptr, p_k, NROWS, DM, DM, DM, DM, DM);
    hgemm2<false,false,true,__half><<<g2, 256, H2SM>>>(
        p_xn, p_wv, v_b, nullptr, p_v, NROWS, DM, DM, DM, DM, DM);

    // 3) feature GEMMs (v1+STAB) -> dd fp32 + pmax; exp epilogues -> fp16
    dim3 gF(NXT, SEQ / 128, NBH);
    hgemm<true,float><<<gF, 256, HSM>>>(
        p_q, p_pj, p_dd, p_pmq, NXT, SEQ, MFEAT, HD, DM, HD, MP,
        (long long)SEQ * DM, HD, 0, 0, (long long)NH * SEQ * MP, (long long)SEQ * MP, NH);
    qexp_kernel<<<NBH * SEQ / 8, 256>>>(p_dd, p_q, p_pmq, p_qp);
    hgemm<true,float><<<gF, 256, HSM>>>(
        p_k, p_pj, p_dd, p_pmk, NXT, SEQ, MFEAT, HD, DM, HD, MP,
        (long long)SEQ * DM, HD, 0, 0, (long long)NH * SEQ * MP, (long long)SEQ * MP, NH);
    kstab_kernel<<<(BATCHN * SEQ + 255) / 256, 256>>>(p_pmk, p_stab);
    kexp_kernel<<<NBH * SEQ / 8, 256>>>(p_dd, p_k, p_stab, mask, p_kp);

    // 4) kvs via fp16 TN mma GEMM, then assemble + ks_sum
    kvs_gemm<<<dim3((MP + 127) / 128, 1, NBH), 256, TNSM>>>(p_kp, p_v, p_kvs2);
    assemble_kernel<<<dim3((HD * MP + 255) / 256, NBH), 256>>>(p_kvs2, p_kvsT);
    kssum_kernel<<<dim3(3, NBH), 192>>>(p_kp, p_kvsT);

    // 5) numer (+denom as col 64): batched v1 GEMM, N=128 dense
    hgemm<false,float><<<dim3(1, SEQ / 128, NBH), 256, HSM>>>(
        p_qp, p_kvsT, p_numer, nullptr, 1, SEQ, KVR, MP, MP, MP, KVR,
        (long long)SEQ * MP, 0, (long long)KVR * MP, 0, (long long)SEQ * KVR, 0, 1);

    // 6) divide + head interleave -> fp16
    divide_kernel<<<(NBH * SEQ * HD) / 256, 256>>>(p_numer, p_attn);

    // 7) out projection + residual(src) -> x1 fp32 (v2)
    hgemm2<false,true,true,float><<<g2, 256, H2SM>>>(
        p_attn, p_wo, out_b, src, p_x1, NROWS, DM, DM, DM, DM, DM);

    // 8) LN2 -> fp16
    ln_kernel<<<NROWS, 256>>>(p_x1, ln2_g, ln2_b, p_hn);

    // 9) FF1 (+ReLU) -> fp16 (v2)
    hgemm2<true,false,true,__half><<<dim3(DFF / 256, NROWS / 128, 1), 256, H2SM>>>(
        p_hn, p_w1, ff1_b, nullptr, p_ff, NROWS, DFF, DM, DM, DM, DFF);

    // 10) FF2 + residual(x1) -> final fp32 output (v2)
    hgemm2<false,true,true,float><<<g2, 256, H2SM>>>(
        p_ff, p_w2, ff2_b, p_x1, out, NROWS, DM, DFF, DFF, DFF, DM);
}

// round 8
// speedup vs baseline: 7.6431x; 1.0426x over previous
#include <cuda_runtime.h>
#include <cuda_fp16.h>
#include <cstdint>

#define BATCHN 4
#define SEQ 2048
#define DM 1024
#define QL 3072            // merged QKV row stride
#define NH 16
#define HD 64
#define DFF 4096
#define MFEAT 532
#define MP 576             // padded feature dim
#define NROWS (BATCHN*SEQ) // 8192
#define NBH (BATCHN*NH)    // 64
#define KVR 128            // kvs^T rows: 64 dims + 1 sum + 63 pad
#define NXT 5              // feature GEMM x-tiles

#define DN 0.35355339059327373f          /* 64^-0.25 */
#define RATIO 0.0433555f                 /* 1/sqrt(532) */
#define FEPS 1e-6f

// ----------------- scratch (device globals; no allocation) -----------------
__device__ __half g_xnh [(size_t)NROWS*DM];
__device__ __half g_qkvh[(size_t)NROWS*QL];
__device__ float  g_dd  [(size_t)NBH*SEQ*MP];
__device__ __half g_qph [(size_t)NBH*SEQ*MP];
__device__ __half g_kph [(size_t)NBH*SEQ*MP];
__device__ float  g_pmaxq[(size_t)NBH*NXT*SEQ];
__device__ float  g_pmaxk[(size_t)NBH*NXT*SEQ];
__device__ float  g_stab[(size_t)BATCHN*SEQ];
__device__ float  g_kvs2[(size_t)NBH*MP*HD];
__device__ __half g_kvsTh[(size_t)NBH*KVR*MP];
__device__ __half g_attnh[(size_t)NROWS*DM];
__device__ float  g_x1 [(size_t)NROWS*DM];
__device__ __half g_hnh [(size_t)NROWS*DM];
__device__ __half g_ffh [(size_t)NROWS*DFF];
// fp16 weight copies
__device__ __half g_wqkv[(size_t)3*DM*DM];
__device__ float  g_bqkv[QL];
__device__ __half g_wo[(size_t)DM*DM];
__device__ __half g_w1[(size_t)DFF*DM];
__device__ __half g_w2[(size_t)DM*DFF];
__device__ __half g_pj[(size_t)MFEAT*HD];

// ===================== helpers =====================
static __device__ __forceinline__ uint32_t smem_u32(const void* p) {
    uint32_t a;
    asm("{ .reg .u64 t; cvta.to.shared.u64 t, %1; cvt.u32.u64 %0, t; }"
        : "=r"(a) : "l"(p));
    return a;
}
static __device__ __forceinline__ void cp16(uint32_t dst, const void* src, int sz) {
    asm volatile("cp.async.cg.shared.global [%0], [%1], 16, %2;"
                 :: "r"(dst), "l"(src), "r"(sz));
}
#define CP_COMMIT() asm volatile("cp.async.commit_group;" ::: "memory")
#define CP_WAIT1()  asm volatile("cp.async.wait_group 1;" ::: "memory")

static __device__ __forceinline__ void mma16(float* c, const uint32_t* a, const uint32_t* b) {
    asm volatile(
        "mma.sync.aligned.m16n8k16.row.col.f32.f16.f16.f32 "
        "{%0,%1,%2,%3}, {%4,%5,%6,%7}, {%8,%9}, {%0,%1,%2,%3};"
        : "+f"(c[0]), "+f"(c[1]), "+f"(c[2]), "+f"(c[3])
        : "r"(a[0]), "r"(a[1]), "r"(a[2]), "r"(a[3]), "r"(b[0]), "r"(b[1]));
}
static __device__ __forceinline__ void ldsm4t(uint32_t* r, uint32_t addr) {
    asm volatile("ldmatrix.sync.aligned.m8n8.x4.trans.shared.b16 {%0,%1,%2,%3}, [%4];"
        : "=r"(r[0]), "=r"(r[1]), "=r"(r[2]), "=r"(r[3]) : "r"(addr));
}
static __device__ __forceinline__ void store2(__half* p, float x, float y) {
    *(__half2*)p = __floats2half2_rn(x, y);
}
static __device__ __forceinline__ void store2(float* p, float x, float y) {
    *(float2*)p = make_float2(x, y);
}
static __device__ __forceinline__ unsigned encf(float f) {
    unsigned u = __float_as_uint(f);
    return (u & 0x80000000u) ? ~u : (u | 0x80000000u);
}
static __device__ __forceinline__ float decf(unsigned u) {
    u = (u & 0x80000000u) ? (u ^ 0x80000000u) : ~u;
    return __uint_as_float(u);
}

// ===================== v1: fp16 mma NT GEMM, 128x128 tile, 3-stage ==========
// MODE 0: plain store.  MODE 1: store + per-row CTA max -> pmax.
// MODE 2: attention divide: C is __half attn base; denom = col 64; write
//         cols 0..63 to attn[(zo*SEQ + row)*DM + zi*HD + col].
#define HSTG 4096
#define HSM  (3*HSTG*4)

template<int MODE, typename CT>
__global__ __launch_bounds__(256)
void hgemm(const __half* __restrict__ A, const __half* __restrict__ B,
           CT* __restrict__ C, float* __restrict__ pmax, int NX,
           int M, int N, int K, int lda, int ldb, int ldc,
           long long sAo, long long sAi, long long sBo, long long sBi,
           long long sCo, long long sCi, int zdiv)
{
    extern __shared__ uint32_t smem[];
    const int tid = threadIdx.x, lane = tid & 31, w = tid >> 5;
    const int wm = w & 1, wn = w >> 1;
    const uint32_t sbase = smem_u32(smem);

    const int z = blockIdx.z;
    const int zo = z / zdiv, zi = z - zo * zdiv;
    const __half* Ag = A + (size_t)zo * sAo + (size_t)zi * sAi;
    const __half* Bg = B + (size_t)zo * sBo + (size_t)zi * sBi;
    CT* Cg = C + (size_t)zo * sCo + (size_t)zi * sCi;
    const int m0 = blockIdx.y * 128, n0 = blockIdx.x * 128;

    const __half* asrc[2]; uint32_t adst[2];
    const __half* bsrc[2]; uint32_t bdst[2]; int bsz[2];
    #pragma unroll
    for (int j = 0; j < 2; j++) {
        int c = j * 256 + tid;
        int row = c >> 2, o = c & 3;
        {
            int reg = ((row >> 3) & 1) + ((o & 1) << 1);
            int idx = (((o >> 1) * 8 + (row >> 4)) * 4 + reg) * 32 + (row & 7) * 4;
            adst[j] = sbase + idx * 4;
            asrc[j] = Ag + (size_t)(m0 + row) * lda + o * 8;
        }
        {
            int reg = o & 1;
            int idx = 2048 + (((o >> 1) * 16 + (row >> 3)) * 2 + reg) * 32 + (row & 7) * 4;
            bdst[j] = sbase + idx * 4;
            int rr = (n0 + row) < N ? (n0 + row) : 0;
            bsrc[j] = Bg + (size_t)rr * ldb + o * 8;
            bsz[j] = (n0 + row) < N ? 16 : 0;
        }
    }

    float acc[4][4][4];
    #pragma unroll
    for (int a = 0; a < 4; a++)
        #pragma unroll
        for (int b = 0; b < 4; b++)
            #pragma unroll
            for (int c = 0; c < 4; c++) acc[a][b][c] = 0.f;

    const int nk = K >> 5;
    #pragma unroll
    for (int s = 0; s < 2; s++) {
        if (s < nk) {
            uint32_t so = (uint32_t)s * (HSTG * 4);
            int koff = s * 32;
            #pragma unroll
            for (int j = 0; j < 2; j++) {
                cp16(adst[j] + so, asrc[j] + koff, 16);
                cp16(bdst[j] + so, bsrc[j] + koff, bsz[j]);
            }
        }
        CP_COMMIT();
    }

    int slot = 0;
    for (int i = 0; i < nk; i++) {
        CP_WAIT1();
        __syncthreads();
        if (i + 2 < nk) {
            int s2 = (i + 2) % 3;
            uint32_t so = (uint32_t)s2 * (HSTG * 4);
            int koff = (i + 2) * 32;
            #pragma unroll
            for (int j = 0; j < 2; j++) {
                cp16(adst[j] + so, asrc[j] + koff, 16);
                cp16(bdst[j] + so, bsrc[j] + koff, bsz[j]);
            }
        }
        CP_COMMIT();
        const uint32_t* sa = smem + (size_t)slot * HSTG;
        const uint32_t* sb = sa + 2048;
        #pragma unroll
        for (int kb = 0; kb < 2; kb++) {
            uint32_t af[4][4], bf[4][2];
            #pragma unroll
            for (int mt = 0; mt < 4; mt++) {
                const uint32_t* p = sa + (size_t)((kb * 8 + wm * 4 + mt) * 4) * 32 + lane;
                af[mt][0] = p[0]; af[mt][1] = p[32]; af[mt][2] = p[64]; af[mt][3] = p[96];
            }
            #pragma unroll
            for (int nt = 0; nt < 4; nt++) {
                const uint32_t* p = sb + (size_t)((kb * 16 + wn * 4 + nt) * 2) * 32 + lane;
                bf[nt][0] = p[0]; bf[nt][1] = p[32];
            }
            #pragma unroll
            for (int mt = 0; mt < 4; mt++)
                #pragma unroll
                for (int nt = 0; nt < 4; nt++)
                    mma16(acc[mt][nt], af[mt], bf[nt]);
        }
        slot = (slot + 1 == 3) ? 0 : slot + 1;
    }

    if (MODE == 2) {
        // denom broadcast: col 64 lives in warps with wn==2, nt=0, (lane&3)==0
        __shared__ float den[128];
        if (wn == 2 && (lane & 3) == 0) {
            #pragma unroll
            for (int mt = 0; mt < 4; mt++) {
                int rl = wm * 64 + mt * 16 + (lane >> 2);
                den[rl] = acc[mt][0][0] + 1e-6f;
                den[rl + 8] = acc[mt][0][2] + 1e-6f;
            }
        }
        __syncthreads();
        if (wn < 2) {
            #pragma unroll
            for (int mt = 0; mt < 4; mt++) {
                int rl = wm * 64 + mt * 16 + (lane >> 2);
                float d0 = den[rl], d1 = den[rl + 8];
                #pragma unroll
                for (int nt = 0; nt < 4; nt++) {
                    int c0 = wn * 32 + nt * 8 + (lane & 3) * 2;
                    __half* p0 = (__half*)Cg + (size_t)(m0 + rl) * ldc + c0;
                    __half* p1 = (__half*)Cg + (size_t)(m0 + rl + 8) * ldc + c0;
                    store2(p0, acc[mt][nt][0] / d0, acc[mt][nt][1] / d0);
                    store2(p1, acc[mt][nt][2] / d1, acc[mt][nt][3] / d1);
                }
            }
        }
        return;
    }

    #pragma unroll
    for (int mt = 0; mt < 4; mt++) {
        const int r0 = m0 + wm * 64 + mt * 16 + (lane >> 2);
        #pragma unroll
        for (int nt = 0; nt < 4; nt++) {
            const int c0 = n0 + wn * 32 + nt * 8 + (lane & 3) * 2;
            if (c0 < N) {
                store2(Cg + (size_t)r0 * ldc + c0, acc[mt][nt][0], acc[mt][nt][1]);
                store2(Cg + (size_t)(r0 + 8) * ldc + c0, acc[mt][nt][2], acc[mt][nt][3]);
            }
        }
    }

    if (MODE == 1) {
        __shared__ unsigned smax[128];
        if (tid < 128) smax[tid] = 0u;
        __syncthreads();
        #pragma unroll
        for (int mt = 0; mt < 4; mt++) {
            float v0 = -1e30f, v1 = -1e30f;
            #pragma unroll
            for (int nt = 0; nt < 4; nt++) {
                int c0 = n0 + wn * 32 + nt * 8 + (lane & 3) * 2;
                if (c0 < N) {
                    v0 = fmaxf(v0, fmaxf(acc[mt][nt][0], acc[mt][nt][1]));
                    v1 = fmaxf(v1, fmaxf(acc[mt][nt][2], acc[mt][nt][3]));
                }
            }
            v0 = fmaxf(v0, __shfl_xor_sync(~0u, v0, 1));
            v0 = fmaxf(v0, __shfl_xor_sync(~0u, v0, 2));
            v1 = fmaxf(v1, __shfl_xor_sync(~0u, v1, 1));
            v1 = fmaxf(v1, __shfl_xor_sync(~0u, v1, 2));
            if ((lane & 3) == 0) {
                int rl = wm * 64 + mt * 16 + (lane >> 2);
                atomicMax(&smax[rl], encf(v0));
                atomicMax(&smax[rl + 8], encf(v1));
            }
        }
        __syncthreads();
        if (tid < 128)
            pmax[((size_t)z * NX + blockIdx.x) * M + m0 + tid] = decf(smax[tid]);
    }
}

// ===================== v2: 128x256 tile, 3-stage, single-sync ================
#define H2STG 6144
#define H2SM  (3*H2STG*4)        // 72KB

template<bool RELU, bool RES, bool BIAS, typename CT>
__global__ __launch_bounds__(256)
void hgemm2(const __half* __restrict__ A, const __half* __restrict__ B,
            const float* __restrict__ bias, const float* __restrict__ res,
            CT* __restrict__ C, int M, int N, int K, int lda, int ldb, int ldc)
{
    extern __shared__ uint32_t smem[];
    const int tid = threadIdx.x, lane = tid & 31, w = tid >> 5;
    const int wm = w & 1, wn = w >> 1;
    const uint32_t sbase = smem_u32(smem);
    const int m0 = blockIdx.y * 128, n0 = blockIdx.x * 256;

    const __half* asrc[2]; uint32_t adst[2];
    #pragma unroll
    for (int j = 0; j < 2; j++) {
        int c = j * 256 + tid;
        int row = c >> 2, o = c & 3;
        int reg = ((row >> 3) & 1) + ((o & 1) << 1);
        int idx = (((o >> 1) * 8 + (row >> 4)) * 4 + reg) * 32 + (row & 7) * 4;
        adst[j] = sbase + idx * 4;
        asrc[j] = A + (size_t)(m0 + row) * lda + o * 8;
    }
    const __half* bsrc[4]; uint32_t bdst[4];
    #pragma unroll
    for (int j = 0; j < 4; j++) {
        int c = j * 256 + tid;
        int row = c >> 2, o = c & 3;
        int reg = o & 1;
        int idx = 2048 + (((o >> 1) * 32 + (row >> 3)) * 2 + reg) * 32 + (row & 7) * 4;
        bdst[j] = sbase + idx * 4;
        bsrc[j] = B + (size_t)(n0 + row) * ldb + o * 8;
    }

    float acc[4][8][4];
    #pragma unroll
    for (int a = 0; a < 4; a++)
        #pragma unroll
        for (int b = 0; b < 8; b++)
            #pragma unroll
            for (int c = 0; c < 4; c++) acc[a][b][c] = 0.f;

    const int nk = K >> 5;
    #pragma unroll
    for (int s = 0; s < 2; s++) {
        uint32_t so = (uint32_t)s * (H2STG * 4);
        int koff = s * 32;
        #pragma unroll
        for (int j = 0; j < 2; j++) cp16(adst[j] + so, asrc[j] + koff, 16);
        #pragma unroll
        for (int j = 0; j < 4; j++) cp16(bdst[j] + so, bsrc[j] + koff, 16);
        CP_COMMIT();
    }

    int slot = 0;
    for (int i = 0; i < nk; i++) {
        CP_WAIT1();
        __syncthreads();
        if (i + 2 < nk) {
            int s2 = (i + 2) % 3;
            uint32_t so = (uint32_t)s2 * (H2STG * 4);
            int koff = (i + 2) * 32;
            #pragma unroll
            for (int j = 0; j < 2; j++) cp16(adst[j] + so, asrc[j] + koff, 16);
            #pragma unroll
            for (int j = 0; j < 4; j++) cp16(bdst[j] + so, bsrc[j] + koff, 16);
        }
        CP_COMMIT();
        const uint32_t* sa = smem + (size_t)slot * H2STG;
        const uint32_t* sb = sa + 2048;
        #pragma unroll
        for (int kb = 0; kb < 2; kb++) {
            uint32_t af[4][4], bf[8][2];
            #pragma unroll
            for (int mt = 0; mt < 4; mt++) {
                const uint32_t* p = sa + (size_t)((kb * 8 + wm * 4 + mt) * 4) * 32 + lane;
                af[mt][0] = p[0]; af[mt][1] = p[32]; af[mt][2] = p[64]; af[mt][3] = p[96];
            }
            #pragma unroll
            for (int nt = 0; nt < 8; nt++) {
                const uint32_t* p = sb + (size_t)((kb * 32 + wn * 8 + nt) * 2) * 32 + lane;
                bf[nt][0] = p[0]; bf[nt][1] = p[32];
            }
            #pragma unroll
            for (int mt = 0; mt < 4; mt++)
                #pragma unroll
                for (int nt = 0; nt < 8; nt++)
                    mma16(acc[mt][nt], af[mt], bf[nt]);
        }
        slot = (slot + 1 == 3) ? 0 : slot + 1;
    }

    #pragma unroll
    for (int mt = 0; mt < 4; mt++) {
        const int r0 = m0 + wm * 64 + mt * 16 + (lane >> 2);
        #pragma unroll
        for (int nt = 0; nt < 8; nt++) {
            const int c0 = n0 + wn * 64 + nt * 8 + (lane & 3) * 2;
            float bx = 0.f, by = 0.f;
            if (BIAS) { float2 b2 = *(const float2*)(bias + c0); bx = b2.x; by = b2.y; }
            float x0 = acc[mt][nt][0] + bx, x1 = acc[mt][nt][1] + by;
            float y0 = acc[mt][nt][2] + bx, y1 = acc[mt][nt][3] + by;
            if (RES) {
                float2 ra = *(const float2*)(res + (size_t)r0 * ldc + c0);
                float2 rb = *(const float2*)(res + (size_t)(r0 + 8) * ldc + c0);
                x0 += ra.x; x1 += ra.y; y0 += rb.x; y1 += rb.y;
            }
            if (RELU) {
                x0 = fmaxf(x0, 0.f); x1 = fmaxf(x1, 0.f);
                y0 = fmaxf(y0, 0.f); y1 = fmaxf(y1, 0.f);
            }
            store2(C + (size_t)r0 * ldc + c0, x0, x1);
            store2(C + (size_t)(r0 + 8) * ldc + c0, y0, y1);
        }
    }
}

// ===================== fp16 TN GEMM for kvs (ldmatrix.trans) =====================
#define TNSTG 3072
#define TNSM (2*TNSTG*4)

__global__ __launch_bounds__(256)
void kvs_gemm(const __half* __restrict__ kp, const __half* __restrict__ v,
              float* __restrict__ kvs2)
{
    extern __shared__ uint32_t smem[];
    const int tid = threadIdx.x, lane = tid & 31, w = tid >> 5;
    const int wm = w >> 2, wn = w & 3;
    const uint32_t sbase = smem_u32(smem);
    const int bh = blockIdx.z, b = bh >> 4, h = bh & 15;
    const int m0 = blockIdx.x * 128;
    const __half* Ag = kp + (size_t)bh * SEQ * MP;
    const __half* Bg = v + (size_t)b * SEQ * QL + h * HD;

    const __half* asrc[2]; uint32_t adst[2]; int asz[2];
    #pragma unroll
    for (int j = 0; j < 2; j++) {
        int c = j * 256 + tid;
        int row = c >> 4, u = c & 15;
        adst[j] = sbase + row * 256 + ((u ^ (row & 7)) << 4);
        bool val = (m0 + u * 8) < MP;
        asrc[j] = Ag + (size_t)row * MP + (val ? (m0 + u * 8) : 0);
        asz[j] = val ? 16 : 0;
    }
    const int brow = tid >> 3, bu = tid & 7;
    const uint32_t bdst = sbase + 8192 + brow * 128 + ((bu ^ (brow & 7)) << 4);
    const __half* bsrc = Bg + (size_t)brow * QL + bu * 8;

    float acc[4][2][4];
    #pragma unroll
    for (int a = 0; a < 4; a++)
        #pragma unroll
        for (int bb = 0; bb < 2; bb++)
            #pragma unroll
            for (int c = 0; c < 4; c++) acc[a][bb][c] = 0.f;

    const int nk = SEQ / 32;
    #pragma unroll
    for (int j = 0; j < 2; j++) cp16(adst[j], asrc[j], asz[j]);
    cp16(bdst, bsrc, 16);
    CP_COMMIT();

    const int q = lane >> 3, r = lane & 7;
    for (int i = 0; i < nk; i++) {
        if (i + 1 < nk) {
            uint32_t so = (uint32_t)((i + 1) & 1) * (TNSTG * 4);
            size_t ko = (size_t)(i + 1) * 32;
            #pragma unroll
            for (int j = 0; j < 2; j++) cp16(adst[j] + so, asrc[j] + ko * MP, asz[j]);
            cp16(bdst + so, bsrc + ko * QL, 16);
        }
        CP_COMMIT();
        CP_WAIT1();
        __syncthreads();
        const uint32_t st = sbase + (uint32_t)(i & 1) * (TNSTG * 4);
        #pragma unroll
        for (int kb = 0; kb < 2; kb++) {
            uint32_t bf[4];
            {
                int krow = kb * 16 + (q & 1) * 8 + r;
                int du = wn * 2 + (q >> 1);
                ldsm4t(bf, st + 8192 + krow * 128 + ((du ^ (krow & 7)) << 4));
            }
            #pragma unroll
            for (int mt = 0; mt < 4; mt++) {
                uint32_t af[4];
                int krow = kb * 16 + (q >> 1) * 8 + r;
                int mu = wm * 8 + mt * 2 + (q & 1);
                ldsm4t(af, st + krow * 256 + ((mu ^ (krow & 7)) << 4));
                mma16(acc[mt][0], af, bf);
                mma16(acc[mt][1], af, bf + 2);
            }
        }
        __syncthreads();
    }

    float* outp = kvs2 + (size_t)bh * MP * HD;
    #pragma unroll
    for (int mt = 0; mt < 4; mt++) {
        const int r0 = m0 + wm * 64 + mt * 16 + (lane >> 2);
        #pragma unroll
        for (int nt = 0; nt < 2; nt++) {
            const int c0 = wn * 16 + nt * 8 + (lane & 3) * 2;
            if (r0 < MP)
                *(float2*)(outp + (size_t)r0 * HD + c0) = make_float2(acc[mt][nt][0], acc[mt][nt][1]);
            if (r0 + 8 < MP)
                *(float2*)(outp + (size_t)(r0 + 8) * HD + c0) = make_float2(acc[mt][nt][2], acc[mt][nt][3]);
        }
    }
}

// ----------------- fp32 -> fp16 convert -----------------
__global__ void cvt_kernel(const float* __restrict__ s, __half* __restrict__ d, int n4)
{
    int i = blockIdx.x * 256 + threadIdx.x;
    if (i >= n4) return;
    float4 v = ((const float4*)s)[i];
    __half2* o = (__half2*)d + (size_t)i * 2;
    o[0] = __floats2half2_rn(v.x, v.y);
    o[1] = __floats2half2_rn(v.z, v.w);
}

// ----------------- bias concat (fp32) -----------------
__global__ void biascat_kernel(const float* __restrict__ qb, const float* __restrict__ kb,
                               const float* __restrict__ vb, float* __restrict__ o)
{
    int i = blockIdx.x * 256 + threadIdx.x;
    if (i >= QL) return;
    int seg = i >> 10, off = i & 1023;
    o[i] = (seg == 0) ? qb[off] : (seg == 1) ? kb[off] : vb[off];
}

// ----------------- LayerNorm (fp32 in, fp16 out) -----------------
__global__ __launch_bounds__(256)
void ln_kernel(const float* __restrict__ x, const float* __restrict__ g,
               const float* __restrict__ beta, __half* __restrict__ y)
{
    size_t row = blockIdx.x;
    int tid = threadIdx.x;
    float4 v = ((const float4*)(x + row * DM))[tid];
    float s = v.x + v.y + v.z + v.w;
    __shared__ float sm[8];
    #pragma unroll
    for (int o = 16; o > 0; o >>= 1) s += __shfl_xor_sync(~0u, s, o);
    if ((tid & 31) == 0) sm[tid >> 5] = s;
    __syncthreads();
    float mu = 0.f;
    #pragma unroll
    for (int i = 0; i < 8; i++) mu += sm[i];
    mu *= (1.f / (float)DM);
    float dx = v.x - mu, dy = v.y - mu, dz = v.z - mu, dw = v.w - mu;
    float q = dx*dx + dy*dy + dz*dz + dw*dw;
    __syncthreads();
    #pragma unroll
    for (int o = 16; o > 0; o >>= 1) q += __shfl_xor_sync(~0u, q, o);
    if ((tid & 31) == 0) sm[tid >> 5] = q;
    __syncthreads();
    float var = 0.f;
    #pragma unroll
    for (int i = 0; i < 8; i++) var += sm[i];
    var *= (1.f / (float)DM);
    float inv = rsqrtf(var + 1e-5f);
    float4 gg = ((const float4*)g)[tid];
    float4 bb = ((const float4*)beta)[tid];
    __half2* o = (__half2*)(y + row * DM) + tid * 2;
    o[0] = __floats2half2_rn(dx * inv * gg.x + bb.x, dy * inv * gg.y + bb.y);
    o[1] = __floats2half2_rn(dz * inv * gg.z + bb.z, dw * inv * gg.w + bb.w);
}

// ----------------- kstab -----------------
__global__ void kstab_kernel(const float* __restrict__ pmaxk, float* __restrict__ stab)
{
    int i = blockIdx.x * 256 + threadIdx.x;
    if (i >= BATCHN * SEQ) return;
    int b = i >> 11, l = i & (SEQ - 1);
    float mx = -1e30f;
    #pragma unroll
    for (int h = 0; h < NH; h++)
        #pragma unroll
        for (int x = 0; x < NXT; x++)
            mx = fmaxf(mx, pmaxk[((size_t)(b * NH + h) * NXT + x) * SEQ + l]);
    stab[i] = mx;
}

// ----------------- q exp -----------------
__global__ __launch_bounds__(256)
void qexp_kernel(const float* __restrict__ dd, const __half* __restrict__ qkv,
                 const float* __restrict__ pmaxq, __half* __restrict__ qph)
{
    const int rr = blockIdx.x * 8 + (threadIdx.x >> 5);
    const int lane = threadIdx.x & 31;
    const int bh = rr >> 11, l = rr & (SEQ - 1);
    const int b = bh >> 4, h = bh & 15;
    float mx = -1e30f;
    #pragma unroll
    for (int x = 0; x < NXT; x++)
        mx = fmaxf(mx, pmaxq[((size_t)bh * NXT + x) * SEQ + l]);
    mx *= DN;
    const __half* qr = qkv + ((size_t)(b * SEQ + l)) * QL + h * HD;
    float a = __half2float(qr[lane]), bb2 = __half2float(qr[lane + 32]);
    float s = a * a + bb2 * bb2;
    #pragma unroll
    for (int o = 16; o > 0; o >>= 1) s += __shfl_xor_sync(~0u, s, o);
    const float dia = 0.5f * DN * DN * s;
    const float* row = dd + (size_t)rr * MP;
    __half* orow = qph + (size_t)rr * MP;
    #pragma unroll
    for (int j = 0; j < 18; j++) {
        int m = j * 32 + lane;
        if (m < MP)
            orow[m] = __float2half(
                (m < MFEAT) ? RATIO * (__expf(DN * row[m] - mx - dia) + FEPS) : 0.f);
    }
}

// ----------------- k exp -----------------
__global__ __launch_bounds__(256)
void kexp_kernel(const float* __restrict__ dd, const __half* __restrict__ qkv,
                 const float* __restrict__ stab, const unsigned char* __restrict__ padmask,
                 __half* __restrict__ kph)
{
    const int rr = blockIdx.x * 8 + (threadIdx.x >> 5);
    const int lane = threadIdx.x & 31;
    const int bh = rr >> 11, l = rr & (SEQ - 1);
    const int b = bh >> 4, h = bh & 15;
    const float mx = DN * stab[b * SEQ + l];
    const __half* kr = qkv + ((size_t)(b * SEQ + l)) * QL + DM + h * HD;
    float a = __half2float(kr[lane]), bb2 = __half2float(kr[lane + 32]);
    float s = a * a + bb2 * bb2;
    #pragma unroll
    for (int o = 16; o > 0; o >>= 1) s += __shfl_xor_sync(~0u, s, o);
    const float dia = 0.5f * DN * DN * s;
    const float keep = padmask[b * SEQ + l] ? 0.f : 1.f;
    const float* row = dd + (size_t)rr * MP;
    __half* orow = kph + (size_t)rr * MP;
    #pragma unroll
    for (int j = 0; j < 18; j++) {
        int m = j * 32 + lane;
        if (m < MP)
            orow[m] = __float2half(
                (m < MFEAT) ? keep * RATIO * (__expf(DN * row[m] - mx - dia) + FEPS) : 0.f);
    }
}

// ----------------- assemble kvsT rows 0..63 -----------------
__global__ void assemble_kernel(const float* __restrict__ kvs2, __half* __restrict__ kvsT)
{
    int bh = blockIdx.y;
    int idx = blockIdx.x * 256 + threadIdx.x;
    if (idx >= HD * MP) return;
    int d = idx / MP, m = idx - d * MP;
    kvsT[(size_t)bh * KVR * MP + (size_t)d * MP + m] =
        __float2half(kvs2[(size_t)bh * MP * HD + (size_t)m * HD + d]);
}

// ks_sum (row 64) + zero rows 65..127
__global__ void kssum_kernel(const __half* __restrict__ kp, __half* __restrict__ kvsT)
{
    int bh = blockIdx.y;
    int m = blockIdx.x * 192 + threadIdx.x;
    if (m >= MP) return;
    const __half* p = kp + (size_t)bh * SEQ * MP + m;
    float a0 = 0.f, a1 = 0.f, a2 = 0.f, a3 = 0.f;
    for (int l = 0; l < SEQ; l += 4) {
        a0 += __half2float(p[(size_t)l * MP]);
        a1 += __half2float(p[(size_t)(l + 1) * MP]);
        a2 += __half2float(p[(size_t)(l + 2) * MP]);
        a3 += __half2float(p[(size_t)(l + 3) * MP]);
    }
    __half* o = kvsT + (size_t)bh * KVR * MP;
    o[(size_t)64 * MP + m] = __float2half((a0 + a1) + (a2 + a3));
    for (int r = 65; r < KVR; r++) o[(size_t)r * MP + m] = __float2half(0.f);
}

// ----------------- launch -----------------
static void* getsym(const void* shadow)
{
    void* p = nullptr;
    cudaGetSymbolAddress(&p, shadow);
    return p;
}

extern "C" void kernel_launch(void* const* d_in, const int* in_sizes, int n_in,
                              void* d_out, int out_size)
{
    const float* src    = (const float*)d_in[0];
    const unsigned char* mask = (const unsigned char*)d_in[1];
    const float* proj   = (const float*)d_in[2];
    const float* q_w    = (const float*)d_in[3];
    const float* q_b    = (const float*)d_in[4];
    const float* k_w    = (const float*)d_in[5];
    const float* k_b    = (const float*)d_in[6];
    const float* v_w    = (const float*)d_in[7];
    const float* v_b    = (const float*)d_in[8];
    const float* out_w  = (const float*)d_in[9];
    const float* out_b  = (const float*)d_in[10];
    const float* ln1_g  = (const float*)d_in[11];
    const float* ln1_b  = (const float*)d_in[12];
    const float* ln2_g  = (const float*)d_in[13];
    const float* ln2_b  = (const float*)d_in[14];
    const float* ff1_w  = (const float*)d_in[15];
    const float* ff1_b  = (const float*)d_in[16];
    const float* ff2_w  = (const float*)d_in[17];
    const float* ff2_b  = (const float*)d_in[18];
    float* out = (float*)d_out;

    __half* p_xn   = (__half*)getsym(g_xnh);
    __half* p_qkv  = (__half*)getsym(g_qkvh);
    float*  p_dd   = (float*)getsym(g_dd);
    __half* p_qp   = (__half*)getsym(g_qph);
    __half* p_kp   = (__half*)getsym(g_kph);
    float*  p_pmq  = (float*)getsym(g_pmaxq);
    float*  p_pmk  = (float*)getsym(g_pmaxk);
    float*  p_stab = (float*)getsym(g_stab);
    float*  p_kvs2 = (float*)getsym(g_kvs2);
    __half* p_kvsT = (__half*)getsym(g_kvsTh);
    __half* p_attn = (__half*)getsym(g_attnh);
    float*  p_x1   = (float*)getsym(g_x1);
    __half* p_hn   = (__half*)getsym(g_hnh);
    __half* p_ff   = (__half*)getsym(g_ffh);
    __half* p_wqkv = (__half*)getsym(g_wqkv);
    float*  p_bqkv = (float*)getsym(g_bqkv);
    __half* p_wo   = (__half*)getsym(g_wo);
    __half* p_w1   = (__half*)getsym(g_w1);
    __half* p_w2   = (__half*)getsym(g_w2);
    __half* p_pj   = (__half*)getsym(g_pj);

    cudaFuncSetAttribute(hgemm<1,float>,
                         cudaFuncAttributeMaxDynamicSharedMemorySize, HSM);
    cudaFuncSetAttribute(hgemm<2,__half>,
                         cudaFuncAttributeMaxDynamicSharedMemorySize, HSM);
    cudaFuncSetAttribute(hgemm2<false,false,true,__half>,
                         cudaFuncAttributeMaxDynamicSharedMemorySize, H2SM);
    cudaFuncSetAttribute(hgemm2<false,true,true,float>,
                         cudaFuncAttributeMaxDynamicSharedMemorySize, H2SM);
    cudaFuncSetAttribute(hgemm2<true,false,true,__half>,
                         cudaFuncAttributeMaxDynamicSharedMemorySize, H2SM);
    cudaFuncSetAttribute(kvs_gemm,
                         cudaFuncAttributeMaxDynamicSharedMemorySize, TNSM);

    const int n4 = DM * DM / 4;
    // launches 1-5 (so ncu -s 5 captures the QKV GEMM)
    cvt_kernel<<<(n4 + 255) / 256, 256>>>(q_w, p_wqkv, n4);
    cvt_kernel<<<(n4 + 255) / 256, 256>>>(k_w, p_wqkv + (size_t)DM * DM, n4);
    cvt_kernel<<<(n4 + 255) / 256, 256>>>(v_w, p_wqkv + (size_t)2 * DM * DM, n4);
    biascat_kernel<<<(QL + 255) / 256, 256>>>(q_b, k_b, v_b, p_bqkv);
    ln_kernel<<<NROWS, 256>>>(src, ln1_g, ln1_b, p_xn);

    // launch 6: merged QKV GEMM (N=3072)
    hgemm2<false,false,true,__half><<<dim3(QL / 256, NROWS / 128, 1), 256, H2SM>>>(
        p_xn, p_wqkv, p_bqkv, nullptr, p_qkv, NROWS, QL, DM, DM, DM, QL);

    // remaining weight converts
    cvt_kernel<<<(n4 + 255) / 256, 256>>>(out_w, p_wo, n4);
    {
        int nf = DFF * DM / 4;
        cvt_kernel<<<(nf + 255) / 256, 256>>>(ff1_w, p_w1, nf);
        cvt_kernel<<<(nf + 255) / 256, 256>>>(ff2_w, p_w2, nf);
        int np = MFEAT * HD / 4;
        cvt_kernel<<<(np + 255) / 256, 256>>>(proj, p_pj, np);
    }

    // feature GEMMs (MODE 1) + exp epilogues
    dim3 gF(NXT, SEQ / 128, NBH);
    hgemm<1,float><<<gF, 256, HSM>>>(
        p_qkv, p_pj, p_dd, p_pmq, NXT, SEQ, MFEAT, HD, QL, HD, MP,
        (long long)SEQ * QL, HD, 0, 0, (long long)NH * SEQ * MP, (long long)SEQ * MP, NH);
    qexp_kernel<<<NBH * SEQ / 8, 256>>>(p_dd, p_qkv, p_pmq, p_qp);
    hgemm<1,float><<<gF, 256, HSM>>>(
        p_qkv + DM, p_pj, p_dd, p_pmk, NXT, SEQ, MFEAT, HD, QL, HD, MP,
        (long long)SEQ * QL, HD, 0, 0, (long long)NH * SEQ * MP, (long long)SEQ * MP, NH);
    kstab_kernel<<<(BATCHN * SEQ + 255) / 256, 256>>>(p_pmk, p_stab);
    kexp_kernel<<<NBH * SEQ / 8, 256>>>(p_dd, p_qkv, p_stab, mask, p_kp);

    // kvs + assemble + ks_sum
    kvs_gemm<<<dim3((MP + 127) / 128, 1, NBH), 256, TNSM>>>(p_kp, p_qkv + 2 * DM, p_kvs2);
    assemble_kernel<<<dim3((HD * MP + 255) / 256, NBH), 256>>>(p_kvs2, p_kvsT);
    kssum_kernel<<<dim3(3, NBH), 192>>>(p_kp, p_kvsT);

    // numer GEMM with fused divide -> attn fp16 [b,l,h,d]
    // zdiv=NH => zo=b, zi=h; per-b and per-h strides for A (qp) and B (kvsT)
    hgemm<2,__half><<<dim3(1, SEQ / 128, NBH), 256, HSM>>>(
        p_qp, p_kvsT, p_attn, nullptr, 1, SEQ, KVR, MP, MP, MP, DM,
        (long long)NH * SEQ * MP, (long long)SEQ * MP,
        (long long)NH * KVR * MP, (long long)KVR * MP,
        (long long)SEQ * DM, HD, NH);

    // out projection + residual(src) -> x1 fp32
    dim3 gO(DM / 256, NROWS / 128, 1);
    hgemm2<false,true,true,float><<<gO, 256, H2SM>>>(
        p_attn, p_wo, out_b, src, p_x1, NROWS, DM, DM, DM, DM, DM);

    // LN2 -> fp16
    ln_kernel<<<NROWS, 256>>>(p_x1, ln2_g, ln2_b, p_hn);

    // FF1 (+ReLU) -> fp16
    hgemm2<true,false,true,__half><<<dim3(DFF / 256, NROWS / 128, 1), 256, H2SM>>>(
        p_hn, p_w1, ff1_b, nullptr, p_ff, NROWS, DFF, DM, DM, DM, DFF);

    // FF2 + residual(x1) -> final fp32 output
    hgemm2<false,true,true,float><<<gO, 256, H2SM>>>(
        p_ff, p_w2, ff2_b, p_x1, out, NROWS, DM, DFF, DFF, DFF, DM);
}

// round 9
// speedup vs baseline: 7.6443x; 1.0002x over previous
#include <cuda_runtime.h>
#include <cuda_fp16.h>
#include <cstdint>

#define BATCHN 4
#define SEQ 2048
#define DM 1024
#define QL 3072            // merged QKV row stride
#define NH 16
#define HD 64
#define DFF 4096
#define MFEAT 532
#define MP 576             // padded feature dim
#define NROWS (BATCHN*SEQ) // 8192
#define NBH (BATCHN*NH)    // 64
#define KVR 128            // kvs^T rows: 64 dims + 1 sum + 63 pad
#define NXT 5              // feature GEMM x-tiles

#define DN 0.35355339059327373f          /* 64^-0.25 */
#define RATIO 0.0433555f                 /* 1/sqrt(532) */
#define FEPS 1e-6f

// ----------------- scratch (device globals; no allocation) -----------------
__device__ __half g_xnh [(size_t)NROWS*DM];
__device__ __half g_qkvh[(size_t)NROWS*QL];
__device__ __half g_qph [(size_t)NBH*SEQ*MP];
__device__ __half g_kph [(size_t)NBH*SEQ*MP];
__device__ float  g_pmaxq[(size_t)NBH*NXT*SEQ];
__device__ float  g_pmaxk[(size_t)NBH*NXT*SEQ];
__device__ float  g_stab[(size_t)BATCHN*SEQ];
__device__ float  g_kvs2[(size_t)NBH*MP*HD];
__device__ __half g_kvsTh[(size_t)NBH*KVR*MP];
__device__ __half g_attnh[(size_t)NROWS*DM];
__device__ float  g_x1 [(size_t)NROWS*DM];
__device__ __half g_hnh [(size_t)NROWS*DM];
__device__ __half g_ffh [(size_t)NROWS*DFF];
// fp16 weight copies
__device__ __half g_wqkv[(size_t)3*DM*DM];
__device__ float  g_bqkv[QL];
__device__ __half g_wo[(size_t)DM*DM];
__device__ __half g_w1[(size_t)DFF*DM];
__device__ __half g_w2[(size_t)DM*DFF];
__device__ __half g_pj[(size_t)MFEAT*HD];

// ===================== helpers =====================
static __device__ __forceinline__ uint32_t smem_u32(const void* p) {
    uint32_t a;
    asm("{ .reg .u64 t; cvta.to.shared.u64 t, %1; cvt.u32.u64 %0, t; }"
        : "=r"(a) : "l"(p));
    return a;
}
static __device__ __forceinline__ void cp16(uint32_t dst, const void* src, int sz) {
    asm volatile("cp.async.cg.shared.global [%0], [%1], 16, %2;"
                 :: "r"(dst), "l"(src), "r"(sz));
}
#define CP_COMMIT() asm volatile("cp.async.commit_group;" ::: "memory")
#define CP_WAIT1()  asm volatile("cp.async.wait_group 1;" ::: "memory")

static __device__ __forceinline__ void mma16(float* c, const uint32_t* a, const uint32_t* b) {
    asm volatile(
        "mma.sync.aligned.m16n8k16.row.col.f32.f16.f16.f32 "
        "{%0,%1,%2,%3}, {%4,%5,%6,%7}, {%8,%9}, {%0,%1,%2,%3};"
        : "+f"(c[0]), "+f"(c[1]), "+f"(c[2]), "+f"(c[3])
        : "r"(a[0]), "r"(a[1]), "r"(a[2]), "r"(a[3]), "r"(b[0]), "r"(b[1]));
}
static __device__ __forceinline__ void ldsm4t(uint32_t* r, uint32_t addr) {
    asm volatile("ldmatrix.sync.aligned.m8n8.x4.trans.shared.b16 {%0,%1,%2,%3}, [%4];"
        : "=r"(r[0]), "=r"(r[1]), "=r"(r[2]), "=r"(r[3]) : "r"(addr));
}
static __device__ __forceinline__ void store2(__half* p, float x, float y) {
    *(__half2*)p = __floats2half2_rn(x, y);
}
static __device__ __forceinline__ void store2(float* p, float x, float y) {
    *(float2*)p = make_float2(x, y);
}
static __device__ __forceinline__ unsigned encf(float f) {
    unsigned u = __float_as_uint(f);
    return (u & 0x80000000u) ? ~u : (u | 0x80000000u);
}
static __device__ __forceinline__ float decf(unsigned u) {
    u = (u & 0x80000000u) ? (u ^ 0x80000000u) : ~u;
    return __uint_as_float(u);
}

// ===================== v1: fp16 mma NT GEMM, 128x128 tile, 3-stage ==========
// MODE 0: plain store.  MODE 1: store + per-row CTA max -> pmax.
// MODE 2: attention divide: C is __half attn base; denom = col 64; write
//         cols 0..63 to attn[(zo*SEQ + row)*DM + zi*HD + col].
#define HSTG 4096
#define HSM  (3*HSTG*4)

template<int MODE, typename CT>
__global__ __launch_bounds__(256)
void hgemm(const __half* __restrict__ A, const __half* __restrict__ B,
           CT* __restrict__ C, float* __restrict__ pmax, int NX,
           int M, int N, int K, int lda, int ldb, int ldc,
           long long sAo, long long sAi, long long sBo, long long sBi,
           long long sCo, long long sCi, int zdiv)
{
    extern __shared__ uint32_t smem[];
    const int tid = threadIdx.x, lane = tid & 31, w = tid >> 5;
    const int wm = w & 1, wn = w >> 1;
    const uint32_t sbase = smem_u32(smem);

    const int z = blockIdx.z;
    const int zo = z / zdiv, zi = z - zo * zdiv;
    const __half* Ag = A + (size_t)zo * sAo + (size_t)zi * sAi;
    const __half* Bg = B + (size_t)zo * sBo + (size_t)zi * sBi;
    CT* Cg = C + (size_t)zo * sCo + (size_t)zi * sCi;
    const int m0 = blockIdx.y * 128, n0 = blockIdx.x * 128;

    const __half* asrc[2]; uint32_t adst[2];
    const __half* bsrc[2]; uint32_t bdst[2]; int bsz[2];
    #pragma unroll
    for (int j = 0; j < 2; j++) {
        int c = j * 256 + tid;
        int row = c >> 2, o = c & 3;
        {
            int reg = ((row >> 3) & 1) + ((o & 1) << 1);
            int idx = (((o >> 1) * 8 + (row >> 4)) * 4 + reg) * 32 + (row & 7) * 4;
            adst[j] = sbase + idx * 4;
            asrc[j] = Ag + (size_t)(m0 + row) * lda + o * 8;
        }
        {
            int reg = o & 1;
            int idx = 2048 + (((o >> 1) * 16 + (row >> 3)) * 2 + reg) * 32 + (row & 7) * 4;
            bdst[j] = sbase + idx * 4;
            int rr = (n0 + row) < N ? (n0 + row) : 0;
            bsrc[j] = Bg + (size_t)rr * ldb + o * 8;
            bsz[j] = (n0 + row) < N ? 16 : 0;
        }
    }

    float acc[4][4][4];
    #pragma unroll
    for (int a = 0; a < 4; a++)
        #pragma unroll
        for (int b = 0; b < 4; b++)
            #pragma unroll
            for (int c = 0; c < 4; c++) acc[a][b][c] = 0.f;

    const int nk = K >> 5;
    #pragma unroll
    for (int s = 0; s < 2; s++) {
        if (s < nk) {
            uint32_t so = (uint32_t)s * (HSTG * 4);
            int koff = s * 32;
            #pragma unroll
            for (int j = 0; j < 2; j++) {
                cp16(adst[j] + so, asrc[j] + koff, 16);
                cp16(bdst[j] + so, bsrc[j] + koff, bsz[j]);
            }
        }
        CP_COMMIT();
    }

    int slot = 0;
    for (int i = 0; i < nk; i++) {
        CP_WAIT1();
        __syncthreads();
        if (i + 2 < nk) {
            int s2 = (i + 2) % 3;
            uint32_t so = (uint32_t)s2 * (HSTG * 4);
            int koff = (i + 2) * 32;
            #pragma unroll
            for (int j = 0; j < 2; j++) {
                cp16(adst[j] + so, asrc[j] + koff, 16);
                cp16(bdst[j] + so, bsrc[j] + koff, bsz[j]);
            }
        }
        CP_COMMIT();
        const uint32_t* sa = smem + (size_t)slot * HSTG;
        const uint32_t* sb = sa + 2048;
        #pragma unroll
        for (int kb = 0; kb < 2; kb++) {
            uint32_t af[4][4], bf[4][2];
            #pragma unroll
            for (int mt = 0; mt < 4; mt++) {
                const uint32_t* p = sa + (size_t)((kb * 8 + wm * 4 + mt) * 4) * 32 + lane;
                af[mt][0] = p[0]; af[mt][1] = p[32]; af[mt][2] = p[64]; af[mt][3] = p[96];
            }
            #pragma unroll
            for (int nt = 0; nt < 4; nt++) {
                const uint32_t* p = sb + (size_t)((kb * 16 + wn * 4 + nt) * 2) * 32 + lane;
                bf[nt][0] = p[0]; bf[nt][1] = p[32];
            }
            #pragma unroll
            for (int mt = 0; mt < 4; mt++)
                #pragma unroll
                for (int nt = 0; nt < 4; nt++)
                    mma16(acc[mt][nt], af[mt], bf[nt]);
        }
        slot = (slot + 1 == 3) ? 0 : slot + 1;
    }

    if (MODE == 2) {
        // denom broadcast: col 64 lives in warps with wn==2, nt=0, (lane&3)==0
        __shared__ float den[128];
        if (wn == 2 && (lane & 3) == 0) {
            #pragma unroll
            for (int mt = 0; mt < 4; mt++) {
                int rl = wm * 64 + mt * 16 + (lane >> 2);
                den[rl] = acc[mt][0][0] + 1e-6f;
                den[rl + 8] = acc[mt][0][2] + 1e-6f;
            }
        }
        __syncthreads();
        if (wn < 2) {
            #pragma unroll
            for (int mt = 0; mt < 4; mt++) {
                int rl = wm * 64 + mt * 16 + (lane >> 2);
                float d0 = den[rl], d1 = den[rl + 8];
                #pragma unroll
                for (int nt = 0; nt < 4; nt++) {
                    int c0 = wn * 32 + nt * 8 + (lane & 3) * 2;
                    __half* p0 = (__half*)Cg + (size_t)(m0 + rl) * ldc + c0;
                    __half* p1 = (__half*)Cg + (size_t)(m0 + rl + 8) * ldc + c0;
                    store2(p0, acc[mt][nt][0] / d0, acc[mt][nt][1] / d0);
                    store2(p1, acc[mt][nt][2] / d1, acc[mt][nt][3] / d1);
                }
            }
        }
        return;
    }

    #pragma unroll
    for (int mt = 0; mt < 4; mt++) {
        const int r0 = m0 + wm * 64 + mt * 16 + (lane >> 2);
        #pragma unroll
        for (int nt = 0; nt < 4; nt++) {
            const int c0 = n0 + wn * 32 + nt * 8 + (lane & 3) * 2;
            if (c0 < N) {
                store2(Cg + (size_t)r0 * ldc + c0, acc[mt][nt][0], acc[mt][nt][1]);
                store2(Cg + (size_t)(r0 + 8) * ldc + c0, acc[mt][nt][2], acc[mt][nt][3]);
            }
        }
    }

    if (MODE == 1) {
        __shared__ unsigned smax[128];
        if (tid < 128) smax[tid] = 0u;
        __syncthreads();
        #pragma unroll
        for (int mt = 0; mt < 4; mt++) {
            float v0 = -1e30f, v1 = -1e30f;
            #pragma unroll
            for (int nt = 0; nt < 4; nt++) {
                int c0 = n0 + wn * 32 + nt * 8 + (lane & 3) * 2;
                if (c0 < N) {
                    v0 = fmaxf(v0, fmaxf(acc[mt][nt][0], acc[mt][nt][1]));
                    v1 = fmaxf(v1, fmaxf(acc[mt][nt][2], acc[mt][nt][3]));
                }
            }
            v0 = fmaxf(v0, __shfl_xor_sync(~0u, v0, 1));
            v0 = fmaxf(v0, __shfl_xor_sync(~0u, v0, 2));
            v1 = fmaxf(v1, __shfl_xor_sync(~0u, v1, 1));
            v1 = fmaxf(v1, __shfl_xor_sync(~0u, v1, 2));
            if ((lane & 3) == 0) {
                int rl = wm * 64 + mt * 16 + (lane >> 2);
                atomicMax(&smax[rl], encf(v0));
                atomicMax(&smax[rl + 8], encf(v1));
            }
        }
        __syncthreads();
        if (tid < 128)
            pmax[((size_t)z * NX + blockIdx.x) * M + m0 + tid] = decf(smax[tid]);
    }
}

// ===================== v2: 128x256 tile, 3-stage, single-sync ================
#define H2STG 6144
#define H2SM  (3*H2STG*4)        // 72KB

template<bool RELU, bool RES, bool BIAS, typename CT>
__global__ __launch_bounds__(256)
void hgemm2(const __half* __restrict__ A, const __half* __restrict__ B,
            const float* __restrict__ bias, const float* __restrict__ res,
            CT* __restrict__ C, int M, int N, int K, int lda, int ldb, int ldc)
{
    extern __shared__ uint32_t smem[];
    const int tid = threadIdx.x, lane = tid & 31, w = tid >> 5;
    const int wm = w & 1, wn = w >> 1;
    const uint32_t sbase = smem_u32(smem);
    const int m0 = blockIdx.y * 128, n0 = blockIdx.x * 256;

    const __half* asrc[2]; uint32_t adst[2];
    #pragma unroll
    for (int j = 0; j < 2; j++) {
        int c = j * 256 + tid;
        int row = c >> 2, o = c & 3;
        int reg = ((row >> 3) & 1) + ((o & 1) << 1);
        int idx = (((o >> 1) * 8 + (row >> 4)) * 4 + reg) * 32 + (row & 7) * 4;
        adst[j] = sbase + idx * 4;
        asrc[j] = A + (size_t)(m0 + row) * lda + o * 8;
    }
    const __half* bsrc[4]; uint32_t bdst[4];
    #pragma unroll
    for (int j = 0; j < 4; j++) {
        int c = j * 256 + tid;
        int row = c >> 2, o = c & 3;
        int reg = o & 1;
        int idx = 2048 + (((o >> 1) * 32 + (row >> 3)) * 2 + reg) * 32 + (row & 7) * 4;
        bdst[j] = sbase + idx * 4;
        bsrc[j] = B + (size_t)(n0 + row) * ldb + o * 8;
    }

    float acc[4][8][4];
    #pragma unroll
    for (int a = 0; a < 4; a++)
        #pragma unroll
        for (int b = 0; b < 8; b++)
            #pragma unroll
            for (int c = 0; c < 4; c++) acc[a][b][c] = 0.f;

    const int nk = K >> 5;
    #pragma unroll
    for (int s = 0; s < 2; s++) {
        uint32_t so = (uint32_t)s * (H2STG * 4);
        int koff = s * 32;
        #pragma unroll
        for (int j = 0; j < 2; j++) cp16(adst[j] + so, asrc[j] + koff, 16);
        #pragma unroll
        for (int j = 0; j < 4; j++) cp16(bdst[j] + so, bsrc[j] + koff, 16);
        CP_COMMIT();
    }

    int slot = 0;
    for (int i = 0; i < nk; i++) {
        CP_WAIT1();
        __syncthreads();
        if (i + 2 < nk) {
            int s2 = (i + 2) % 3;
            uint32_t so = (uint32_t)s2 * (H2STG * 4);
            int koff = (i + 2) * 32;
            #pragma unroll
            for (int j = 0; j < 2; j++) cp16(adst[j] + so, asrc[j] + koff, 16);
            #pragma unroll
            for (int j = 0; j < 4; j++) cp16(bdst[j] + so, bsrc[j] + koff, 16);
        }
        CP_COMMIT();
        const uint32_t* sa = smem + (size_t)slot * H2STG;
        const uint32_t* sb = sa + 2048;
        #pragma unroll
        for (int kb = 0; kb < 2; kb++) {
            uint32_t af[4][4], bf[8][2];
            #pragma unroll
            for (int mt = 0; mt < 4; mt++) {
                const uint32_t* p = sa + (size_t)((kb * 8 + wm * 4 + mt) * 4) * 32 + lane;
                af[mt][0] = p[0]; af[mt][1] = p[32]; af[mt][2] = p[64]; af[mt][3] = p[96];
            }
            #pragma unroll
            for (int nt = 0; nt < 8; nt++) {
                const uint32_t* p = sb + (size_t)((kb * 32 + wn * 8 + nt) * 2) * 32 + lane;
                bf[nt][0] = p[0]; bf[nt][1] = p[32];
            }
            #pragma unroll
            for (int mt = 0; mt < 4; mt++)
                #pragma unroll
                for (int nt = 0; nt < 8; nt++)
                    mma16(acc[mt][nt], af[mt], bf[nt]);
        }
        slot = (slot + 1 == 3) ? 0 : slot + 1;
    }

    #pragma unroll
    for (int mt = 0; mt < 4; mt++) {
        const int r0 = m0 + wm * 64 + mt * 16 + (lane >> 2);
        #pragma unroll
        for (int nt = 0; nt < 8; nt++) {
            const int c0 = n0 + wn * 64 + nt * 8 + (lane & 3) * 2;
            float bx = 0.f, by = 0.f;
            if (BIAS) { float2 b2 = *(const float2*)(bias + c0); bx = b2.x; by = b2.y; }
            float x0 = acc[mt][nt][0] + bx, x1 = acc[mt][nt][1] + by;
            float y0 = acc[mt][nt][2] + bx, y1 = acc[mt][nt][3] + by;
            if (RES) {
                float2 ra = *(const float2*)(res + (size_t)r0 * ldc + c0);
                float2 rb = *(const float2*)(res + (size_t)(r0 + 8) * ldc + c0);
                x0 += ra.x; x1 += ra.y; y0 += rb.x; y1 += rb.y;
            }
            if (RELU) {
                x0 = fmaxf(x0, 0.f); x1 = fmaxf(x1, 0.f);
                y0 = fmaxf(y0, 0.f); y1 = fmaxf(y1, 0.f);
            }
            store2(C + (size_t)r0 * ldc + c0, x0, x1);
            store2(C + (size_t)(r0 + 8) * ldc + c0, y0, y1);
        }
    }
}

// ===================== fp16 TN GEMM for kvs (ldmatrix.trans) =====================
#define TNSTG 3072
#define TNSM (2*TNSTG*4)

__global__ __launch_bounds__(256)
void kvs_gemm(const __half* __restrict__ kp, const __half* __restrict__ v,
              float* __restrict__ kvs2)
{
    extern __shared__ uint32_t smem[];
    const int tid = threadIdx.x, lane = tid & 31, w = tid >> 5;
    const int wm = w >> 2, wn = w & 3;
    const uint32_t sbase = smem_u32(smem);
    const int bh = blockIdx.z, b = bh >> 4, h = bh & 15;
    const int m0 = blockIdx.x * 128;
    const __half* Ag = kp + (size_t)bh * SEQ * MP;
    const __half* Bg = v + (size_t)b * SEQ * QL + h * HD;

    const __half* asrc[2]; uint32_t adst[2]; int asz[2];
    #pragma unroll
    for (int j = 0; j < 2; j++) {
        int c = j * 256 + tid;
        int row = c >> 4, u = c & 15;
        adst[j] = sbase + row * 256 + ((u ^ (row & 7)) << 4);
        bool val = (m0 + u * 8) < MP;
        asrc[j] = Ag + (size_t)row * MP + (val ? (m0 + u * 8) : 0);
        asz[j] = val ? 16 : 0;
    }
    const int brow = tid >> 3, bu = tid & 7;
    const uint32_t bdst = sbase + 8192 + brow * 128 + ((bu ^ (brow & 7)) << 4);
    const __half* bsrc = Bg + (size_t)brow * QL + bu * 8;

    float acc[4][2][4];
    #pragma unroll
    for (int a = 0; a < 4; a++)
        #pragma unroll
        for (int bb = 0; bb < 2; bb++)
            #pragma unroll
            for (int c = 0; c < 4; c++) acc[a][bb][c] = 0.f;

    const int nk = SEQ / 32;
    #pragma unroll
    for (int j = 0; j < 2; j++) cp16(adst[j], asrc[j], asz[j]);
    cp16(bdst, bsrc, 16);
    CP_COMMIT();

    const int q = lane >> 3, r = lane & 7;
    for (int i = 0; i < nk; i++) {
        if (i + 1 < nk) {
            uint32_t so = (uint32_t)((i + 1) & 1) * (TNSTG * 4);
            size_t ko = (size_t)(i + 1) * 32;
            #pragma unroll
            for (int j = 0; j < 2; j++) cp16(adst[j] + so, asrc[j] + ko * MP, asz[j]);
            cp16(bdst + so, bsrc + ko * QL, 16);
        }
        CP_COMMIT();
        CP_WAIT1();
        __syncthreads();
        const uint32_t st = sbase + (uint32_t)(i & 1) * (TNSTG * 4);
        #pragma unroll
        for (int kb = 0; kb < 2; kb++) {
            uint32_t bf[4];
            {
                int krow = kb * 16 + (q & 1) * 8 + r;
                int du = wn * 2 + (q >> 1);
                ldsm4t(bf, st + 8192 + krow * 128 + ((du ^ (krow & 7)) << 4));
            }
            #pragma unroll
            for (int mt = 0; mt < 4; mt++) {
                uint32_t af[4];
                int krow = kb * 16 + (q >> 1) * 8 + r;
                int mu = wm * 8 + mt * 2 + (q & 1);
                ldsm4t(af, st + krow * 256 + ((mu ^ (krow & 7)) << 4));
                mma16(acc[mt][0], af, bf);
                mma16(acc[mt][1], af, bf + 2);
            }
        }
        __syncthreads();
    }

    float* outp = kvs2 + (size_t)bh * MP * HD;
    #pragma unroll
    for (int mt = 0; mt < 4; mt++) {
        const int r0 = m0 + wm * 64 + mt * 16 + (lane >> 2);
        #pragma unroll
        for (int nt = 0; nt < 2; nt++) {
            const int c0 = wn * 16 + nt * 8 + (lane & 3) * 2;
            if (r0 < MP)
                *(float2*)(outp + (size_t)r0 * HD + c0) = make_float2(acc[mt][nt][0], acc[mt][nt][1]);
            if (r0 + 8 < MP)
                *(float2*)(outp + (size_t)(r0 + 8) * HD + c0) = make_float2(acc[mt][nt][2], acc[mt][nt][3]);
        }
    }
}

// ----------------- fp32 -> fp16 convert -----------------
__global__ void cvt_kernel(const float* __restrict__ s, __half* __restrict__ d, int n4)
{
    int i = blockIdx.x * 256 + threadIdx.x;
    if (i >= n4) return;
    float4 v = ((const float4*)s)[i];
    __half2* o = (__half2*)d + (size_t)i * 2;
    o[0] = __floats2half2_rn(v.x, v.y);
    o[1] = __floats2half2_rn(v.z, v.w);
}

// ----------------- bias concat (fp32) -----------------
__global__ void biascat_kernel(const float* __restrict__ qb, const float* __restrict__ kb,
                               const float* __restrict__ vb, float* __restrict__ o)
{
    int i = blockIdx.x * 256 + threadIdx.x;
    if (i >= QL) return;
    int seg = i >> 10, off = i & 1023;
    o[i] = (seg == 0) ? qb[off] : (seg == 1) ? kb[off] : vb[off];
}

// ----------------- LayerNorm (fp32 in, fp16 out) -----------------
__global__ __launch_bounds__(256)
void ln_kernel(const float* __restrict__ x, const float* __restrict__ g,
               const float* __restrict__ beta, __half* __restrict__ y)
{
    size_t row = blockIdx.x;
    int tid = threadIdx.x;
    float4 v = ((const float4*)(x + row * DM))[tid];
    float s = v.x + v.y + v.z + v.w;
    __shared__ float sm[8];
    #pragma unroll
    for (int o = 16; o > 0; o >>= 1) s += __shfl_xor_sync(~0u, s, o);
    if ((tid & 31) == 0) sm[tid >> 5] = s;
    __syncthreads();
    float mu = 0.f;
    #pragma unroll
    for (int i = 0; i < 8; i++) mu += sm[i];
    mu *= (1.f / (float)DM);
    float dx = v.x - mu, dy = v.y - mu, dz = v.z - mu, dw = v.w - mu;
    float q = dx*dx + dy*dy + dz*dz + dw*dw;
    __syncthreads();
    #pragma unroll
    for (int o = 16; o > 0; o >>= 1) q += __shfl_xor_sync(~0u, q, o);
    if ((tid & 31) == 0) sm[tid >> 5] = q;
    __syncthreads();
    float var = 0.f;
    #pragma unroll
    for (int i = 0; i < 8; i++) var += sm[i];
    var *= (1.f / (float)DM);
    float inv = rsqrtf(var + 1e-5f);
    float4 gg = ((const float4*)g)[tid];
    float4 bb = ((const float4*)beta)[tid];
    __half2* o = (__half2*)(y + row * DM) + tid * 2;
    o[0] = __floats2half2_rn(dx * inv * gg.x + bb.x, dy * inv * gg.y + bb.y);
    o[1] = __floats2half2_rn(dz * inv * gg.z + bb.z, dw * inv * gg.w + bb.w);
}

// ----------------- kstab -----------------
__global__ void kstab_kernel(const float* __restrict__ pmaxk, float* __restrict__ stab)
{
    int i = blockIdx.x * 256 + threadIdx.x;
    if (i >= BATCHN * SEQ) return;
    int b = i >> 11, l = i & (SEQ - 1);
    float mx = -1e30f;
    #pragma unroll
    for (int h = 0; h < NH; h++)
        #pragma unroll
        for (int x = 0; x < NXT; x++)
            mx = fmaxf(mx, pmaxk[((size_t)(b * NH + h) * NXT + x) * SEQ + l]);
    stab[i] = mx;
}

// ----------------- q exp (in-place on fp16 qp) -----------------
__global__ __launch_bounds__(256)
void qexp_kernel(__half* __restrict__ qp, const __half* __restrict__ qkv,
                 const float* __restrict__ pmaxq)
{
    const int rr = blockIdx.x * 8 + (threadIdx.x >> 5);
    const int lane = threadIdx.x & 31;
    const int bh = rr >> 11, l = rr & (SEQ - 1);
    const int b = bh >> 4, h = bh & 15;
    float mx = -1e30f;
    #pragma unroll
    for (int x = 0; x < NXT; x++)
        mx = fmaxf(mx, pmaxq[((size_t)bh * NXT + x) * SEQ + l]);
    mx *= DN;
    const __half* qr = qkv + ((size_t)(b * SEQ + l)) * QL + h * HD;
    float a = __half2float(qr[lane]), bb2 = __half2float(qr[lane + 32]);
    float s = a * a + bb2 * bb2;
    #pragma unroll
    for (int o = 16; o > 0; o >>= 1) s += __shfl_xor_sync(~0u, s, o);
    const float dia = 0.5f * DN * DN * s;
    __half* row = qp + (size_t)rr * MP;
    #pragma unroll
    for (int j = 0; j < 18; j++) {
        int m = j * 32 + lane;
        if (m < MP) {
            float v = (m < MFEAT)
                ? RATIO * (__expf(DN * __half2float(row[m]) - mx - dia) + FEPS) : 0.f;
            row[m] = __float2half(v);
        }
    }
}

// ----------------- k exp (in-place on fp16 kp) -----------------
__global__ __launch_bounds__(256)
void kexp_kernel(__half* __restrict__ kp, const __half* __restrict__ qkv,
                 const float* __restrict__ stab, const unsigned char* __restrict__ padmask)
{
    const int rr = blockIdx.x * 8 + (threadIdx.x >> 5);
    const int lane = threadIdx.x & 31;
    const int bh = rr >> 11, l = rr & (SEQ - 1);
    const int b = bh >> 4, h = bh & 15;
    const float mx = DN * stab[b * SEQ + l];
    const __half* kr = qkv + ((size_t)(b * SEQ + l)) * QL + DM + h * HD;
    float a = __half2float(kr[lane]), bb2 = __half2float(kr[lane + 32]);
    float s = a * a + bb2 * bb2;
    #pragma unroll
    for (int o = 16; o > 0; o >>= 1) s += __shfl_xor_sync(~0u, s, o);
    const float dia = 0.5f * DN * DN * s;
    const float keep = padmask[b * SEQ + l] ? 0.f : 1.f;
    __half* row = kp + (size_t)rr * MP;
    #pragma unroll
    for (int j = 0; j < 18; j++) {
        int m = j * 32 + lane;
        if (m < MP) {
            float v = (m < MFEAT)
                ? keep * RATIO * (__expf(DN * __half2float(row[m]) - mx - dia) + FEPS) : 0.f;
            row[m] = __float2half(v);
        }
    }
}

// ----------------- assemble kvsT rows 0..63 -----------------
__global__ void assemble_kernel(const float* __restrict__ kvs2, __half* __restrict__ kvsT)
{
    int bh = blockIdx.y;
    int idx = blockIdx.x * 256 + threadIdx.x;
    if (idx >= HD * MP) return;
    int d = idx / MP, m = idx - d * MP;
    kvsT[(size_t)bh * KVR * MP + (size_t)d * MP + m] =
        __float2half(kvs2[(size_t)bh * MP * HD + (size_t)m * HD + d]);
}

// ks_sum (row 64) + zero rows 65..127
__global__ void kssum_kernel(const __half* __restrict__ kp, __half* __restrict__ kvsT)
{
    int bh = blockIdx.y;
    int m = blockIdx.x * 192 + threadIdx.x;
    if (m >= MP) return;
    const __half* p = kp + (size_t)bh * SEQ * MP + m;
    float a0 = 0.f, a1 = 0.f, a2 = 0.f, a3 = 0.f;
    for (int l = 0; l < SEQ; l += 4) {
        a0 += __half2float(p[(size_t)l * MP]);
        a1 += __half2float(p[(size_t)(l + 1) * MP]);
        a2 += __half2float(p[(size_t)(l + 2) * MP]);
        a3 += __half2float(p[(size_t)(l + 3) * MP]);
    }
    __half* o = kvsT + (size_t)bh * KVR * MP;
    o[(size_t)64 * MP + m] = __float2half((a0 + a1) + (a2 + a3));
    for (int r = 65; r < KVR; r++) o[(size_t)r * MP + m] = __float2half(0.f);
}

// ----------------- launch -----------------
static void* getsym(const void* shadow)
{
    void* p = nullptr;
    cudaGetSymbolAddress(&p, shadow);
    return p;
}

extern "C" void kernel_launch(void* const* d_in, const int* in_sizes, int n_in,
                              void* d_out, int out_size)
{
    const float* src    = (const float*)d_in[0];
    const unsigned char* mask = (const unsigned char*)d_in[1];
    const float* proj   = (const float*)d_in[2];
    const float* q_w    = (const float*)d_in[3];
    const float* q_b    = (const float*)d_in[4];
    const float* k_w    = (const float*)d_in[5];
    const float* k_b    = (const float*)d_in[6];
    const float* v_w    = (const float*)d_in[7];
    const float* v_b    = (const float*)d_in[8];
    const float* out_w  = (const float*)d_in[9];
    const float* out_b  = (const float*)d_in[10];
    const float* ln1_g  = (const float*)d_in[11];
    const float* ln1_b  = (const float*)d_in[12];
    const float* ln2_g  = (const float*)d_in[13];
    const float* ln2_b  = (const float*)d_in[14];
    const float* ff1_w  = (const float*)d_in[15];
    const float* ff1_b  = (const float*)d_in[16];
    const float* ff2_w  = (const float*)d_in[17];
    const float* ff2_b  = (const float*)d_in[18];
    float* out = (float*)d_out;

    __half* p_xn   = (__half*)getsym(g_xnh);
    __half* p_qkv  = (__half*)getsym(g_qkvh);
    __half* p_qp   = (__half*)getsym(g_qph);
    __half* p_kp   = (__half*)getsym(g_kph);
    float*  p_pmq  = (float*)getsym(g_pmaxq);
    float*  p_pmk  = (float*)getsym(g_pmaxk);
    float*  p_stab = (float*)getsym(g_stab);
    float*  p_kvs2 = (float*)getsym(g_kvs2);
    __half* p_kvsT = (__half*)getsym(g_kvsTh);
    __half* p_attn = (__half*)getsym(g_attnh);
    float*  p_x1   = (float*)getsym(g_x1);
    __half* p_hn   = (__half*)getsym(g_hnh);
    __half* p_ff   = (__half*)getsym(g_ffh);
    __half* p_wqkv = (__half*)getsym(g_wqkv);
    float*  p_bqkv = (float*)getsym(g_bqkv);
    __half* p_wo   = (__half*)getsym(g_wo);
    __half* p_w1   = (__half*)getsym(g_w1);
    __half* p_w2   = (__half*)getsym(g_w2);
    __half* p_pj   = (__half*)getsym(g_pj);

    cudaFuncSetAttribute(hgemm<1,__half>,
                         cudaFuncAttributeMaxDynamicSharedMemorySize, HSM);
    cudaFuncSetAttribute(hgemm<2,__half>,
                         cudaFuncAttributeMaxDynamicSharedMemorySize, HSM);
    cudaFuncSetAttribute(hgemm2<false,false,true,__half>,
                         cudaFuncAttributeMaxDynamicSharedMemorySize, H2SM);
    cudaFuncSetAttribute(hgemm2<false,true,true,float>,
                         cudaFuncAttributeMaxDynamicSharedMemorySize, H2SM);
    cudaFuncSetAttribute(hgemm2<true,false,true,__half>,
                         cudaFuncAttributeMaxDynamicSharedMemorySize, H2SM);
    cudaFuncSetAttribute(kvs_gemm,
                         cudaFuncAttributeMaxDynamicSharedMemorySize, TNSM);

    const int n4 = DM * DM / 4;
    cvt_kernel<<<(n4 + 255) / 256, 256>>>(q_w, p_wqkv, n4);
    cvt_kernel<<<(n4 + 255) / 256, 256>>>(k_w, p_wqkv + (size_t)DM * DM, n4);
    cvt_kernel<<<(n4 + 255) / 256, 256>>>(v_w, p_wqkv + (size_t)2 * DM * DM, n4);
    biascat_kernel<<<(QL + 255) / 256, 256>>>(q_b, k_b, v_b, p_bqkv);
    ln_kernel<<<NROWS, 256>>>(src, ln1_g, ln1_b, p_xn);

    // merged QKV GEMM (N=3072)
    hgemm2<false,false,true,__half><<<dim3(QL / 256, NROWS / 128, 1), 256, H2SM>>>(
        p_xn, p_wqkv, p_bqkv, nullptr, p_qkv, NROWS, QL, DM, DM, DM, QL);

    // remaining weight converts
    cvt_kernel<<<(n4 + 255) / 256, 256>>>(out_w, p_wo, n4);
    {
        int nf = DFF * DM / 4;
        cvt_kernel<<<(nf + 255) / 256, 256>>>(ff1_w, p_w1, nf);
        cvt_kernel<<<(nf + 255) / 256, 256>>>(ff2_w, p_w2, nf);
        int np = MFEAT * HD / 4;
        cvt_kernel<<<(np + 255) / 256, 256>>>(proj, p_pj, np);
    }

    // feature GEMMs (MODE 1, fp16 out into qp/kp) + in-place exp epilogues
    dim3 gF(NXT, SEQ / 128, NBH);
    hgemm<1,__half><<<gF, 256, HSM>>>(
        p_qkv, p_pj, p_qp, p_pmq, NXT, SEQ, MFEAT, HD, QL, HD, MP,
        (long long)SEQ * QL, HD, 0, 0, (long long)NH * SEQ * MP, (long long)SEQ * MP, NH);
    qexp_kernel<<<NBH * SEQ / 8, 256>>>(p_qp, p_qkv, p_pmq);
    hgemm<1,__half><<<gF, 256, HSM>>>(
        p_qkv + DM, p_pj, p_kp, p_pmk, NXT, SEQ, MFEAT, HD, QL, HD, MP,
        (long long)SEQ * QL, HD, 0, 0, (long long)NH * SEQ * MP, (long long)SEQ * MP, NH);
    kstab_kernel<<<(BATCHN * SEQ + 255) / 256, 256>>>(p_pmk, p_stab);
    kexp_kernel<<<NBH * SEQ / 8, 256>>>(p_kp, p_qkv, p_stab, mask);

    // kvs + assemble + ks_sum
    kvs_gemm<<<dim3((MP + 127) / 128, 1, NBH), 256, TNSM>>>(p_kp, p_qkv + 2 * DM, p_kvs2);
    assemble_kernel<<<dim3((HD * MP + 255) / 256, NBH), 256>>>(p_kvs2, p_kvsT);
    kssum_kernel<<<dim3(3, NBH), 192>>>(p_kp, p_kvsT);

    // numer GEMM with fused divide -> attn fp16 [b,l,h,d]
    hgemm<2,__half><<<dim3(1, SEQ / 128, NBH), 256, HSM>>>(
        p_qp, p_kvsT, p_attn, nullptr, 1, SEQ, KVR, MP, MP, MP, DM,
        (long long)NH * SEQ * MP, (long long)SEQ * MP,
        (long long)NH * KVR * MP, (long long)KVR * MP,
        (long long)SEQ * DM, HD, NH);

    // out projection + residual(src) -> x1 fp32
    dim3 gO(DM / 256, NROWS / 128, 1);
    hgemm2<false,true,true,float><<<gO, 256, H2SM>>>(
        p_attn, p_wo, out_b, src, p_x1, NROWS, DM, DM, DM, DM, DM);

    // LN2 -> fp16
    ln_kernel<<<NROWS, 256>>>(p_x1, ln2_g, ln2_b, p_hn);

    // FF1 (+ReLU) -> fp16
    hgemm2<true,false,true,__half><<<dim3(DFF / 256, NROWS / 128, 1), 256, H2SM>>>(
        p_hn, p_w1, ff1_b, nullptr, p_ff, NROWS, DFF, DM, DM, DM, DFF);

    // FF2 + residual(x1) -> final fp32 output
    hgemm2<false,true,true,float><<<gO, 256, H2SM>>>(
        p_ff, p_w2, ff2_b, p_x1, out, NROWS, DM, DFF, DFF, DFF, DM);
}

// round 10
// speedup vs baseline: 7.7353x; 1.0119x over previous
#include <cuda_runtime.h>
#include <cuda_fp16.h>
#include <cstdint>

#define BATCHN 4
#define SEQ 2048
#define DM 1024
#define QL 3072            // merged QKV row stride
#define NH 16
#define HD 64
#define DFF 4096
#define MFEAT 532
#define MP 576             // padded feature dim
#define NROWS (BATCHN*SEQ) // 8192
#define NBH (BATCHN*NH)    // 64
#define KVR 128            // kvs^T rows: 64 dims + 1 sum + 63 pad
#define NXT 5              // feature GEMM x-tiles

#define DN 0.35355339059327373f          /* 64^-0.25 */
#define RATIO 0.0433555f                 /* 1/sqrt(532) */
#define FEPS 1e-6f

// ----------------- scratch (device globals; no allocation) -----------------
__device__ __half g_xnh [(size_t)NROWS*DM];
__device__ __half g_qkvh[(size_t)NROWS*QL];
__device__ __half g_qph [(size_t)NBH*SEQ*MP];
__device__ __half g_kph [(size_t)NBH*SEQ*MP];
__device__ float  g_pmaxq[(size_t)NBH*NXT*SEQ];
__device__ float  g_pmaxk[(size_t)NBH*NXT*SEQ];
__device__ float  g_stab[(size_t)BATCHN*SEQ];
__device__ __half g_kvsTh[(size_t)NBH*KVR*MP];
__device__ __half g_attnh[(size_t)NROWS*DM];
__device__ float  g_x1 [(size_t)NROWS*DM];
__device__ __half g_hnh [(size_t)NROWS*DM];
__device__ __half g_ffh [(size_t)NROWS*DFF];
// fp16 weight copies
__device__ __half g_wqkv[(size_t)3*DM*DM];
__device__ float  g_bqkv[QL];
__device__ __half g_wo[(size_t)DM*DM];
__device__ __half g_w1[(size_t)DFF*DM];
__device__ __half g_w2[(size_t)DM*DFF];
__device__ __half g_pj[(size_t)MFEAT*HD];

// ===================== helpers =====================
static __device__ __forceinline__ uint32_t smem_u32(const void* p) {
    uint32_t a;
    asm("{ .reg .u64 t; cvta.to.shared.u64 t, %1; cvt.u32.u64 %0, t; }"
        : "=r"(a) : "l"(p));
    return a;
}
static __device__ __forceinline__ void cp16(uint32_t dst, const void* src, int sz) {
    asm volatile("cp.async.cg.shared.global [%0], [%1], 16, %2;"
                 :: "r"(dst), "l"(src), "r"(sz));
}
#define CP_COMMIT() asm volatile("cp.async.commit_group;" ::: "memory")
#define CP_WAIT1()  asm volatile("cp.async.wait_group 1;" ::: "memory")

static __device__ __forceinline__ void mma16(float* c, const uint32_t* a, const uint32_t* b) {
    asm volatile(
        "mma.sync.aligned.m16n8k16.row.col.f32.f16.f16.f32 "
        "{%0,%1,%2,%3}, {%4,%5,%6,%7}, {%8,%9}, {%0,%1,%2,%3};"
        : "+f"(c[0]), "+f"(c[1]), "+f"(c[2]), "+f"(c[3])
        : "r"(a[0]), "r"(a[1]), "r"(a[2]), "r"(a[3]), "r"(b[0]), "r"(b[1]));
}
static __device__ __forceinline__ void ldsm4t(uint32_t* r, uint32_t addr) {
    asm volatile("ldmatrix.sync.aligned.m8n8.x4.trans.shared.b16 {%0,%1,%2,%3}, [%4];"
        : "=r"(r[0]), "=r"(r[1]), "=r"(r[2]), "=r"(r[3]) : "r"(addr));
}
static __device__ __forceinline__ void store2(__half* p, float x, float y) {
    *(__half2*)p = __floats2half2_rn(x, y);
}
static __device__ __forceinline__ void store2(float* p, float x, float y) {
    *(float2*)p = make_float2(x, y);
}
static __device__ __forceinline__ unsigned encf(float f) {
    unsigned u = __float_as_uint(f);
    return (u & 0x80000000u) ? ~u : (u | 0x80000000u);
}
static __device__ __forceinline__ float decf(unsigned u) {
    u = (u & 0x80000000u) ? (u ^ 0x80000000u) : ~u;
    return __uint_as_float(u);
}

// ===================== v1: fp16 mma NT GEMM, 128x128 tile, 3-stage ==========
// MODE 0: plain store.  MODE 1: store + per-row CTA max -> pmax.
// MODE 2: attention divide (denom = col 64), write [b,l,h,d] fp16.
#define HSTG 4096
#define HSM  (3*HSTG*4)

template<int MODE, typename CT>
__global__ __launch_bounds__(256)
void hgemm(const __half* __restrict__ A, const __half* __restrict__ B,
           CT* __restrict__ C, float* __restrict__ pmax, int NX,
           int M, int N, int K, int lda, int ldb, int ldc,
           long long sAo, long long sAi, long long sBo, long long sBi,
           long long sCo, long long sCi, int zdiv)
{
    extern __shared__ uint32_t smem[];
    const int tid = threadIdx.x, lane = tid & 31, w = tid >> 5;
    const int wm = w & 1, wn = w >> 1;
    const uint32_t sbase = smem_u32(smem);

    const int z = blockIdx.z;
    const int zo = z / zdiv, zi = z - zo * zdiv;
    const __half* Ag = A + (size_t)zo * sAo + (size_t)zi * sAi;
    const __half* Bg = B + (size_t)zo * sBo + (size_t)zi * sBi;
    CT* Cg = C + (size_t)zo * sCo + (size_t)zi * sCi;
    const int m0 = blockIdx.y * 128, n0 = blockIdx.x * 128;

    const __half* asrc[2]; uint32_t adst[2];
    const __half* bsrc[2]; uint32_t bdst[2]; int bsz[2];
    #pragma unroll
    for (int j = 0; j < 2; j++) {
        int c = j * 256 + tid;
        int row = c >> 2, o = c & 3;
        {
            int reg = ((row >> 3) & 1) + ((o & 1) << 1);
            int idx = (((o >> 1) * 8 + (row >> 4)) * 4 + reg) * 32 + (row & 7) * 4;
            adst[j] = sbase + idx * 4;
            asrc[j] = Ag + (size_t)(m0 + row) * lda + o * 8;
        }
        {
            int reg = o & 1;
            int idx = 2048 + (((o >> 1) * 16 + (row >> 3)) * 2 + reg) * 32 + (row & 7) * 4;
            bdst[j] = sbase + idx * 4;
            int rr = (n0 + row) < N ? (n0 + row) : 0;
            bsrc[j] = Bg + (size_t)rr * ldb + o * 8;
            bsz[j] = (n0 + row) < N ? 16 : 0;
        }
    }

    float acc[4][4][4];
    #pragma unroll
    for (int a = 0; a < 4; a++)
        #pragma unroll
        for (int b = 0; b < 4; b++)
            #pragma unroll
            for (int c = 0; c < 4; c++) acc[a][b][c] = 0.f;

    const int nk = K >> 5;
    #pragma unroll
    for (int s = 0; s < 2; s++) {
        if (s < nk) {
            uint32_t so = (uint32_t)s * (HSTG * 4);
            int koff = s * 32;
            #pragma unroll
            for (int j = 0; j < 2; j++) {
                cp16(adst[j] + so, asrc[j] + koff, 16);
                cp16(bdst[j] + so, bsrc[j] + koff, bsz[j]);
            }
        }
        CP_COMMIT();
    }

    int slot = 0;
    for (int i = 0; i < nk; i++) {
        CP_WAIT1();
        __syncthreads();
        if (i + 2 < nk) {
            int s2 = (i + 2) % 3;
            uint32_t so = (uint32_t)s2 * (HSTG * 4);
            int koff = (i + 2) * 32;
            #pragma unroll
            for (int j = 0; j < 2; j++) {
                cp16(adst[j] + so, asrc[j] + koff, 16);
                cp16(bdst[j] + so, bsrc[j] + koff, bsz[j]);
            }
        }
        CP_COMMIT();
        const uint32_t* sa = smem + (size_t)slot * HSTG;
        const uint32_t* sb = sa + 2048;
        #pragma unroll
        for (int kb = 0; kb < 2; kb++) {
            uint32_t af[4][4], bf[4][2];
            #pragma unroll
            for (int mt = 0; mt < 4; mt++) {
                const uint32_t* p = sa + (size_t)((kb * 8 + wm * 4 + mt) * 4) * 32 + lane;
                af[mt][0] = p[0]; af[mt][1] = p[32]; af[mt][2] = p[64]; af[mt][3] = p[96];
            }
            #pragma unroll
            for (int nt = 0; nt < 4; nt++) {
                const uint32_t* p = sb + (size_t)((kb * 16 + wn * 4 + nt) * 2) * 32 + lane;
                bf[nt][0] = p[0]; bf[nt][1] = p[32];
            }
            #pragma unroll
            for (int mt = 0; mt < 4; mt++)
                #pragma unroll
                for (int nt = 0; nt < 4; nt++)
                    mma16(acc[mt][nt], af[mt], bf[nt]);
        }
        slot = (slot + 1 == 3) ? 0 : slot + 1;
    }

    if (MODE == 2) {
        __shared__ float den[128];
        if (wn == 2 && (lane & 3) == 0) {
            #pragma unroll
            for (int mt = 0; mt < 4; mt++) {
                int rl = wm * 64 + mt * 16 + (lane >> 2);
                den[rl] = acc[mt][0][0] + 1e-6f;
                den[rl + 8] = acc[mt][0][2] + 1e-6f;
            }
        }
        __syncthreads();
        if (wn < 2) {
            #pragma unroll
            for (int mt = 0; mt < 4; mt++) {
                int rl = wm * 64 + mt * 16 + (lane >> 2);
                float d0 = den[rl], d1 = den[rl + 8];
                #pragma unroll
                for (int nt = 0; nt < 4; nt++) {
                    int c0 = wn * 32 + nt * 8 + (lane & 3) * 2;
                    __half* p0 = (__half*)Cg + (size_t)(m0 + rl) * ldc + c0;
                    __half* p1 = (__half*)Cg + (size_t)(m0 + rl + 8) * ldc + c0;
                    store2(p0, acc[mt][nt][0] / d0, acc[mt][nt][1] / d0);
                    store2(p1, acc[mt][nt][2] / d1, acc[mt][nt][3] / d1);
                }
            }
        }
        return;
    }

    #pragma unroll
    for (int mt = 0; mt < 4; mt++) {
        const int r0 = m0 + wm * 64 + mt * 16 + (lane >> 2);
        #pragma unroll
        for (int nt = 0; nt < 4; nt++) {
            const int c0 = n0 + wn * 32 + nt * 8 + (lane & 3) * 2;
            if (c0 < N) {
                store2(Cg + (size_t)r0 * ldc + c0, acc[mt][nt][0], acc[mt][nt][1]);
                store2(Cg + (size_t)(r0 + 8) * ldc + c0, acc[mt][nt][2], acc[mt][nt][3]);
            }
        }
    }

    if (MODE == 1) {
        __shared__ unsigned smax[128];
        if (tid < 128) smax[tid] = 0u;
        __syncthreads();
        #pragma unroll
        for (int mt = 0; mt < 4; mt++) {
            float v0 = -1e30f, v1 = -1e30f;
            #pragma unroll
            for (int nt = 0; nt < 4; nt++) {
                int c0 = n0 + wn * 32 + nt * 8 + (lane & 3) * 2;
                if (c0 < N) {
                    v0 = fmaxf(v0, fmaxf(acc[mt][nt][0], acc[mt][nt][1]));
                    v1 = fmaxf(v1, fmaxf(acc[mt][nt][2], acc[mt][nt][3]));
                }
            }
            v0 = fmaxf(v0, __shfl_xor_sync(~0u, v0, 1));
            v0 = fmaxf(v0, __shfl_xor_sync(~0u, v0, 2));
            v1 = fmaxf(v1, __shfl_xor_sync(~0u, v1, 1));
            v1 = fmaxf(v1, __shfl_xor_sync(~0u, v1, 2));
            if ((lane & 3) == 0) {
                int rl = wm * 64 + mt * 16 + (lane >> 2);
                atomicMax(&smax[rl], encf(v0));
                atomicMax(&smax[rl + 8], encf(v1));
            }
        }
        __syncthreads();
        if (tid < 128)
            pmax[((size_t)z * NX + blockIdx.x) * M + m0 + tid] = decf(smax[tid]);
    }
}

// ===================== v2: 128x256 tile, 3-stage, single-sync ================
#define H2STG 6144
#define H2SM  (3*H2STG*4)        // 72KB

template<bool RELU, bool RES, bool BIAS, typename CT>
__global__ __launch_bounds__(256)
void hgemm2(const __half* __restrict__ A, const __half* __restrict__ B,
            const float* __restrict__ bias, const float* __restrict__ res,
            CT* __restrict__ C, int M, int N, int K, int lda, int ldb, int ldc)
{
    extern __shared__ uint32_t smem[];
    const int tid = threadIdx.x, lane = tid & 31, w = tid >> 5;
    const int wm = w & 1, wn = w >> 1;
    const uint32_t sbase = smem_u32(smem);
    const int m0 = blockIdx.y * 128, n0 = blockIdx.x * 256;

    const __half* asrc[2]; uint32_t adst[2];
    #pragma unroll
    for (int j = 0; j < 2; j++) {
        int c = j * 256 + tid;
        int row = c >> 2, o = c & 3;
        int reg = ((row >> 3) & 1) + ((o & 1) << 1);
        int idx = (((o >> 1) * 8 + (row >> 4)) * 4 + reg) * 32 + (row & 7) * 4;
        adst[j] = sbase + idx * 4;
        asrc[j] = A + (size_t)(m0 + row) * lda + o * 8;
    }
    const __half* bsrc[4]; uint32_t bdst[4];
    #pragma unroll
    for (int j = 0; j < 4; j++) {
        int c = j * 256 + tid;
        int row = c >> 2, o = c & 3;
        int reg = o & 1;
        int idx = 2048 + (((o >> 1) * 32 + (row >> 3)) * 2 + reg) * 32 + (row & 7) * 4;
        bdst[j] = sbase + idx * 4;
        bsrc[j] = B + (size_t)(n0 + row) * ldb + o * 8;
    }

    float acc[4][8][4];
    #pragma unroll
    for (int a = 0; a < 4; a++)
        #pragma unroll
        for (int b = 0; b < 8; b++)
            #pragma unroll
            for (int c = 0; c < 4; c++) acc[a][b][c] = 0.f;

    const int nk = K >> 5;
    #pragma unroll
    for (int s = 0; s < 2; s++) {
        uint32_t so = (uint32_t)s * (H2STG * 4);
        int koff = s * 32;
        #pragma unroll
        for (int j = 0; j < 2; j++) cp16(adst[j] + so, asrc[j] + koff, 16);
        #pragma unroll
        for (int j = 0; j < 4; j++) cp16(bdst[j] + so, bsrc[j] + koff, 16);
        CP_COMMIT();
    }

    int slot = 0;
    for (int i = 0; i < nk; i++) {
        CP_WAIT1();
        __syncthreads();
        if (i + 2 < nk) {
            int s2 = (i + 2) % 3;
            uint32_t so = (uint32_t)s2 * (H2STG * 4);
            int koff = (i + 2) * 32;
            #pragma unroll
            for (int j = 0; j < 2; j++) cp16(adst[j] + so, asrc[j] + koff, 16);
            #pragma unroll
            for (int j = 0; j < 4; j++) cp16(bdst[j] + so, bsrc[j] + koff, 16);
        }
        CP_COMMIT();
        const uint32_t* sa = smem + (size_t)slot * H2STG;
        const uint32_t* sb = sa + 2048;
        #pragma unroll
        for (int kb = 0; kb < 2; kb++) {
            uint32_t af[4][4], bf[8][2];
            #pragma unroll
            for (int mt = 0; mt < 4; mt++) {
                const uint32_t* p = sa + (size_t)((kb * 8 + wm * 4 + mt) * 4) * 32 + lane;
                af[mt][0] = p[0]; af[mt][1] = p[32]; af[mt][2] = p[64]; af[mt][3] = p[96];
            }
            #pragma unroll
            for (int nt = 0; nt < 8; nt++) {
                const uint32_t* p = sb + (size_t)((kb * 32 + wn * 8 + nt) * 2) * 32 + lane;
                bf[nt][0] = p[0]; bf[nt][1] = p[32];
            }
            #pragma unroll
            for (int mt = 0; mt < 4; mt++)
                #pragma unroll
                for (int nt = 0; nt < 8; nt++)
                    mma16(acc[mt][nt], af[mt], bf[nt]);
        }
        slot = (slot + 1 == 3) ? 0 : slot + 1;
    }

    #pragma unroll
    for (int mt = 0; mt < 4; mt++) {
        const int r0 = m0 + wm * 64 + mt * 16 + (lane >> 2);
        #pragma unroll
        for (int nt = 0; nt < 8; nt++) {
            const int c0 = n0 + wn * 64 + nt * 8 + (lane & 3) * 2;
            float bx = 0.f, by = 0.f;
            if (BIAS) { float2 b2 = *(const float2*)(bias + c0); bx = b2.x; by = b2.y; }
            float x0 = acc[mt][nt][0] + bx, x1 = acc[mt][nt][1] + by;
            float y0 = acc[mt][nt][2] + bx, y1 = acc[mt][nt][3] + by;
            if (RES) {
                float2 ra = *(const float2*)(res + (size_t)r0 * ldc + c0);
                float2 rb = *(const float2*)(res + (size_t)(r0 + 8) * ldc + c0);
                x0 += ra.x; x1 += ra.y; y0 += rb.x; y1 += rb.y;
            }
            if (RELU) {
                x0 = fmaxf(x0, 0.f); x1 = fmaxf(x1, 0.f);
                y0 = fmaxf(y0, 0.f); y1 = fmaxf(y1, 0.f);
            }
            store2(C + (size_t)r0 * ldc + c0, x0, x1);
            store2(C + (size_t)(r0 + 8) * ldc + c0, y0, y1);
        }
    }
}

// ===================== fp16 TN GEMM for kvs, writes kvsT transposed ==========
#define TNSTG 3072
#define TNSM (2*TNSTG*4)

__global__ __launch_bounds__(256)
void kvs_gemm(const __half* __restrict__ kp, const __half* __restrict__ v,
              __half* __restrict__ kvsT)
{
    extern __shared__ uint32_t smem[];
    const int tid = threadIdx.x, lane = tid & 31, w = tid >> 5;
    const int wm = w >> 2, wn = w & 3;
    const uint32_t sbase = smem_u32(smem);
    const int bh = blockIdx.z, b = bh >> 4, h = bh & 15;
    const int m0 = blockIdx.x * 128;
    const __half* Ag = kp + (size_t)bh * SEQ * MP;
    const __half* Bg = v + (size_t)b * SEQ * QL + h * HD;

    const __half* asrc[2]; uint32_t adst[2]; int asz[2];
    #pragma unroll
    for (int j = 0; j < 2; j++) {
        int c = j * 256 + tid;
        int row = c >> 4, u = c & 15;
        adst[j] = sbase + row * 256 + ((u ^ (row & 7)) << 4);
        bool val = (m0 + u * 8) < MP;
        asrc[j] = Ag + (size_t)row * MP + (val ? (m0 + u * 8) : 0);
        asz[j] = val ? 16 : 0;
    }
    const int brow = tid >> 3, bu = tid & 7;
    const uint32_t bdst = sbase + 8192 + brow * 128 + ((bu ^ (brow & 7)) << 4);
    const __half* bsrc = Bg + (size_t)brow * QL + bu * 8;

    float acc[4][2][4];
    #pragma unroll
    for (int a = 0; a < 4; a++)
        #pragma unroll
        for (int bb = 0; bb < 2; bb++)
            #pragma unroll
            for (int c = 0; c < 4; c++) acc[a][bb][c] = 0.f;

    const int nk = SEQ / 32;
    #pragma unroll
    for (int j = 0; j < 2; j++) cp16(adst[j], asrc[j], asz[j]);
    cp16(bdst, bsrc, 16);
    CP_COMMIT();

    const int q = lane >> 3, r = lane & 7;
    for (int i = 0; i < nk; i++) {
        if (i + 1 < nk) {
            uint32_t so = (uint32_t)((i + 1) & 1) * (TNSTG * 4);
            size_t ko = (size_t)(i + 1) * 32;
            #pragma unroll
            for (int j = 0; j < 2; j++) cp16(adst[j] + so, asrc[j] + ko * MP, asz[j]);
            cp16(bdst + so, bsrc + ko * QL, 16);
        }
        CP_COMMIT();
        CP_WAIT1();
        __syncthreads();
        const uint32_t st = sbase + (uint32_t)(i & 1) * (TNSTG * 4);
        #pragma unroll
        for (int kb = 0; kb < 2; kb++) {
            uint32_t bf[4];
            {
                int krow = kb * 16 + (q & 1) * 8 + r;
                int du = wn * 2 + (q >> 1);
                ldsm4t(bf, st + 8192 + krow * 128 + ((du ^ (krow & 7)) << 4));
            }
            #pragma unroll
            for (int mt = 0; mt < 4; mt++) {
                uint32_t af[4];
                int krow = kb * 16 + (q >> 1) * 8 + r;
                int mu = wm * 8 + mt * 2 + (q & 1);
                ldsm4t(af, st + krow * 256 + ((mu ^ (krow & 7)) << 4));
                mma16(acc[mt][0], af, bf);
                mma16(acc[mt][1], af, bf + 2);
            }
        }
        __syncthreads();
    }

    // write TRANSPOSED into kvsT[d][m] (d = c0, m = r0), fp16
    __half* outp = kvsT + (size_t)bh * KVR * MP;
    #pragma unroll
    for (int mt = 0; mt < 4; mt++) {
        const int r0 = m0 + wm * 64 + mt * 16 + (lane >> 2);
        #pragma unroll
        for (int nt = 0; nt < 2; nt++) {
            const int c0 = wn * 16 + nt * 8 + (lane & 3) * 2;
            if (r0 < MP) {
                outp[(size_t)c0 * MP + r0]       = __float2half(acc[mt][nt][0]);
                outp[(size_t)(c0 + 1) * MP + r0] = __float2half(acc[mt][nt][1]);
            }
            if (r0 + 8 < MP) {
                outp[(size_t)c0 * MP + r0 + 8]       = __float2half(acc[mt][nt][2]);
                outp[(size_t)(c0 + 1) * MP + r0 + 8] = __float2half(acc[mt][nt][3]);
            }
        }
    }
}

// ----------------- fp32 -> fp16 converts -----------------
__global__ void cvt_kernel(const float* __restrict__ s, __half* __restrict__ d, int n4)
{
    int i = blockIdx.x * 256 + threadIdx.x;
    if (i >= n4) return;
    float4 v = ((const float4*)s)[i];
    __half2* o = (__half2*)d + (size_t)i * 2;
    o[0] = __floats2half2_rn(v.x, v.y);
    o[1] = __floats2half2_rn(v.z, v.w);
}

// three-weight convert (QKV) in one launch
__global__ void cvt3_kernel(const float* __restrict__ s0, const float* __restrict__ s1,
                            const float* __restrict__ s2, __half* __restrict__ d)
{
    const int n4 = DM * DM / 4;
    int i = blockIdx.x * 256 + threadIdx.x;
    if (i >= 3 * n4) return;
    int seg = i / n4, off = i - seg * n4;
    const float* s = (seg == 0) ? s0 : (seg == 1) ? s1 : s2;
    float4 v = ((const float4*)s)[off];
    __half2* o = (__half2*)d + (size_t)i * 2;
    o[0] = __floats2half2_rn(v.x, v.y);
    o[1] = __floats2half2_rn(v.z, v.w);
}

// ----------------- bias concat (fp32) -----------------
__global__ void biascat_kernel(const float* __restrict__ qb, const float* __restrict__ kb,
                               const float* __restrict__ vb, float* __restrict__ o)
{
    int i = blockIdx.x * 256 + threadIdx.x;
    if (i >= QL) return;
    int seg = i >> 10, off = i & 1023;
    o[i] = (seg == 0) ? qb[off] : (seg == 1) ? kb[off] : vb[off];
}

// ----------------- LayerNorm (fp32 in, fp16 out) -----------------
__global__ __launch_bounds__(256)
void ln_kernel(const float* __restrict__ x, const float* __restrict__ g,
               const float* __restrict__ beta, __half* __restrict__ y)
{
    size_t row = blockIdx.x;
    int tid = threadIdx.x;
    float4 v = ((const float4*)(x + row * DM))[tid];
    float s = v.x + v.y + v.z + v.w;
    __shared__ float sm[8];
    #pragma unroll
    for (int o = 16; o > 0; o >>= 1) s += __shfl_xor_sync(~0u, s, o);
    if ((tid & 31) == 0) sm[tid >> 5] = s;
    __syncthreads();
    float mu = 0.f;
    #pragma unroll
    for (int i = 0; i < 8; i++) mu += sm[i];
    mu *= (1.f / (float)DM);
    float dx = v.x - mu, dy = v.y - mu, dz = v.z - mu, dw = v.w - mu;
    float q = dx*dx + dy*dy + dz*dz + dw*dw;
    __syncthreads();
    #pragma unroll
    for (int o = 16; o > 0; o >>= 1) q += __shfl_xor_sync(~0u, q, o);
    if ((tid & 31) == 0) sm[tid >> 5] = q;
    __syncthreads();
    float var = 0.f;
    #pragma unroll
    for (int i = 0; i < 8; i++) var += sm[i];
    var *= (1.f / (float)DM);
    float inv = rsqrtf(var + 1e-5f);
    float4 gg = ((const float4*)g)[tid];
    float4 bb = ((const float4*)beta)[tid];
    __half2* o = (__half2*)(y + row * DM) + tid * 2;
    o[0] = __floats2half2_rn(dx * inv * gg.x + bb.x, dy * inv * gg.y + bb.y);
    o[1] = __floats2half2_rn(dz * inv * gg.z + bb.z, dw * inv * gg.w + bb.w);
}

// ----------------- kstab -----------------
__global__ void kstab_kernel(const float* __restrict__ pmaxk, float* __restrict__ stab)
{
    int i = blockIdx.x * 256 + threadIdx.x;
    if (i >= BATCHN * SEQ) return;
    int b = i >> 11, l = i & (SEQ - 1);
    float mx = -1e30f;
    #pragma unroll
    for (int h = 0; h < NH; h++)
        #pragma unroll
        for (int x = 0; x < NXT; x++)
            mx = fmaxf(mx, pmaxk[((size_t)(b * NH + h) * NXT + x) * SEQ + l]);
    stab[i] = mx;
}

// ----------------- q exp (in-place on fp16 qp) -----------------
__global__ __launch_bounds__(256)
void qexp_kernel(__half* __restrict__ qp, const __half* __restrict__ qkv,
                 const float* __restrict__ pmaxq)
{
    const int rr = blockIdx.x * 8 + (threadIdx.x >> 5);
    const int lane = threadIdx.x & 31;
    const int bh = rr >> 11, l = rr & (SEQ - 1);
    const int b = bh >> 4, h = bh & 15;
    float mx = -1e30f;
    #pragma unroll
    for (int x = 0; x < NXT; x++)
        mx = fmaxf(mx, pmaxq[((size_t)bh * NXT + x) * SEQ + l]);
    mx *= DN;
    const __half* qr = qkv + ((size_t)(b * SEQ + l)) * QL + h * HD;
    float a = __half2float(qr[lane]), bb2 = __half2float(qr[lane + 32]);
    float s = a * a + bb2 * bb2;
    #pragma unroll
    for (int o = 16; o > 0; o >>= 1) s += __shfl_xor_sync(~0u, s, o);
    const float dia = 0.5f * DN * DN * s;
    __half* row = qp + (size_t)rr * MP;
    #pragma unroll
    for (int j = 0; j < 18; j++) {
        int m = j * 32 + lane;
        if (m < MP) {
            float v = (m < MFEAT)
                ? RATIO * (__expf(DN * __half2float(row[m]) - mx - dia) + FEPS) : 0.f;
            row[m] = __float2half(v);
        }
    }
}

// ----------------- k exp (in-place on fp16 kp) -----------------
__global__ __launch_bounds__(256)
void kexp_kernel(__half* __restrict__ kp, const __half* __restrict__ qkv,
                 const float* __restrict__ stab, const unsigned char* __restrict__ padmask)
{
    const int rr = blockIdx.x * 8 + (threadIdx.x >> 5);
    const int lane = threadIdx.x & 31;
    const int bh = rr >> 11, l = rr & (SEQ - 1);
    const int b = bh >> 4, h = bh & 15;
    const float mx = DN * stab[b * SEQ + l];
    const __half* kr = qkv + ((size_t)(b * SEQ + l)) * QL + DM + h * HD;
    float a = __half2float(kr[lane]), bb2 = __half2float(kr[lane + 32]);
    float s = a * a + bb2 * bb2;
    #pragma unroll
    for (int o = 16; o > 0; o >>= 1) s += __shfl_xor_sync(~0u, s, o);
    const float dia = 0.5f * DN * DN * s;
    const float keep = padmask[b * SEQ + l] ? 0.f : 1.f;
    __half* row = kp + (size_t)rr * MP;
    #pragma unroll
    for (int j = 0; j < 18; j++) {
        int m = j * 32 + lane;
        if (m < MP) {
            float v = (m < MFEAT)
                ? keep * RATIO * (__expf(DN * __half2float(row[m]) - mx - dia) + FEPS) : 0.f;
            row[m] = __float2half(v);
        }
    }
}

// ks_sum (row 64) + zero rows 65..127
__global__ void kssum_kernel(const __half* __restrict__ kp, __half* __restrict__ kvsT)
{
    int bh = blockIdx.y;
    int m = blockIdx.x * 192 + threadIdx.x;
    if (m >= MP) return;
    const __half* p = kp + (size_t)bh * SEQ * MP + m;
    float a0 = 0.f, a1 = 0.f, a2 = 0.f, a3 = 0.f;
    for (int l = 0; l < SEQ; l += 4) {
        a0 += __half2float(p[(size_t)l * MP]);
        a1 += __half2float(p[(size_t)(l + 1) * MP]);
        a2 += __half2float(p[(size_t)(l + 2) * MP]);
        a3 += __half2float(p[(size_t)(l + 3) * MP]);
    }
    __half* o = kvsT + (size_t)bh * KVR * MP;
    o[(size_t)64 * MP + m] = __float2half((a0 + a1) + (a2 + a3));
    for (int r = 65; r < KVR; r++) o[(size_t)r * MP + m] = __float2half(0.f);
}

// ----------------- launch -----------------
static void* getsym(const void* shadow)
{
    void* p = nullptr;
    cudaGetSymbolAddress(&p, shadow);
    return p;
}

extern "C" void kernel_launch(void* const* d_in, const int* in_sizes, int n_in,
                              void* d_out, int out_size)
{
    const float* src    = (const float*)d_in[0];
    const unsigned char* mask = (const unsigned char*)d_in[1];
    const float* proj   = (const float*)d_in[2];
    const float* q_w    = (const float*)d_in[3];
    const float* q_b    = (const float*)d_in[4];
    const float* k_w    = (const float*)d_in[5];
    const float* k_b    = (const float*)d_in[6];
    const float* v_w    = (const float*)d_in[7];
    const float* v_b    = (const float*)d_in[8];
    const float* out_w  = (const float*)d_in[9];
    const float* out_b  = (const float*)d_in[10];
    const float* ln1_g  = (const float*)d_in[11];
    const float* ln1_b  = (const float*)d_in[12];
    const float* ln2_g  = (const float*)d_in[13];
    const float* ln2_b  = (const float*)d_in[14];
    const float* ff1_w  = (const float*)d_in[15];
    const float* ff1_b  = (const float*)d_in[16];
    const float* ff2_w  = (const float*)d_in[17];
    const float* ff2_b  = (const float*)d_in[18];
    float* out = (float*)d_out;

    __half* p_xn   = (__half*)getsym(g_xnh);
    __half* p_qkv  = (__half*)getsym(g_qkvh);
    __half* p_qp   = (__half*)getsym(g_qph);
    __half* p_kp   = (__half*)getsym(g_kph);
    float*  p_pmq  = (float*)getsym(g_pmaxq);
    float*  p_pmk  = (float*)getsym(g_pmaxk);
    float*  p_stab = (float*)getsym(g_stab);
    __half* p_kvsT = (__half*)getsym(g_kvsTh);
    __half* p_attn = (__half*)getsym(g_attnh);
    float*  p_x1   = (float*)getsym(g_x1);
    __half* p_hn   = (__half*)getsym(g_hnh);
    __half* p_ff   = (__half*)getsym(g_ffh);
    __half* p_wqkv = (__half*)getsym(g_wqkv);
    float*  p_bqkv = (float*)getsym(g_bqkv);
    __half* p_wo   = (__half*)getsym(g_wo);
    __half* p_w1   = (__half*)getsym(g_w1);
    __half* p_w2   = (__half*)getsym(g_w2);
    __half* p_pj   = (__half*)getsym(g_pj);

    cudaFuncSetAttribute(hgemm<1,__half>,
                         cudaFuncAttributeMaxDynamicSharedMemorySize, HSM);
    cudaFuncSetAttribute(hgemm<2,__half>,
                         cudaFuncAttributeMaxDynamicSharedMemorySize, HSM);
    cudaFuncSetAttribute(hgemm2<false,false,true,__half>,
                         cudaFuncAttributeMaxDynamicSharedMemorySize, H2SM);
    cudaFuncSetAttribute(hgemm2<false,true,true,float>,
                         cudaFuncAttributeMaxDynamicSharedMemorySize, H2SM);
    cudaFuncSetAttribute(hgemm2<true,false,true,__half>,
                         cudaFuncAttributeMaxDynamicSharedMemorySize, H2SM);
    cudaFuncSetAttribute(kvs_gemm,
                         cudaFuncAttributeMaxDynamicSharedMemorySize, TNSM);

    // launches 1-3 (so ncu's capture slot #4 is the QKV GEMM)
    {
        int n4t = 3 * DM * DM / 4;
        cvt3_kernel<<<(n4t + 255) / 256, 256>>>(q_w, k_w, v_w, p_wqkv);
    }
    biascat_kernel<<<(QL + 255) / 256, 256>>>(q_b, k_b, v_b, p_bqkv);
    ln_kernel<<<NROWS, 256>>>(src, ln1_g, ln1_b, p_xn);

    // launch 4: merged QKV GEMM (N=3072)
    hgemm2<false,false,true,__half><<<dim3(QL / 256, NROWS / 128, 1), 256, H2SM>>>(
        p_xn, p_wqkv, p_bqkv, nullptr, p_qkv, NROWS, QL, DM, DM, DM, QL);

    // remaining weight converts
    {
        int n4 = DM * DM / 4;
        cvt_kernel<<<(n4 + 255) / 256, 256>>>(out_w, p_wo, n4);
        int nf = DFF * DM / 4;
        cvt_kernel<<<(nf + 255) / 256, 256>>>(ff1_w, p_w1, nf);
        cvt_kernel<<<(nf + 255) / 256, 256>>>(ff2_w, p_w2, nf);
        int np = MFEAT * HD / 4;
        cvt_kernel<<<(np + 255) / 256, 256>>>(proj, p_pj, np);
    }

    // feature GEMMs (MODE 1, fp16 out into qp/kp) + in-place exp epilogues
    dim3 gF(NXT, SEQ / 128, NBH);
    hgemm<1,__half><<<gF, 256, HSM>>>(
        p_qkv, p_pj, p_qp, p_pmq, NXT, SEQ, MFEAT, HD, QL, HD, MP,
        (long long)SEQ * QL, HD, 0, 0, (long long)NH * SEQ * MP, (long long)SEQ * MP, NH);
    qexp_kernel<<<NBH * SEQ / 8, 256>>>(p_qp, p_qkv, p_pmq);
    hgemm<1,__half><<<gF, 256, HSM>>>(
        p_qkv + DM, p_pj, p_kp, p_pmk, NXT, SEQ, MFEAT, HD, QL, HD, MP,
        (long long)SEQ * QL, HD, 0, 0, (long long)NH * SEQ * MP, (long long)SEQ * MP, NH);
    kstab_kernel<<<(BATCHN * SEQ + 255) / 256, 256>>>(p_pmk, p_stab);
    kexp_kernel<<<NBH * SEQ / 8, 256>>>(p_kp, p_qkv, p_stab, mask);

    // kvs (writes kvsT transposed) + ks_sum/zero-pad
    kvs_gemm<<<dim3((MP + 127) / 128, 1, NBH), 256, TNSM>>>(p_kp, p_qkv + 2 * DM, p_kvsT);
    kssum_kernel<<<dim3(3, NBH), 192>>>(p_kp, p_kvsT);

    // numer GEMM with fused divide -> attn fp16 [b,l,h,d]
    hgemm<2,__half><<<dim3(1, SEQ / 128, NBH), 256, HSM>>>(
        p_qp, p_kvsT, p_attn, nullptr, 1, SEQ, KVR, MP, MP, MP, DM,
        (long long)NH * SEQ * MP, (long long)SEQ * MP,
        (long long)NH * KVR * MP, (long long)KVR * MP,
        (long long)SEQ * DM, HD, NH);

    // out projection + residual(src) -> x1 fp32
    dim3 gO(DM / 256, NROWS / 128, 1);
    hgemm2<false,true,true,float><<<gO, 256, H2SM>>>(
        p_attn, p_wo, out_b, src, p_x1, NROWS, DM, DM, DM, DM, DM);

    // LN2 -> fp16
    ln_kernel<<<NROWS, 256>>>(p_x1, ln2_g, ln2_b, p_hn);

    // FF1 (+ReLU) -> fp16
    hgemm2<true,false,true,__half><<<dim3(DFF / 256, NROWS / 128, 1), 256, H2SM>>>(
        p_hn, p_w1, ff1_b, nullptr, p_ff, NROWS, DFF, DM, DM, DM, DFF);

    // FF2 + residual(x1) -> final fp32 output
    hgemm2<false,true,true,float><<<gO, 256, H2SM>>>(
        p_ff, p_w2, ff2_b, p_x1, out, NROWS, DM, DFF, DFF, DFF, DM);
}